// round 1
// baseline (speedup 1.0000x reference)
#include <cuda_runtime.h>
#include <math.h>

// Problem constants
#define Bb   2
#define Ss   2048
#define Dd   1024
#define Hh   16
#define HDd  64
#define Mrows (Bb*Ss)   // 4096

// ---------------- scratch (no allocs allowed) ----------------
__device__ float g_q [Mrows*Dd];
__device__ float g_k [Mrows*Dd];
__device__ float g_v [Mrows*Dd];
__device__ float g_qt[Mrows*Dd];   // [B,H,S,HD]
__device__ float g_kt[Mrows*Dd];
__device__ float g_vt[Mrows*Dd];
__device__ float g_ao[Mrows*Dd];   // attention out, [B,S,H*HD]

// =================================================================
// SGEMM NT:  C[M,N] = A[M,K] * W[N,K]^T   (both row-major, K inner)
// 128x128x16 tile, 256 threads, 8x8 per thread
// =================================================================
__global__ __launch_bounds__(256, 2)
void sgemm_nt(const float* __restrict__ A, const float* __restrict__ W,
              float* __restrict__ C, int M, int N, int K) {
    __shared__ float As[16][128 + 4];
    __shared__ float Bs[16][128 + 4];

    const int tid = threadIdx.x;
    const int tx  = tid & 15;          // 0..15  -> col group
    const int ty  = tid >> 4;          // 0..15  -> row group
    const int bm  = blockIdx.y * 128;
    const int bn  = blockIdx.x * 128;

    const int r0 = tid >> 2;           // 0..63
    const int c0 = (tid & 3) << 2;     // 0,4,8,12

    const float* Ap = A + (size_t)(bm + r0) * K + c0;
    const float* Bp = W + (size_t)(bn + r0) * K + c0;
    const size_t rowskip = (size_t)64 * K;

    float acc[8][8];
#pragma unroll
    for (int i = 0; i < 8; ++i)
#pragma unroll
        for (int j = 0; j < 8; ++j) acc[i][j] = 0.f;

    for (int kt = 0; kt < K; kt += 16) {
        float4 a0 = *(const float4*)(Ap + kt);
        float4 a1 = *(const float4*)(Ap + kt + rowskip);
        float4 b0 = *(const float4*)(Bp + kt);
        float4 b1 = *(const float4*)(Bp + kt + rowskip);

        __syncthreads();   // previous compute done before overwrite
        As[c0+0][r0]    = a0.x; As[c0+1][r0]    = a0.y;
        As[c0+2][r0]    = a0.z; As[c0+3][r0]    = a0.w;
        As[c0+0][r0+64] = a1.x; As[c0+1][r0+64] = a1.y;
        As[c0+2][r0+64] = a1.z; As[c0+3][r0+64] = a1.w;
        Bs[c0+0][r0]    = b0.x; Bs[c0+1][r0]    = b0.y;
        Bs[c0+2][r0]    = b0.z; Bs[c0+3][r0]    = b0.w;
        Bs[c0+0][r0+64] = b1.x; Bs[c0+1][r0+64] = b1.y;
        Bs[c0+2][r0+64] = b1.z; Bs[c0+3][r0+64] = b1.w;
        __syncthreads();

#pragma unroll
        for (int kk = 0; kk < 16; ++kk) {
            float ar[8], br[8];
            *(float4*)(ar  ) = *(const float4*)&As[kk][ty*8];
            *(float4*)(ar+4) = *(const float4*)&As[kk][ty*8+4];
            *(float4*)(br  ) = *(const float4*)&Bs[kk][tx*8];
            *(float4*)(br+4) = *(const float4*)&Bs[kk][tx*8+4];
#pragma unroll
            for (int i = 0; i < 8; ++i)
#pragma unroll
                for (int j = 0; j < 8; ++j)
                    acc[i][j] = fmaf(ar[i], br[j], acc[i][j]);
        }
    }

#pragma unroll
    for (int i = 0; i < 8; ++i) {
        float* cp = C + (size_t)(bm + ty*8 + i) * N + bn + tx*8;
        float4 v0 = make_float4(acc[i][0], acc[i][1], acc[i][2], acc[i][3]);
        float4 v1 = make_float4(acc[i][4], acc[i][5], acc[i][6], acc[i][7]);
        *(float4*)(cp)     = v0;
        *(float4*)(cp + 4) = v1;
    }
}

// =================================================================
// RMSNorm (per head) + RoPE + transpose to [B,H,S,HD].
// One warp per (b,s,h) row; lane handles dims (lane, lane+32).
// =================================================================
__global__ __launch_bounds__(256)
void norm_rope_kernel(const float* __restrict__ q, const float* __restrict__ k,
                      const float* __restrict__ v,
                      const float* __restrict__ qw, const float* __restrict__ kw,
                      float* __restrict__ qt, float* __restrict__ kt,
                      float* __restrict__ vt) {
    const int gw   = blockIdx.x * 8 + (threadIdx.x >> 5);   // global warp id
    const int lane = threadIdx.x & 31;
    const int h  = gw & (Hh - 1);
    const int bs = gw >> 4;            // b*S + s
    const int s  = bs & (Ss - 1);
    const int b  = bs >> 11;

    const size_t src = (size_t)bs * Dd + h * HDd;
    const size_t dst = (((size_t)(b * Hh + h)) * Ss + s) * HDd;

    // RoPE angle (double for exact argument reduction at large s)
    const double ifd = exp(-(double)lane * (log(10000.0) / 32.0));
    double sd_, cd_;
    sincos((double)s * ifd, &sd_, &cd_);
    const float cs = (float)cd_, sn = (float)sd_;

    // ---- Q ----
    {
        float x1 = q[src + lane], x2 = q[src + lane + 32];
        float ss2 = x1 * x1 + x2 * x2;
#pragma unroll
        for (int off = 16; off; off >>= 1)
            ss2 += __shfl_xor_sync(0xffffffffu, ss2, off);
        float r = rsqrtf(ss2 * (1.0f / 64.0f) + 1e-6f);
        float n1 = x1 * r * qw[lane];
        float n2 = x2 * r * qw[lane + 32];
        qt[dst + lane]      = n1 * cs - n2 * sn;
        qt[dst + lane + 32] = n2 * cs + n1 * sn;
    }
    // ---- K ----
    {
        float x1 = k[src + lane], x2 = k[src + lane + 32];
        float ss2 = x1 * x1 + x2 * x2;
#pragma unroll
        for (int off = 16; off; off >>= 1)
            ss2 += __shfl_xor_sync(0xffffffffu, ss2, off);
        float r = rsqrtf(ss2 * (1.0f / 64.0f) + 1e-6f);
        float n1 = x1 * r * kw[lane];
        float n2 = x2 * r * kw[lane + 32];
        kt[dst + lane]      = n1 * cs - n2 * sn;
        kt[dst + lane + 32] = n2 * cs + n1 * sn;
    }
    // ---- V (transpose only) ----
    vt[dst + lane]      = v[src + lane];
    vt[dst + lane + 32] = v[src + lane + 32];
}

// =================================================================
// Flash attention, causal + sink softmax.
// Block: (qtile=64 rows) x (bh). 256 threads, 4x4 micro-tile.
// smem: Qs (Q^T), KP (K^T then P^T), Vs (natural) -> 48KB
// =================================================================
__global__ __launch_bounds__(256)
void attn_kernel(const float* __restrict__ qt, const float* __restrict__ kt,
                 const float* __restrict__ vt, const float* __restrict__ sinkl,
                 float* __restrict__ ao) {
    __shared__ float Qs[64][64];   // [d][r]
    __shared__ float KP[64][64];   // [d][c] as K^T, reused as [c][r] for P^T
    __shared__ float Vs[64][64];   // [c][d]

    const int tid = threadIdx.x;
    const int tx  = tid & 15;      // col group (keys / out-dims)
    const int ty  = tid >> 4;      // row group (queries)
    const int qi  = blockIdx.x;
    const int bh  = blockIdx.y;
    const int h   = bh & (Hh - 1);
    const int b   = bh >> 4;

    const float* qb = qt + (size_t)bh * Ss * HDd;
    const float* kb = kt + (size_t)bh * Ss * HDd;
    const float* vb = vt + (size_t)bh * Ss * HDd;
    const int q0 = qi * 64;

    // Load Q tile transposed
#pragma unroll
    for (int u = 0; u < 4; ++u) {
        int f = tid + u * 256;
        int r = f & 63, c = (f >> 6) << 2;
        float4 qv = *(const float4*)&qb[(size_t)(q0 + r) * HDd + c];
        Qs[c+0][r] = qv.x; Qs[c+1][r] = qv.y;
        Qs[c+2][r] = qv.z; Qs[c+3][r] = qv.w;
    }

    const float snk = sinkl[h];
    float m[4], l[4], o[4][4];
#pragma unroll
    for (int i = 0; i < 4; ++i) {
        m[i] = snk; l[i] = 1.0f;
#pragma unroll
        for (int j = 0; j < 4; ++j) o[i][j] = 0.f;
    }

    for (int j = 0; j <= qi; ++j) {
        const float* kjb = kb + (size_t)j * 64 * HDd;
        const float* vjb = vb + (size_t)j * 64 * HDd;

        float4 kreg[4], vreg[4];
#pragma unroll
        for (int u = 0; u < 4; ++u) {
            int f = tid + u * 256;
            int r = f & 63, c = (f >> 6) << 2;
            kreg[u] = *(const float4*)&kjb[(size_t)r * HDd + c];
            int rv = f >> 4, cv = (f & 15) << 2;
            vreg[u] = *(const float4*)&vjb[(size_t)rv * HDd + cv];
        }

        __syncthreads();   // previous iteration's P/V reads done
#pragma unroll
        for (int u = 0; u < 4; ++u) {
            int f = tid + u * 256;
            int r = f & 63, c = (f >> 6) << 2;
            KP[c+0][r] = kreg[u].x; KP[c+1][r] = kreg[u].y;
            KP[c+2][r] = kreg[u].z; KP[c+3][r] = kreg[u].w;
            int rv = f >> 4, cv = (f & 15) << 2;
            *(float4*)&Vs[rv][cv] = vreg[u];
        }
        __syncthreads();

        // S = Q K^T (4x4 per thread)
        float sc[4][4];
#pragma unroll
        for (int i = 0; i < 4; ++i)
#pragma unroll
            for (int jj = 0; jj < 4; ++jj) sc[i][jj] = 0.f;

#pragma unroll
        for (int d = 0; d < 64; ++d) {
            float4 aq = *(const float4*)&Qs[d][ty * 4];
            float4 bk = *(const float4*)&KP[d][tx * 4];
            float qa[4] = {aq.x, aq.y, aq.z, aq.w};
            float ka[4] = {bk.x, bk.y, bk.z, bk.w};
#pragma unroll
            for (int i = 0; i < 4; ++i)
#pragma unroll
                for (int jj = 0; jj < 4; ++jj)
                    sc[i][jj] = fmaf(qa[i], ka[jj], sc[i][jj]);
        }

        const float scale = 0.125f;   // HD^-0.5
        if (j == qi) {
#pragma unroll
            for (int i = 0; i < 4; ++i)
#pragma unroll
                for (int jj = 0; jj < 4; ++jj)
                    sc[i][jj] = (tx * 4 + jj > ty * 4 + i) ? -1e30f
                                                           : sc[i][jj] * scale;
        } else {
#pragma unroll
            for (int i = 0; i < 4; ++i)
#pragma unroll
                for (int jj = 0; jj < 4; ++jj) sc[i][jj] *= scale;
        }

        // online softmax update (sink already folded into m/l init)
#pragma unroll
        for (int i = 0; i < 4; ++i) {
            float tm = fmaxf(fmaxf(sc[i][0], sc[i][1]),
                             fmaxf(sc[i][2], sc[i][3]));
#pragma unroll
            for (int off = 1; off < 16; off <<= 1)
                tm = fmaxf(tm, __shfl_xor_sync(0xffffffffu, tm, off));
            float mn   = fmaxf(m[i], tm);
            float corr = __expf(m[i] - mn);
            float rs   = 0.f;
#pragma unroll
            for (int jj = 0; jj < 4; ++jj) {
                float p = __expf(sc[i][jj] - mn);
                sc[i][jj] = p;
                rs += p;
            }
#pragma unroll
            for (int off = 1; off < 16; off <<= 1)
                rs += __shfl_xor_sync(0xffffffffu, rs, off);
            l[i] = l[i] * corr + rs;
            m[i] = mn;
#pragma unroll
            for (int jj = 0; jj < 4; ++jj) o[i][jj] *= corr;
        }

        __syncthreads();   // all K reads done; reuse KP for P^T
#pragma unroll
        for (int jj = 0; jj < 4; ++jj) {
            float4 pv = make_float4(sc[0][jj], sc[1][jj], sc[2][jj], sc[3][jj]);
            *(float4*)&KP[tx * 4 + jj][ty * 4] = pv;
        }
        __syncthreads();

        // O += P V
#pragma unroll
        for (int c = 0; c < 64; ++c) {
            float4 pr = *(const float4*)&KP[c][ty * 4];
            float4 vv = *(const float4*)&Vs[c][tx * 4];
            float pa[4] = {pr.x, pr.y, pr.z, pr.w};
            float va[4] = {vv.x, vv.y, vv.z, vv.w};
#pragma unroll
            for (int i = 0; i < 4; ++i)
#pragma unroll
                for (int jj = 0; jj < 4; ++jj)
                    o[i][jj] = fmaf(pa[i], va[jj], o[i][jj]);
        }
    }

    // epilogue: divide by l, write [B,S,H*HD]
#pragma unroll
    for (int i = 0; i < 4; ++i) {
        float inv = 1.0f / l[i];
        float4 ov = make_float4(o[i][0] * inv, o[i][1] * inv,
                                o[i][2] * inv, o[i][3] * inv);
        *(float4*)&ao[((size_t)b * Ss + q0 + ty * 4 + i) * Dd + h * HDd + tx * 4] = ov;
    }
}

// =================================================================
extern "C" void kernel_launch(void* const* d_in, const int* in_sizes, int n_in,
                              void* d_out, int out_size) {
    const float* x  = (const float*)d_in[0];
    const float* wq = (const float*)d_in[1];
    const float* wk = (const float*)d_in[2];
    const float* wv = (const float*)d_in[3];
    const float* wo = (const float*)d_in[4];
    const float* qw = (const float*)d_in[5];
    const float* kw = (const float*)d_in[6];
    const float* sk = (const float*)d_in[7];
    float* out = (float*)d_out;

    float *q, *k, *v, *qtp, *ktp, *vtp, *aop;
    cudaGetSymbolAddress((void**)&q,   g_q);
    cudaGetSymbolAddress((void**)&k,   g_k);
    cudaGetSymbolAddress((void**)&v,   g_v);
    cudaGetSymbolAddress((void**)&qtp, g_qt);
    cudaGetSymbolAddress((void**)&ktp, g_kt);
    cudaGetSymbolAddress((void**)&vtp, g_vt);
    cudaGetSymbolAddress((void**)&aop, g_ao);

    dim3 gg(Dd / 128, Mrows / 128);   // (8, 32)
    sgemm_nt<<<gg, 256>>>(x, wq, q, Mrows, Dd, Dd);
    sgemm_nt<<<gg, 256>>>(x, wk, k, Mrows, Dd, Dd);
    sgemm_nt<<<gg, 256>>>(x, wv, v, Mrows, Dd, Dd);

    norm_rope_kernel<<<(Mrows * Hh) / 8, 256>>>(q, k, v, qw, kw, qtp, ktp, vtp);

    attn_kernel<<<dim3(Ss / 64, Bb * Hh), 256>>>(qtp, ktp, vtp, sk, aop);

    sgemm_nt<<<gg, 256>>>(aop, wo, out, Mrows, Dd, Dd);
}

// round 3
// speedup vs baseline: 1.7332x; 1.7332x over previous
#include <cuda_runtime.h>
#include <cuda_bf16.h>
#include <stdint.h>
#include <math.h>

// Problem constants
#define Bb   2
#define Ss   2048
#define Dd   1024
#define Hh   16
#define HDd  64
#define Mrows (Bb*Ss)   // 4096

// ---------------- scratch (no allocs allowed) ----------------
__device__ float g_q [Mrows*Dd];
__device__ float g_k [Mrows*Dd];
__device__ float g_v [Mrows*Dd];
__device__ float g_qt[Mrows*Dd];   // [B,H,S,HD]
__device__ float g_kt[Mrows*Dd];
__device__ float g_vt[Mrows*Dd];
__device__ float g_ao[Mrows*Dd];   // attention out, [B,S,H*HD]

// ================= PTX helpers ==========================
__device__ __forceinline__ uint32_t smem_u32(const void* p) {
    uint32_t a;
    asm("{ .reg .u64 t; cvta.to.shared.u64 t, %1; cvt.u32.u64 %0, t; }"
        : "=r"(a) : "l"(p));
    return a;
}
__device__ __forceinline__ void cp_async16(uint32_t s, const void* g) {
    asm volatile("cp.async.cg.shared.global [%0], [%1], 16;"
                 :: "r"(s), "l"(g));
}
#define CP_COMMIT() asm volatile("cp.async.commit_group;" ::: "memory")
#define CP_WAIT(n)  asm volatile("cp.async.wait_group %0;" :: "n"(n) : "memory")

#define LDSM_X4(r, addr) \
    asm volatile("ldmatrix.sync.aligned.m8n8.x4.shared.b16 {%0,%1,%2,%3}, [%4];" \
        : "=r"((r)[0]), "=r"((r)[1]), "=r"((r)[2]), "=r"((r)[3]) : "r"(addr))

#define MMA_BF16(d, a, b0, b1) \
    asm volatile("mma.sync.aligned.m16n8k16.row.col.f32.bf16.bf16.f32 " \
        "{%0,%1,%2,%3}, {%4,%5,%6,%7}, {%8,%9}, {%0,%1,%2,%3};" \
        : "+f"((d)[0]), "+f"((d)[1]), "+f"((d)[2]), "+f"((d)[3]) \
        : "r"((a)[0]), "r"((a)[1]), "r"((a)[2]), "r"((a)[3]), \
          "r"(b0), "r"(b1))

// Split x into hi (bf16 truncation, packed) and lo (bf16-rounded residual).
__device__ __forceinline__ void split2(float x0, float x1,
                                       uint32_t& hi, uint32_t& lo) {
    uint32_t u0 = __float_as_uint(x0), u1 = __float_as_uint(x1);
    asm("prmt.b32 %0, %1, %2, 0x7632;" : "=r"(hi) : "r"(u0), "r"(u1));
    float r0 = x0 - __uint_as_float(u0 & 0xFFFF0000u);
    float r1 = x1 - __uint_as_float(u1 & 0xFFFF0000u);
    asm("cvt.rn.bf16x2.f32 %0, %1, %2;" : "=r"(lo) : "f"(r1), "f"(r0));
}

// =================================================================
// bf16-split HMMA GEMM NT:  C[M,N] = A[M,K] * W[N,K]^T
//   C = Ah*Wh + Ah*Wl + Al*Wh  (fp32 accum; ~2^-16 rel error)
// Tile 256(M) x 128(N) x 32(K), 256 thr, 8 warps (4x2), warp 64x64.
// cp.async double-buffered raw fp32 staging; bf16 tiles padded to
// 40-elem (80B) rows for conflict-free ldmatrix.
// =================================================================
#define GK 1024
#define BM 256
#define BN 128
#define BK 32
#define NS (GK / BK)          // 32 k-iters
#define PITCHB 80             // bf16 row pitch in bytes (40 elems)

// dynamic smem layout (bytes)
#define RAWA   0              // 2 x 32768
#define RAWB   65536          // 2 x 16384
#define ABH    98304          // 256*80 = 20480
#define ABL    118784
#define BBH    139264         // 128*80 = 10240
#define BBL    149504
#define GEMM_SMEM 159744

__global__ __launch_bounds__(256, 1)
void gemm_tc(const float* __restrict__ A, const float* __restrict__ W,
             float* __restrict__ C) {
    extern __shared__ char smem[];
    const uint32_t sb = smem_u32(smem);
    const int tid  = threadIdx.x;
    const int wid  = tid >> 5;
    const int lane = tid & 31;
    const int wm   = wid & 3;          // warp M index (0..3)
    const int wn   = wid >> 2;         // warp N index (0..1)
    const int bm   = blockIdx.y * BM;
    const int bn   = blockIdx.x * BN;

    // ldmatrix lane address offsets (within bf16 tiles)
    // A frag (x4, m16k16): lanes 0-15 -> rows m0+0..15 @k0; 16-31 -> same rows @k0+8
    const int aRow = (lane & 15);
    const int aKof = (lane >> 4) * 16;        // bytes (8 bf16)
    // B frag (x4, n16k16): lanes 0-7 rows n0..7 @k0; 8-15 @k0+8; 16-23 rows n0+8..15 @k0; 24-31 @k0+8
    const int bRow = ((lane >> 4) << 3) + (lane & 7);
    const int bKof = ((lane >> 3) & 1) * 16;  // bytes

    uint32_t aAddr[4], bAddr[4];
#pragma unroll
    for (int mf = 0; mf < 4; ++mf)
        aAddr[mf] = sb + ABH + (wm * 64 + mf * 16 + aRow) * PITCHB + aKof;
#pragma unroll
    for (int nf2 = 0; nf2 < 4; ++nf2)
        bAddr[nf2] = sb + BBH + (wn * 64 + nf2 * 16 + bRow) * PITCHB + bKof;

    float acc[4][8][4];
#pragma unroll
    for (int i = 0; i < 4; ++i)
#pragma unroll
        for (int j = 0; j < 8; ++j)
#pragma unroll
            for (int c = 0; c < 4; ++c) acc[i][j][c] = 0.f;

    // ---- prologue: prefetch stage 0 ----
#pragma unroll
    for (int u = 0; u < 8; ++u) {
        int q = tid + u * 256;
        cp_async16(sb + RAWA + q * 16,
                   A + (size_t)(bm + (q >> 3)) * GK + (q & 7) * 4);
    }
#pragma unroll
    for (int u = 0; u < 4; ++u) {
        int q = tid + u * 256;
        cp_async16(sb + RAWB + q * 16,
                   W + (size_t)(bn + (q >> 3)) * GK + (q & 7) * 4);
    }
    CP_COMMIT();

    for (int s = 0; s < NS; ++s) {
        const int b = s & 1;

        if (s + 1 < NS) {
            const int nb = b ^ 1;
            const int k0 = (s + 1) * BK;
#pragma unroll
            for (int u = 0; u < 8; ++u) {
                int q = tid + u * 256;
                cp_async16(sb + RAWA + nb * 32768 + q * 16,
                           A + (size_t)(bm + (q >> 3)) * GK + k0 + (q & 7) * 4);
            }
#pragma unroll
            for (int u = 0; u < 4; ++u) {
                int q = tid + u * 256;
                cp_async16(sb + RAWB + nb * 16384 + q * 16,
                           W + (size_t)(bn + (q >> 3)) * GK + k0 + (q & 7) * 4);
            }
            CP_COMMIT();
            CP_WAIT(1);
        } else {
            CP_WAIT(0);
        }
        __syncthreads();   // stage s arrived AND previous mma done

        // ---- convert raw fp32 -> bf16 hi/lo tiles ----
#pragma unroll
        for (int u = 0; u < 8; ++u) {
            int q = tid + u * 256;
            float4 v = *(const float4*)(smem + RAWA + b * 32768 + q * 16);
            int r = q >> 3, cq = q & 7;
            uint2 hi, lo;
            split2(v.x, v.y, hi.x, lo.x);
            split2(v.z, v.w, hi.y, lo.y);
            *(uint2*)(smem + ABH + r * PITCHB + cq * 8) = hi;
            *(uint2*)(smem + ABL + r * PITCHB + cq * 8) = lo;
        }
#pragma unroll
        for (int u = 0; u < 4; ++u) {
            int q = tid + u * 256;
            float4 v = *(const float4*)(smem + RAWB + b * 16384 + q * 16);
            int r = q >> 3, cq = q & 7;
            uint2 hi, lo;
            split2(v.x, v.y, hi.x, lo.x);
            split2(v.z, v.w, hi.y, lo.y);
            *(uint2*)(smem + BBH + r * PITCHB + cq * 8) = hi;
            *(uint2*)(smem + BBL + r * PITCHB + cq * 8) = lo;
        }
        __syncthreads();

        // ---- MMA: 2 k16-steps x 3 split terms ----
#pragma unroll
        for (int ks = 0; ks < 2; ++ks) {
            const int ko = ks * 32;   // 16 bf16 = 32 bytes
            uint32_t ah[4][4], al[4][4], bb[4][4];
#pragma unroll
            for (int mf = 0; mf < 4; ++mf) {
                LDSM_X4(ah[mf], aAddr[mf] + ko);
                LDSM_X4(al[mf], aAddr[mf] + (ABL - ABH) + ko);
            }
#pragma unroll
            for (int nf2 = 0; nf2 < 4; ++nf2)
                LDSM_X4(bb[nf2], bAddr[nf2] + ko);   // B hi
#pragma unroll
            for (int mf = 0; mf < 4; ++mf)
#pragma unroll
                for (int nf2 = 0; nf2 < 4; ++nf2) {
                    MMA_BF16(acc[mf][2*nf2],   ah[mf], bb[nf2][0], bb[nf2][1]);
                    MMA_BF16(acc[mf][2*nf2+1], ah[mf], bb[nf2][2], bb[nf2][3]);
                    MMA_BF16(acc[mf][2*nf2],   al[mf], bb[nf2][0], bb[nf2][1]);
                    MMA_BF16(acc[mf][2*nf2+1], al[mf], bb[nf2][2], bb[nf2][3]);
                }
#pragma unroll
            for (int nf2 = 0; nf2 < 4; ++nf2)
                LDSM_X4(bb[nf2], bAddr[nf2] + (BBL - BBH) + ko);   // B lo
#pragma unroll
            for (int mf = 0; mf < 4; ++mf)
#pragma unroll
                for (int nf2 = 0; nf2 < 4; ++nf2) {
                    MMA_BF16(acc[mf][2*nf2],   ah[mf], bb[nf2][0], bb[nf2][1]);
                    MMA_BF16(acc[mf][2*nf2+1], ah[mf], bb[nf2][2], bb[nf2][3]);
                }
        }
    }

    // ---- epilogue ----
    const int gid = lane >> 2, tig = lane & 3;
#pragma unroll
    for (int mf = 0; mf < 4; ++mf) {
        const int grow = bm + wm * 64 + mf * 16 + gid;
#pragma unroll
        for (int nf = 0; nf < 8; ++nf) {
            const int gcol = bn + wn * 64 + nf * 8 + tig * 2;
            *(float2*)&C[(size_t)grow * Dd + gcol] =
                make_float2(acc[mf][nf][0], acc[mf][nf][1]);
            *(float2*)&C[(size_t)(grow + 8) * Dd + gcol] =
                make_float2(acc[mf][nf][2], acc[mf][nf][3]);
        }
    }
}

// =================================================================
// RMSNorm (per head) + RoPE + transpose to [B,H,S,HD]. fp32 sincos.
// =================================================================
__global__ __launch_bounds__(256)
void norm_rope_kernel(const float* __restrict__ q, const float* __restrict__ k,
                      const float* __restrict__ v,
                      const float* __restrict__ qw, const float* __restrict__ kw,
                      float* __restrict__ qt, float* __restrict__ kt,
                      float* __restrict__ vt) {
    const int gw   = blockIdx.x * 8 + (threadIdx.x >> 5);
    const int lane = threadIdx.x & 31;
    const int h  = gw & (Hh - 1);
    const int bs = gw >> 4;
    const int s  = bs & (Ss - 1);
    const int b  = bs >> 11;

    const size_t src = (size_t)bs * Dd + h * HDd;
    const size_t dst = (((size_t)(b * Hh + h)) * Ss + s) * HDd;

    const float inv = exp2f(-(float)lane * 0.4152410118609203f); // log2(1e4)/32
    float sn, cs;
    sincosf((float)s * inv, &sn, &cs);

    { // Q
        float x1 = q[src + lane], x2 = q[src + lane + 32];
        float ss2 = x1 * x1 + x2 * x2;
#pragma unroll
        for (int off = 16; off; off >>= 1)
            ss2 += __shfl_xor_sync(0xffffffffu, ss2, off);
        float r = rsqrtf(ss2 * (1.0f / 64.0f) + 1e-6f);
        float n1 = x1 * r * qw[lane];
        float n2 = x2 * r * qw[lane + 32];
        qt[dst + lane]      = n1 * cs - n2 * sn;
        qt[dst + lane + 32] = n2 * cs + n1 * sn;
    }
    { // K
        float x1 = k[src + lane], x2 = k[src + lane + 32];
        float ss2 = x1 * x1 + x2 * x2;
#pragma unroll
        for (int off = 16; off; off >>= 1)
            ss2 += __shfl_xor_sync(0xffffffffu, ss2, off);
        float r = rsqrtf(ss2 * (1.0f / 64.0f) + 1e-6f);
        float n1 = x1 * r * kw[lane];
        float n2 = x2 * r * kw[lane + 32];
        kt[dst + lane]      = n1 * cs - n2 * sn;
        kt[dst + lane + 32] = n2 * cs + n1 * sn;
    }
    vt[dst + lane]      = v[src + lane];
    vt[dst + lane + 32] = v[src + lane + 32];
}

// =================================================================
// Flash attention, causal + sink softmax. (proven R1 kernel)
// =================================================================
__global__ __launch_bounds__(256)
void attn_kernel(const float* __restrict__ qt, const float* __restrict__ kt,
                 const float* __restrict__ vt, const float* __restrict__ sinkl,
                 float* __restrict__ ao) {
    __shared__ float Qs[64][64];
    __shared__ float KP[64][64];
    __shared__ float Vs[64][64];

    const int tid = threadIdx.x;
    const int tx  = tid & 15;
    const int ty  = tid >> 4;
    const int qi  = blockIdx.x;
    const int bh  = blockIdx.y;
    const int h   = bh & (Hh - 1);
    const int b   = bh >> 4;

    const float* qb = qt + (size_t)bh * Ss * HDd;
    const float* kb = kt + (size_t)bh * Ss * HDd;
    const float* vb = vt + (size_t)bh * Ss * HDd;
    const int q0 = qi * 64;

#pragma unroll
    for (int u = 0; u < 4; ++u) {
        int f = tid + u * 256;
        int r = f & 63, c = (f >> 6) << 2;
        float4 qv = *(const float4*)&qb[(size_t)(q0 + r) * HDd + c];
        Qs[c+0][r] = qv.x; Qs[c+1][r] = qv.y;
        Qs[c+2][r] = qv.z; Qs[c+3][r] = qv.w;
    }

    const float snk = sinkl[h];
    float m[4], l[4], o[4][4];
#pragma unroll
    for (int i = 0; i < 4; ++i) {
        m[i] = snk; l[i] = 1.0f;
#pragma unroll
        for (int j = 0; j < 4; ++j) o[i][j] = 0.f;
    }

    for (int j = 0; j <= qi; ++j) {
        const float* kjb = kb + (size_t)j * 64 * HDd;
        const float* vjb = vb + (size_t)j * 64 * HDd;

        float4 kreg[4], vreg[4];
#pragma unroll
        for (int u = 0; u < 4; ++u) {
            int f = tid + u * 256;
            int r = f & 63, c = (f >> 6) << 2;
            kreg[u] = *(const float4*)&kjb[(size_t)r * HDd + c];
            int rv = f >> 4, cv = (f & 15) << 2;
            vreg[u] = *(const float4*)&vjb[(size_t)rv * HDd + cv];
        }

        __syncthreads();
#pragma unroll
        for (int u = 0; u < 4; ++u) {
            int f = tid + u * 256;
            int r = f & 63, c = (f >> 6) << 2;
            KP[c+0][r] = kreg[u].x; KP[c+1][r] = kreg[u].y;
            KP[c+2][r] = kreg[u].z; KP[c+3][r] = kreg[u].w;
            int rv = f >> 4, cv = (f & 15) << 2;
            *(float4*)&Vs[rv][cv] = vreg[u];
        }
        __syncthreads();

        float sc[4][4];
#pragma unroll
        for (int i = 0; i < 4; ++i)
#pragma unroll
            for (int jj = 0; jj < 4; ++jj) sc[i][jj] = 0.f;

#pragma unroll
        for (int d = 0; d < 64; ++d) {
            float4 aq = *(const float4*)&Qs[d][ty * 4];
            float4 bk = *(const float4*)&KP[d][tx * 4];
            float qa[4] = {aq.x, aq.y, aq.z, aq.w};
            float ka[4] = {bk.x, bk.y, bk.z, bk.w};
#pragma unroll
            for (int i = 0; i < 4; ++i)
#pragma unroll
                for (int jj = 0; jj < 4; ++jj)
                    sc[i][jj] = fmaf(qa[i], ka[jj], sc[i][jj]);
        }

        const float scale = 0.125f;
        if (j == qi) {
#pragma unroll
            for (int i = 0; i < 4; ++i)
#pragma unroll
                for (int jj = 0; jj < 4; ++jj)
                    sc[i][jj] = (tx * 4 + jj > ty * 4 + i) ? -1e30f
                                                           : sc[i][jj] * scale;
        } else {
#pragma unroll
            for (int i = 0; i < 4; ++i)
#pragma unroll
                for (int jj = 0; jj < 4; ++jj) sc[i][jj] *= scale;
        }

#pragma unroll
        for (int i = 0; i < 4; ++i) {
            float tm = fmaxf(fmaxf(sc[i][0], sc[i][1]),
                             fmaxf(sc[i][2], sc[i][3]));
#pragma unroll
            for (int off = 1; off < 16; off <<= 1)
                tm = fmaxf(tm, __shfl_xor_sync(0xffffffffu, tm, off));
            float mn   = fmaxf(m[i], tm);
            float corr = __expf(m[i] - mn);
            float rs   = 0.f;
#pragma unroll
            for (int jj = 0; jj < 4; ++jj) {
                float p = __expf(sc[i][jj] - mn);
                sc[i][jj] = p;
                rs += p;
            }
#pragma unroll
            for (int off = 1; off < 16; off <<= 1)
                rs += __shfl_xor_sync(0xffffffffu, rs, off);
            l[i] = l[i] * corr + rs;
            m[i] = mn;
#pragma unroll
            for (int jj = 0; jj < 4; ++jj) o[i][jj] *= corr;
        }

        __syncthreads();
#pragma unroll
        for (int jj = 0; jj < 4; ++jj) {
            float4 pv = make_float4(sc[0][jj], sc[1][jj], sc[2][jj], sc[3][jj]);
            *(float4*)&KP[tx * 4 + jj][ty * 4] = pv;
        }
        __syncthreads();

#pragma unroll
        for (int c = 0; c < 64; ++c) {
            float4 pr = *(const float4*)&KP[c][ty * 4];
            float4 vv = *(const float4*)&Vs[c][tx * 4];
            float pa[4] = {pr.x, pr.y, pr.z, pr.w};
            float va[4] = {vv.x, vv.y, vv.z, vv.w};
#pragma unroll
            for (int i = 0; i < 4; ++i)
#pragma unroll
                for (int jj = 0; jj < 4; ++jj)
                    o[i][jj] = fmaf(pa[i], va[jj], o[i][jj]);
        }
    }

#pragma unroll
    for (int i = 0; i < 4; ++i) {
        float inv = 1.0f / l[i];
        float4 ov = make_float4(o[i][0] * inv, o[i][1] * inv,
                                o[i][2] * inv, o[i][3] * inv);
        *(float4*)&ao[((size_t)b * Ss + q0 + ty * 4 + i) * Dd + h * HDd + tx * 4] = ov;
    }
}

// =================================================================
extern "C" void kernel_launch(void* const* d_in, const int* in_sizes, int n_in,
                              void* d_out, int out_size) {
    const float* x  = (const float*)d_in[0];
    const float* wq = (const float*)d_in[1];
    const float* wk = (const float*)d_in[2];
    const float* wv = (const float*)d_in[3];
    const float* wo = (const float*)d_in[4];
    const float* qw = (const float*)d_in[5];
    const float* kw = (const float*)d_in[6];
    const float* sk = (const float*)d_in[7];
    float* out = (float*)d_out;

    float *q, *k, *v, *qtp, *ktp, *vtp, *aop;
    cudaGetSymbolAddress((void**)&q,   g_q);
    cudaGetSymbolAddress((void**)&k,   g_k);
    cudaGetSymbolAddress((void**)&v,   g_v);
    cudaGetSymbolAddress((void**)&qtp, g_qt);
    cudaGetSymbolAddress((void**)&ktp, g_kt);
    cudaGetSymbolAddress((void**)&vtp, g_vt);
    cudaGetSymbolAddress((void**)&aop, g_ao);

    cudaFuncSetAttribute(gemm_tc, cudaFuncAttributeMaxDynamicSharedMemorySize,
                         GEMM_SMEM);

    dim3 gg(Dd / BN, Mrows / BM);   // (8, 16) = 128 CTAs
    gemm_tc<<<gg, 256, GEMM_SMEM>>>(x, wq, q);
    gemm_tc<<<gg, 256, GEMM_SMEM>>>(x, wk, k);
    gemm_tc<<<gg, 256, GEMM_SMEM>>>(x, wv, v);

    norm_rope_kernel<<<(Mrows * Hh) / 8, 256>>>(q, k, v, qw, kw, qtp, ktp, vtp);

    attn_kernel<<<dim3(Ss / 64, Bb * Hh), 256>>>(qtp, ktp, vtp, sk, aop);

    gemm_tc<<<gg, 256, GEMM_SMEM>>>(aop, wo, out);
}

// round 4
// speedup vs baseline: 3.2529x; 1.8768x over previous
#include <cuda_runtime.h>
#include <cuda_bf16.h>
#include <stdint.h>
#include <math.h>

// Problem constants
#define Bb   2
#define Ss   2048
#define Dd   1024
#define Hh   16
#define HDd  64
#define Mrows (Bb*Ss)   // 4096

// ---------------- scratch (no allocs allowed) ----------------
__device__ float    g_qkv[Mrows * 3072];          // fused QKV output (fp32)
__device__ uint16_t g_xh [Mrows * Dd];            // x bf16 hi/lo
__device__ uint16_t g_xl [Mrows * Dd];
__device__ uint16_t g_wh [3072 * Dd];             // fused wq|wk|wv hi/lo
__device__ uint16_t g_wl [3072 * Dd];
__device__ uint16_t g_woh[Dd * Dd];
__device__ uint16_t g_wol[Dd * Dd];
__device__ uint16_t g_qh [Mrows * Dd];            // [B,H,S,64] bf16 hi/lo
__device__ uint16_t g_ql [Mrows * Dd];
__device__ uint16_t g_kh [Mrows * Dd];
__device__ uint16_t g_kl [Mrows * Dd];
__device__ uint16_t g_vh [Mrows * Dd];
__device__ uint16_t g_vl [Mrows * Dd];
__device__ uint16_t g_aoh[Mrows * Dd];            // attn out bf16 hi/lo [B,S,D]
__device__ uint16_t g_aol[Mrows * Dd];

// ================= PTX helpers ==========================
__device__ __forceinline__ uint32_t smem_u32(const void* p) {
    uint32_t a;
    asm("{ .reg .u64 t; cvta.to.shared.u64 t, %1; cvt.u32.u64 %0, t; }"
        : "=r"(a) : "l"(p));
    return a;
}
__device__ __forceinline__ void cp_async16(uint32_t s, const void* g) {
    asm volatile("cp.async.cg.shared.global [%0], [%1], 16;" :: "r"(s), "l"(g));
}
#define CP_COMMIT() asm volatile("cp.async.commit_group;" ::: "memory")
#define CP_WAIT(n)  asm volatile("cp.async.wait_group %0;" :: "n"(n) : "memory")

#define LDSM_X4(r, addr) \
    asm volatile("ldmatrix.sync.aligned.m8n8.x4.shared.b16 {%0,%1,%2,%3}, [%4];" \
        : "=r"((r)[0]), "=r"((r)[1]), "=r"((r)[2]), "=r"((r)[3]) : "r"(addr))
#define LDSM_X4_T(r, addr) \
    asm volatile("ldmatrix.sync.aligned.m8n8.x4.trans.shared.b16 {%0,%1,%2,%3}, [%4];" \
        : "=r"((r)[0]), "=r"((r)[1]), "=r"((r)[2]), "=r"((r)[3]) : "r"(addr))

#define MMA_BF16(d, a, b0, b1) \
    asm volatile("mma.sync.aligned.m16n8k16.row.col.f32.bf16.bf16.f32 " \
        "{%0,%1,%2,%3}, {%4,%5,%6,%7}, {%8,%9}, {%0,%1,%2,%3};" \
        : "+f"((d)[0]), "+f"((d)[1]), "+f"((d)[2]), "+f"((d)[3]) \
        : "r"((a)[0]), "r"((a)[1]), "r"((a)[2]), "r"((a)[3]), \
          "r"(b0), "r"(b1))

// pack(e0 low, e1 high) from bf16 truncations of two floats
__device__ __forceinline__ uint32_t pack_trunc(float a, float b) {
    uint32_t ua = __float_as_uint(a), ub = __float_as_uint(b), r;
    asm("prmt.b32 %0, %1, %2, 0x7632;" : "=r"(r) : "r"(ua), "r"(ub));
    return r;
}
// pack(e0 low, e1 high) with round-to-nearest bf16
__device__ __forceinline__ uint32_t pack_rn(float a, float b) {
    uint32_t r;
    asm("cvt.rn.bf16x2.f32 %0, %1, %2;" : "=r"(r) : "f"(b), "f"(a));
    return r;
}
__device__ __forceinline__ float trunc_bf(float a) {
    return __uint_as_float(__float_as_uint(a) & 0xFFFF0000u);
}
__device__ __forceinline__ void split2(float x0, float x1,
                                       uint32_t& hi, uint32_t& lo) {
    hi = pack_trunc(x0, x1);
    lo = pack_rn(x0 - trunc_bf(x0), x1 - trunc_bf(x1));
}

// =================================================================
// convert: fp32 -> bf16 hi/lo split (vectorized x4)
// =================================================================
__global__ __launch_bounds__(256)
void cvt_split(const float4* __restrict__ src, uint2* __restrict__ hi,
               uint2* __restrict__ lo, int n4) {
    int i = blockIdx.x * 256 + threadIdx.x;
    if (i < n4) {
        float4 v = src[i];
        uint2 h, l;
        split2(v.x, v.y, h.x, l.x);
        split2(v.z, v.w, h.y, l.y);
        hi[i] = h;
        lo[i] = l;
    }
}

// =================================================================
// bf16-split HMMA GEMM NT (pre-converted inputs):
//   C[M,N] = (Ah+Al)[M,K] * (Bh+Bl)[N,K]^T, 3 split terms, fp32 acc
// Tile 128x128x64, 256 thr, warps 4(M)x2(N), warp tile 32x64.
// =================================================================
#define GK 1024
#define PITCH 144                 // 64 bf16 = 128B row + 16B pad
#define G_AH 0
#define G_AL 18432
#define G_BH 36864
#define G_BL 55296
#define G_STG 73728
#define GEMM_SMEM (2 * G_STG)     // 147456

__device__ __forceinline__ void gemm_issue(
    uint32_t stg, const uint16_t* Ah, const uint16_t* Al,
    const uint16_t* Bh, const uint16_t* Bl,
    int bm, int bn, int k0, int tid) {
#pragma unroll
    for (int u = 0; u < 4; ++u) {
        int q = tid + u * 256;          // 0..1023
        int r = q >> 3, c = q & 7;
        uint32_t d = r * PITCH + c * 16;
        size_t sa = (size_t)(bm + r) * GK + k0 + c * 8;
        size_t sb2 = (size_t)(bn + r) * GK + k0 + c * 8;
        cp_async16(stg + G_AH + d, Ah + sa);
        cp_async16(stg + G_AL + d, Al + sa);
        cp_async16(stg + G_BH + d, Bh + sb2);
        cp_async16(stg + G_BL + d, Bl + sb2);
    }
}

__global__ __launch_bounds__(256, 1)
void gemm_bf16s(const uint16_t* __restrict__ Ah, const uint16_t* __restrict__ Al,
                const uint16_t* __restrict__ Bh, const uint16_t* __restrict__ Bl,
                float* __restrict__ C, int N) {
    extern __shared__ char smem[];
    const uint32_t sb = smem_u32(smem);
    const int tid = threadIdx.x;
    const int wid = tid >> 5, lane = tid & 31;
    const int wm = wid & 3, wn = wid >> 2;
    const int gid = lane >> 2, tig = lane & 3;
    const int bm = blockIdx.y * 128, bn = blockIdx.x * 128;

    // fragment smem addresses (relative; add stage base)
    uint32_t aAddr[2], bAddr[4];
#pragma unroll
    for (int mf = 0; mf < 2; ++mf)
        aAddr[mf] = (wm * 32 + mf * 16 + (lane & 15)) * PITCH + (lane >> 4) * 16;
#pragma unroll
    for (int nb = 0; nb < 4; ++nb)
        bAddr[nb] = (wn * 64 + nb * 16 + ((lane >> 4) << 3) + (lane & 7)) * PITCH
                    + ((lane >> 3) & 1) * 16;

    float acc[2][8][4];
#pragma unroll
    for (int i = 0; i < 2; ++i)
#pragma unroll
        for (int j = 0; j < 8; ++j)
#pragma unroll
            for (int c = 0; c < 4; ++c) acc[i][j][c] = 0.f;

    gemm_issue(sb, Ah, Al, Bh, Bl, bm, bn, 0, tid);
    CP_COMMIT();

    for (int s = 0; s < 16; ++s) {
        if (s < 15) {
            gemm_issue(sb + ((s + 1) & 1) * G_STG, Ah, Al, Bh, Bl,
                       bm, bn, (s + 1) * 64, tid);
            CP_COMMIT();
            CP_WAIT(1);
        } else {
            CP_WAIT(0);
        }
        __syncthreads();
        const uint32_t stg = sb + (s & 1) * G_STG;

#pragma unroll
        for (int ks = 0; ks < 4; ++ks) {
            uint32_t ah[2][4], al[2][4];
#pragma unroll
            for (int mf = 0; mf < 2; ++mf) {
                LDSM_X4(ah[mf], stg + G_AH + aAddr[mf] + ks * 32);
                LDSM_X4(al[mf], stg + G_AL + aAddr[mf] + ks * 32);
            }
#pragma unroll
            for (int nb = 0; nb < 4; ++nb) {
                uint32_t bh4[4], bl4[4];
                LDSM_X4(bh4, stg + G_BH + bAddr[nb] + ks * 32);
                LDSM_X4(bl4, stg + G_BL + bAddr[nb] + ks * 32);
#pragma unroll
                for (int mf = 0; mf < 2; ++mf) {
                    MMA_BF16(acc[mf][2*nb],   ah[mf], bh4[0], bh4[1]);
                    MMA_BF16(acc[mf][2*nb+1], ah[mf], bh4[2], bh4[3]);
                    MMA_BF16(acc[mf][2*nb],   ah[mf], bl4[0], bl4[1]);
                    MMA_BF16(acc[mf][2*nb+1], ah[mf], bl4[2], bl4[3]);
                    MMA_BF16(acc[mf][2*nb],   al[mf], bh4[0], bh4[1]);
                    MMA_BF16(acc[mf][2*nb+1], al[mf], bh4[2], bh4[3]);
                }
            }
        }
        __syncthreads();   // protect buffer before next issue overwrites
    }

    // epilogue
#pragma unroll
    for (int mf = 0; mf < 2; ++mf) {
        const int row = bm + wm * 32 + mf * 16 + gid;
#pragma unroll
        for (int nf = 0; nf < 8; ++nf) {
            const int col = bn + wn * 64 + nf * 8 + tig * 2;
            *(float2*)&C[(size_t)row * N + col] =
                make_float2(acc[mf][nf][0], acc[mf][nf][1]);
            *(float2*)&C[(size_t)(row + 8) * N + col] =
                make_float2(acc[mf][nf][2], acc[mf][nf][3]);
        }
    }
}

// =================================================================
// RMSNorm + RoPE + transpose + bf16 hi/lo split.
// Reads fused qkv [4096, 3072]; writes qh/ql, kh/kl, vh/vl [B,H,S,64].
// =================================================================
__device__ __forceinline__ void split_store(uint16_t* hi, uint16_t* lo,
                                            size_t idx, float x) {
    uint32_t u = __float_as_uint(x);
    hi[idx] = (uint16_t)(u >> 16);
    float r = x - __uint_as_float(u & 0xFFFF0000u);
    __nv_bfloat16 t = __float2bfloat16(r);
    lo[idx] = *reinterpret_cast<uint16_t*>(&t);
}

__global__ __launch_bounds__(256)
void norm_rope_kernel(const float* __restrict__ qkv,
                      const float* __restrict__ qw, const float* __restrict__ kw,
                      uint16_t* __restrict__ qh, uint16_t* __restrict__ ql,
                      uint16_t* __restrict__ kh, uint16_t* __restrict__ kl,
                      uint16_t* __restrict__ vh, uint16_t* __restrict__ vl) {
    const int gw   = blockIdx.x * 8 + (threadIdx.x >> 5);
    const int lane = threadIdx.x & 31;
    const int h  = gw & (Hh - 1);
    const int bs = gw >> 4;
    const int s  = bs & (Ss - 1);
    const int b  = bs >> 11;

    const size_t src = (size_t)bs * 3072 + h * HDd;
    const size_t dst = (((size_t)(b * Hh + h)) * Ss + s) * HDd;

    const float inv = exp2f(-(float)lane * 0.4152410118609203f); // log2(1e4)/32
    float sn, cs;
    sincosf((float)s * inv, &sn, &cs);

    { // Q
        float x1 = qkv[src + lane], x2 = qkv[src + lane + 32];
        float ss2 = x1 * x1 + x2 * x2;
#pragma unroll
        for (int off = 16; off; off >>= 1)
            ss2 += __shfl_xor_sync(0xffffffffu, ss2, off);
        float r = rsqrtf(ss2 * (1.0f / 64.0f) + 1e-6f);
        float n1 = x1 * r * qw[lane];
        float n2 = x2 * r * qw[lane + 32];
        split_store(qh, ql, dst + lane,      n1 * cs - n2 * sn);
        split_store(qh, ql, dst + lane + 32, n2 * cs + n1 * sn);
    }
    { // K
        float x1 = qkv[src + 1024 + lane], x2 = qkv[src + 1024 + lane + 32];
        float ss2 = x1 * x1 + x2 * x2;
#pragma unroll
        for (int off = 16; off; off >>= 1)
            ss2 += __shfl_xor_sync(0xffffffffu, ss2, off);
        float r = rsqrtf(ss2 * (1.0f / 64.0f) + 1e-6f);
        float n1 = x1 * r * kw[lane];
        float n2 = x2 * r * kw[lane + 32];
        split_store(kh, kl, dst + lane,      n1 * cs - n2 * sn);
        split_store(kh, kl, dst + lane + 32, n2 * cs + n1 * sn);
    }
    { // V (split only)
        split_store(vh, vl, dst + lane,      qkv[src + 2048 + lane]);
        split_store(vh, vl, dst + lane + 32, qkv[src + 2048 + lane + 32]);
    }
}

// =================================================================
// Tensor-core flash attention, causal + sink softmax, bf16-split.
// Br=128, Bc=64. 8 warps, each owns 16 q-rows x full 64 kv/d cols.
// =================================================================
#define APITCH 144
#define A_QH 0
#define A_QL 18432
#define A_QSZ 36864
#define A_KH 0
#define A_KL 9216
#define A_VH 18432
#define A_VL 27648
#define A_STG 36864
#define ATTN_SMEM (A_QSZ + 2 * A_STG)   // 110592

__device__ __forceinline__ void attn_kv_issue(
    uint32_t stg, const uint16_t* kh, const uint16_t* kl,
    const uint16_t* vh, const uint16_t* vl, size_t seqbase, int j, int tid) {
#pragma unroll
    for (int u = 0; u < 2; ++u) {
        int q = tid + u * 256;          // 0..511
        int r = q >> 3, c = q & 7;
        size_t src = seqbase + (size_t)(j * 64 + r) * 64 + c * 8;
        uint32_t d = r * APITCH + c * 16;
        cp_async16(stg + A_KH + d, kh + src);
        cp_async16(stg + A_KL + d, kl + src);
        cp_async16(stg + A_VH + d, vh + src);
        cp_async16(stg + A_VL + d, vl + src);
    }
}

__global__ __launch_bounds__(256, 1)
void attn_tc(const uint16_t* __restrict__ qh, const uint16_t* __restrict__ ql,
             const uint16_t* __restrict__ kh, const uint16_t* __restrict__ kl,
             const uint16_t* __restrict__ vh, const uint16_t* __restrict__ vl,
             const float* __restrict__ sinkl,
             uint16_t* __restrict__ aoh, uint16_t* __restrict__ aol) {
    extern __shared__ char smem[];
    const uint32_t sb = smem_u32(smem);
    const int tid = threadIdx.x;
    const int wid = tid >> 5, lane = tid & 31;
    const int gid = lane >> 2, tig = lane & 3;
    const int qb = gridDim.x - 1 - blockIdx.x;   // heavy tiles first
    const int bh = blockIdx.y;
    const int h  = bh & (Hh - 1);
    const int b  = bh >> 4;
    const size_t seqbase = (size_t)bh * Ss * HDd;
    const int q0 = qb * 128;

    // ---- prologue: Q tile + KV stage 0 ----
#pragma unroll
    for (int u = 0; u < 4; ++u) {
        int q = tid + u * 256;          // 0..1023
        int r = q >> 3, c = q & 7;
        size_t src = seqbase + (size_t)(q0 + r) * 64 + c * 8;
        uint32_t d = r * APITCH + c * 16;
        cp_async16(sb + A_QH + d, qh + src);
        cp_async16(sb + A_QL + d, ql + src);
    }
    attn_kv_issue(sb + A_QSZ, kh, kl, vh, vl, seqbase, 0, tid);
    CP_COMMIT();

    // fragment smem addresses
    const uint32_t qA = sb + A_QH + (wid * 16 + (lane & 15)) * APITCH
                        + (lane >> 4) * 16;
    uint32_t kB[4];
#pragma unroll
    for (int nb = 0; nb < 4; ++nb)
        kB[nb] = (nb * 16 + ((lane >> 4) << 3) + (lane & 7)) * APITCH
                 + ((lane >> 3) & 1) * 16;
    const uint32_t vBrel = (lane & 15) * APITCH + (lane >> 4) * 16;

    const float snk = sinkl[h];
    float m0 = snk, m1 = snk, l0 = 1.f, l1 = 1.f;
    float o[8][4];
#pragma unroll
    for (int i = 0; i < 8; ++i)
#pragma unroll
        for (int c = 0; c < 4; ++c) o[i][c] = 0.f;

    const int jmax = 2 * qb + 1;
    const int r0g = q0 + wid * 16 + gid;
    const int r1g = r0g + 8;

    for (int j = 0; j <= jmax; ++j) {
        if (j < jmax) {
            attn_kv_issue(sb + A_QSZ + ((j + 1) & 1) * A_STG,
                          kh, kl, vh, vl, seqbase, j + 1, tid);
            CP_COMMIT();
            CP_WAIT(1);
        } else {
            CP_WAIT(0);
        }
        __syncthreads();
        const uint32_t stg = sb + A_QSZ + (j & 1) * A_STG;

        // ---- S = Q K^T (3-term split) ----
        float s[8][4];
#pragma unroll
        for (int i = 0; i < 8; ++i)
#pragma unroll
            for (int c = 0; c < 4; ++c) s[i][c] = 0.f;

#pragma unroll
        for (int ks = 0; ks < 4; ++ks) {
            uint32_t qah[4], qal[4];
            LDSM_X4(qah, qA + ks * 32);
            LDSM_X4(qal, qA + (A_QL - A_QH) + ks * 32);
#pragma unroll
            for (int nb = 0; nb < 4; ++nb) {
                uint32_t kbh[4], kbl[4];
                LDSM_X4(kbh, stg + A_KH + kB[nb] + ks * 32);
                LDSM_X4(kbl, stg + A_KL + kB[nb] + ks * 32);
                MMA_BF16(s[2*nb],   qah, kbh[0], kbh[1]);
                MMA_BF16(s[2*nb+1], qah, kbh[2], kbh[3]);
                MMA_BF16(s[2*nb],   qah, kbl[0], kbl[1]);
                MMA_BF16(s[2*nb+1], qah, kbl[2], kbl[3]);
                MMA_BF16(s[2*nb],   qal, kbh[0], kbh[1]);
                MMA_BF16(s[2*nb+1], qal, kbh[2], kbh[3]);
            }
        }

        // ---- scale + causal mask ----
        const bool msk = (j >= 2 * qb);
#pragma unroll
        for (int nf = 0; nf < 8; ++nf)
#pragma unroll
            for (int c = 0; c < 4; ++c) {
                float v = s[nf][c] * 0.125f;
                if (msk) {
                    int col = j * 64 + nf * 8 + tig * 2 + (c & 1);
                    int row = (c < 2) ? r0g : r1g;
                    if (col > row) v = -1e30f;
                }
                s[nf][c] = v;
            }

        // ---- online softmax (rows gid, gid+8) ----
        float mx0 = -1e30f, mx1 = -1e30f;
#pragma unroll
        for (int nf = 0; nf < 8; ++nf) {
            mx0 = fmaxf(mx0, fmaxf(s[nf][0], s[nf][1]));
            mx1 = fmaxf(mx1, fmaxf(s[nf][2], s[nf][3]));
        }
        mx0 = fmaxf(mx0, __shfl_xor_sync(0xffffffffu, mx0, 1));
        mx0 = fmaxf(mx0, __shfl_xor_sync(0xffffffffu, mx0, 2));
        mx1 = fmaxf(mx1, __shfl_xor_sync(0xffffffffu, mx1, 1));
        mx1 = fmaxf(mx1, __shfl_xor_sync(0xffffffffu, mx1, 2));
        const float mn0 = fmaxf(m0, mx0), mn1 = fmaxf(m1, mx1);
        const float cr0 = __expf(m0 - mn0), cr1 = __expf(m1 - mn1);
        float rs0 = 0.f, rs1 = 0.f;
#pragma unroll
        for (int nf = 0; nf < 8; ++nf) {
            s[nf][0] = __expf(s[nf][0] - mn0);
            s[nf][1] = __expf(s[nf][1] - mn0);
            s[nf][2] = __expf(s[nf][2] - mn1);
            s[nf][3] = __expf(s[nf][3] - mn1);
            rs0 += s[nf][0] + s[nf][1];
            rs1 += s[nf][2] + s[nf][3];
        }
        rs0 += __shfl_xor_sync(0xffffffffu, rs0, 1);
        rs0 += __shfl_xor_sync(0xffffffffu, rs0, 2);
        rs1 += __shfl_xor_sync(0xffffffffu, rs1, 1);
        rs1 += __shfl_xor_sync(0xffffffffu, rs1, 2);
        l0 = l0 * cr0 + rs0; l1 = l1 * cr1 + rs1;
        m0 = mn0; m1 = mn1;
#pragma unroll
        for (int nf = 0; nf < 8; ++nf) {
            o[nf][0] *= cr0; o[nf][1] *= cr0;
            o[nf][2] *= cr1; o[nf][3] *= cr1;
        }

        // ---- O += P V (3-term split; P frags from registers) ----
#pragma unroll
        for (int ks = 0; ks < 4; ++ks) {
            uint32_t pah[4], pal[4];
            pah[0] = pack_trunc(s[2*ks][0],   s[2*ks][1]);
            pah[1] = pack_trunc(s[2*ks][2],   s[2*ks][3]);
            pah[2] = pack_trunc(s[2*ks+1][0], s[2*ks+1][1]);
            pah[3] = pack_trunc(s[2*ks+1][2], s[2*ks+1][3]);
            pal[0] = pack_rn(s[2*ks][0]   - trunc_bf(s[2*ks][0]),
                             s[2*ks][1]   - trunc_bf(s[2*ks][1]));
            pal[1] = pack_rn(s[2*ks][2]   - trunc_bf(s[2*ks][2]),
                             s[2*ks][3]   - trunc_bf(s[2*ks][3]));
            pal[2] = pack_rn(s[2*ks+1][0] - trunc_bf(s[2*ks+1][0]),
                             s[2*ks+1][1] - trunc_bf(s[2*ks+1][1]));
            pal[3] = pack_rn(s[2*ks+1][2] - trunc_bf(s[2*ks+1][2]),
                             s[2*ks+1][3] - trunc_bf(s[2*ks+1][3]));
#pragma unroll
            for (int db = 0; db < 4; ++db) {
                uint32_t vbh[4], vbl[4];
                LDSM_X4_T(vbh, stg + A_VH + vBrel + ks * 16 * APITCH + db * 32);
                LDSM_X4_T(vbl, stg + A_VL + vBrel + ks * 16 * APITCH + db * 32);
                MMA_BF16(o[2*db],   pah, vbh[0], vbh[1]);
                MMA_BF16(o[2*db+1], pah, vbh[2], vbh[3]);
                MMA_BF16(o[2*db],   pah, vbl[0], vbl[1]);
                MMA_BF16(o[2*db+1], pah, vbl[2], vbl[3]);
                MMA_BF16(o[2*db],   pal, vbh[0], vbh[1]);
                MMA_BF16(o[2*db+1], pal, vbh[2], vbh[3]);
            }
        }
        __syncthreads();   // protect KV buffer before next issue
    }

    // ---- epilogue: normalize, split to bf16 hi/lo, write [B,S,D] ----
    const float i0 = 1.f / l0, i1 = 1.f / l1;
#pragma unroll
    for (int nf = 0; nf < 8; ++nf) {
        const int col = h * HDd + nf * 8 + tig * 2;
        {
            float y0 = o[nf][0] * i0, y1 = o[nf][1] * i0;
            size_t idx = ((size_t)(b * Ss + r0g)) * Dd + col;
            *(uint32_t*)&aoh[idx] = pack_trunc(y0, y1);
            *(uint32_t*)&aol[idx] = pack_rn(y0 - trunc_bf(y0), y1 - trunc_bf(y1));
        }
        {
            float y2 = o[nf][2] * i1, y3 = o[nf][3] * i1;
            size_t idx = ((size_t)(b * Ss + r1g)) * Dd + col;
            *(uint32_t*)&aoh[idx] = pack_trunc(y2, y3);
            *(uint32_t*)&aol[idx] = pack_rn(y2 - trunc_bf(y2), y3 - trunc_bf(y3));
        }
    }
}

// =================================================================
extern "C" void kernel_launch(void* const* d_in, const int* in_sizes, int n_in,
                              void* d_out, int out_size) {
    const float* x  = (const float*)d_in[0];
    const float* wq = (const float*)d_in[1];
    const float* wk = (const float*)d_in[2];
    const float* wv = (const float*)d_in[3];
    const float* wo = (const float*)d_in[4];
    const float* qw = (const float*)d_in[5];
    const float* kw = (const float*)d_in[6];
    const float* sk = (const float*)d_in[7];
    float* out = (float*)d_out;

    float *qkv;
    uint16_t *xh, *xl, *wh, *wl, *woh, *wol;
    uint16_t *qhp, *qlp, *khp, *klp, *vhp, *vlp, *aoh, *aol;
    cudaGetSymbolAddress((void**)&qkv, g_qkv);
    cudaGetSymbolAddress((void**)&xh,  g_xh);
    cudaGetSymbolAddress((void**)&xl,  g_xl);
    cudaGetSymbolAddress((void**)&wh,  g_wh);
    cudaGetSymbolAddress((void**)&wl,  g_wl);
    cudaGetSymbolAddress((void**)&woh, g_woh);
    cudaGetSymbolAddress((void**)&wol, g_wol);
    cudaGetSymbolAddress((void**)&qhp, g_qh);
    cudaGetSymbolAddress((void**)&qlp, g_ql);
    cudaGetSymbolAddress((void**)&khp, g_kh);
    cudaGetSymbolAddress((void**)&klp, g_kl);
    cudaGetSymbolAddress((void**)&vhp, g_vh);
    cudaGetSymbolAddress((void**)&vlp, g_vl);
    cudaGetSymbolAddress((void**)&aoh, g_aoh);
    cudaGetSymbolAddress((void**)&aol, g_aol);

    cudaFuncSetAttribute(gemm_bf16s, cudaFuncAttributeMaxDynamicSharedMemorySize,
                         GEMM_SMEM);
    cudaFuncSetAttribute(attn_tc, cudaFuncAttributeMaxDynamicSharedMemorySize,
                         ATTN_SMEM);

    // ---- converts ----
    cvt_split<<<4096, 256>>>((const float4*)x, (uint2*)xh, (uint2*)xl, 1048576);
    cvt_split<<<1024, 256>>>((const float4*)wq, (uint2*)wh, (uint2*)wl, 262144);
    cvt_split<<<1024, 256>>>((const float4*)wk, (uint2*)wh + 262144,
                             (uint2*)wl + 262144, 262144);
    cvt_split<<<1024, 256>>>((const float4*)wv, (uint2*)wh + 524288,
                             (uint2*)wl + 524288, 262144);
    cvt_split<<<1024, 256>>>((const float4*)wo, (uint2*)woh, (uint2*)wol, 262144);

    // ---- fused QKV projection: [4096,1024] x [3072,1024]^T ----
    gemm_bf16s<<<dim3(3072 / 128, Mrows / 128), 256, GEMM_SMEM>>>(
        xh, xl, wh, wl, qkv, 3072);

    // ---- norm + rope + split ----
    norm_rope_kernel<<<(Mrows * Hh) / 8, 256>>>(qkv, qw, kw,
                                                qhp, qlp, khp, klp, vhp, vlp);

    // ---- flash attention ----
    attn_tc<<<dim3(Ss / 128, Bb * Hh), 256, ATTN_SMEM>>>(
        qhp, qlp, khp, klp, vhp, vlp, sk, aoh, aol);

    // ---- output projection ----
    gemm_bf16s<<<dim3(Dd / 128, Mrows / 128), 256, GEMM_SMEM>>>(
        aoh, aol, woh, wol, out, Dd);
}

// round 5
// speedup vs baseline: 3.2950x; 1.0130x over previous
#include <cuda_runtime.h>
#include <cuda_bf16.h>
#include <stdint.h>
#include <math.h>

// Problem constants
#define Bb   2
#define Ss   2048
#define Dd   1024
#define Hh   16
#define HDd  64
#define Mrows (Bb*Ss)   // 4096

// ---------------- scratch (no allocs allowed) ----------------
__device__ float    g_qkv[Mrows * 3072];          // fused QKV output (fp32)
__device__ uint16_t g_xh [Mrows * Dd];            // x bf16 hi/lo
__device__ uint16_t g_xl [Mrows * Dd];
__device__ uint16_t g_wh [3072 * Dd];             // fused wq|wk|wv hi/lo
__device__ uint16_t g_wl [3072 * Dd];
__device__ uint16_t g_woh[Dd * Dd];
__device__ uint16_t g_wol[Dd * Dd];
__device__ uint16_t g_qh [Mrows * Dd];            // [B,H,S,64] bf16 hi/lo
__device__ uint16_t g_ql [Mrows * Dd];
__device__ uint16_t g_kh [Mrows * Dd];
__device__ uint16_t g_kl [Mrows * Dd];
__device__ uint16_t g_vh [Mrows * Dd];
__device__ uint16_t g_vl [Mrows * Dd];
__device__ uint16_t g_aoh[Mrows * Dd];            // attn out bf16 hi/lo [B,S,D]
__device__ uint16_t g_aol[Mrows * Dd];

// ================= PTX helpers ==========================
__device__ __forceinline__ uint32_t smem_u32(const void* p) {
    uint32_t a;
    asm("{ .reg .u64 t; cvta.to.shared.u64 t, %1; cvt.u32.u64 %0, t; }"
        : "=r"(a) : "l"(p));
    return a;
}
__device__ __forceinline__ void cp_async16(uint32_t s, const void* g) {
    asm volatile("cp.async.cg.shared.global [%0], [%1], 16;" :: "r"(s), "l"(g));
}
#define CP_COMMIT() asm volatile("cp.async.commit_group;" ::: "memory")
#define CP_WAIT(n)  asm volatile("cp.async.wait_group %0;" :: "n"(n) : "memory")

#define LDSM_X4(r, addr) \
    asm volatile("ldmatrix.sync.aligned.m8n8.x4.shared.b16 {%0,%1,%2,%3}, [%4];" \
        : "=r"((r)[0]), "=r"((r)[1]), "=r"((r)[2]), "=r"((r)[3]) : "r"(addr))
#define LDSM_X4_T(r, addr) \
    asm volatile("ldmatrix.sync.aligned.m8n8.x4.trans.shared.b16 {%0,%1,%2,%3}, [%4];" \
        : "=r"((r)[0]), "=r"((r)[1]), "=r"((r)[2]), "=r"((r)[3]) : "r"(addr))

#define MMA_BF16(d, a, b0, b1) \
    asm volatile("mma.sync.aligned.m16n8k16.row.col.f32.bf16.bf16.f32 " \
        "{%0,%1,%2,%3}, {%4,%5,%6,%7}, {%8,%9}, {%0,%1,%2,%3};" \
        : "+f"((d)[0]), "+f"((d)[1]), "+f"((d)[2]), "+f"((d)[3]) \
        : "r"((a)[0]), "r"((a)[1]), "r"((a)[2]), "r"((a)[3]), \
          "r"(b0), "r"(b1))

__device__ __forceinline__ uint32_t pack_trunc(float a, float b) {
    uint32_t ua = __float_as_uint(a), ub = __float_as_uint(b), r;
    asm("prmt.b32 %0, %1, %2, 0x7632;" : "=r"(r) : "r"(ua), "r"(ub));
    return r;
}
__device__ __forceinline__ uint32_t pack_rn(float a, float b) {
    uint32_t r;
    asm("cvt.rn.bf16x2.f32 %0, %1, %2;" : "=r"(r) : "f"(b), "f"(a));
    return r;
}
__device__ __forceinline__ float trunc_bf(float a) {
    return __uint_as_float(__float_as_uint(a) & 0xFFFF0000u);
}
__device__ __forceinline__ void split2(float x0, float x1,
                                       uint32_t& hi, uint32_t& lo) {
    hi = pack_trunc(x0, x1);
    lo = pack_rn(x0 - trunc_bf(x0), x1 - trunc_bf(x1));
}

// =================================================================
// fused convert: x, wq|wk|wv (concat), wo  -> bf16 hi/lo splits
// linear index over 2M float4s
// =================================================================
__global__ __launch_bounds__(256)
void cvt_all(const float4* __restrict__ x,  const float4* __restrict__ wq,
             const float4* __restrict__ wk, const float4* __restrict__ wv,
             const float4* __restrict__ wo,
             uint2* __restrict__ xh, uint2* __restrict__ xl,
             uint2* __restrict__ wh, uint2* __restrict__ wl,
             uint2* __restrict__ woh, uint2* __restrict__ wol) {
    int i = blockIdx.x * 256 + threadIdx.x;     // 0 .. 2M-1
    const float4* src;
    uint2 *dh, *dl;
    if (i < 1048576) {
        src = x + i; dh = xh + i; dl = xl + i;
    } else {
        int i2 = i - 1048576;
        int reg = i2 >> 18;            // 0..3 (262144 each)
        int off = i2 & 262143;
        if (reg == 0)      { src = wq + off; dh = wh + off;          dl = wl + off; }
        else if (reg == 1) { src = wk + off; dh = wh + 262144 + off; dl = wl + 262144 + off; }
        else if (reg == 2) { src = wv + off; dh = wh + 524288 + off; dl = wl + 524288 + off; }
        else               { src = wo + off; dh = woh + off;         dl = wol + off; }
    }
    float4 v = *src;
    uint2 h, l;
    split2(v.x, v.y, h.x, l.x);
    split2(v.z, v.w, h.y, l.y);
    *dh = h;
    *dl = l;
}

// =================================================================
// bf16-split HMMA GEMM NT v2:
//   C[M,N] = (Ah+Al)(Bh+Bl)^T, 3 split terms, fp32 acc
// Tile 256x128x32, 256 thr, warps 4(M)x2(N), warp tile 64x64.
// 3-stage cp.async ring, 1 syncthreads/stage.
// =================================================================
#define GK 1024
#define GPITCH 80                 // 32 bf16 = 64B row + 16B pad
#define G2_AH 0                   // 256*80 = 20480
#define G2_AL 20480
#define G2_BH 40960               // 128*80 = 10240
#define G2_BL 51200
#define G2_STG 61440
#define GEMM_SMEM (3 * G2_STG)    // 184320

__device__ __forceinline__ void gemm_issue(
    uint32_t stg, const uint16_t* __restrict__ Ah, const uint16_t* __restrict__ Al,
    const uint16_t* __restrict__ Bh, const uint16_t* __restrict__ Bl,
    int bm, int bn, int k0, int tid) {
#pragma unroll
    for (int u = 0; u < 4; ++u) {
        int q = tid + u * 256;          // 0..1023
        int r = q >> 2, c = q & 3;
        uint32_t d = r * GPITCH + c * 16;
        size_t src = (size_t)(bm + r) * GK + k0 + c * 8;
        cp_async16(stg + G2_AH + d, Ah + src);
        cp_async16(stg + G2_AL + d, Al + src);
    }
#pragma unroll
    for (int u = 0; u < 2; ++u) {
        int q = tid + u * 256;          // 0..511
        int r = q >> 2, c = q & 3;
        uint32_t d = r * GPITCH + c * 16;
        size_t src = (size_t)(bn + r) * GK + k0 + c * 8;
        cp_async16(stg + G2_BH + d, Bh + src);
        cp_async16(stg + G2_BL + d, Bl + src);
    }
}

__global__ __launch_bounds__(256, 1)
void gemm_bf16s(const uint16_t* __restrict__ Ah, const uint16_t* __restrict__ Al,
                const uint16_t* __restrict__ Bh, const uint16_t* __restrict__ Bl,
                float* __restrict__ C, int N) {
    extern __shared__ char smem[];
    const uint32_t sb = smem_u32(smem);
    const int tid = threadIdx.x;
    const int wid = tid >> 5, lane = tid & 31;
    const int wm = wid & 3, wn = wid >> 2;
    const int gid = lane >> 2, tig = lane & 3;
    const int bm = blockIdx.y * 256, bn = blockIdx.x * 128;
    const int NS = GK / 32;   // 32 stages

    // fragment addresses (relative to stage base)
    uint32_t aAddr[4], bAddr[4];
#pragma unroll
    for (int mf = 0; mf < 4; ++mf)
        aAddr[mf] = G2_AH + (wm * 64 + mf * 16 + (lane & 15)) * GPITCH
                    + (lane >> 4) * 16;
#pragma unroll
    for (int nb = 0; nb < 4; ++nb)
        bAddr[nb] = G2_BH + (wn * 64 + nb * 16 + ((lane >> 4) << 3) + (lane & 7))
                    * GPITCH + ((lane >> 3) & 1) * 16;

    float acc[4][8][4];
#pragma unroll
    for (int i = 0; i < 4; ++i)
#pragma unroll
        for (int j = 0; j < 8; ++j)
#pragma unroll
            for (int c = 0; c < 4; ++c) acc[i][j][c] = 0.f;

    gemm_issue(sb, Ah, Al, Bh, Bl, bm, bn, 0, tid);
    CP_COMMIT();
    gemm_issue(sb + G2_STG, Ah, Al, Bh, Bl, bm, bn, 32, tid);
    CP_COMMIT();

    for (int s = 0; s < NS; ++s) {
        if (s < NS - 1) { CP_WAIT(1); } else { CP_WAIT(0); }
        __syncthreads();
        if (s + 2 < NS) {
            gemm_issue(sb + ((s + 2) % 3) * G2_STG, Ah, Al, Bh, Bl,
                       bm, bn, (s + 2) * 32, tid);
            CP_COMMIT();
        }
        const uint32_t stg = sb + (s % 3) * G2_STG;

#pragma unroll
        for (int ks = 0; ks < 2; ++ks) {
            uint32_t bh4[4][4], bl4[4][4];
#pragma unroll
            for (int nb = 0; nb < 4; ++nb) {
                LDSM_X4(bh4[nb], stg + bAddr[nb] + ks * 32);
                LDSM_X4(bl4[nb], stg + bAddr[nb] + (G2_BL - G2_BH) + ks * 32);
            }
#pragma unroll
            for (int mf = 0; mf < 4; ++mf) {
                uint32_t ah[4], al[4];
                LDSM_X4(ah, stg + aAddr[mf] + ks * 32);
                LDSM_X4(al, stg + aAddr[mf] + (G2_AL - G2_AH) + ks * 32);
#pragma unroll
                for (int nb = 0; nb < 4; ++nb) {
                    MMA_BF16(acc[mf][2*nb],   ah, bh4[nb][0], bh4[nb][1]);
                    MMA_BF16(acc[mf][2*nb+1], ah, bh4[nb][2], bh4[nb][3]);
                    MMA_BF16(acc[mf][2*nb],   ah, bl4[nb][0], bl4[nb][1]);
                    MMA_BF16(acc[mf][2*nb+1], ah, bl4[nb][2], bl4[nb][3]);
                    MMA_BF16(acc[mf][2*nb],   al, bh4[nb][0], bh4[nb][1]);
                    MMA_BF16(acc[mf][2*nb+1], al, bh4[nb][2], bh4[nb][3]);
                }
            }
        }
    }

    // epilogue
#pragma unroll
    for (int mf = 0; mf < 4; ++mf) {
        const int row = bm + wm * 64 + mf * 16 + gid;
#pragma unroll
        for (int nf = 0; nf < 8; ++nf) {
            const int col = bn + wn * 64 + nf * 8 + tig * 2;
            *(float2*)&C[(size_t)row * N + col] =
                make_float2(acc[mf][nf][0], acc[mf][nf][1]);
            *(float2*)&C[(size_t)(row + 8) * N + col] =
                make_float2(acc[mf][nf][2], acc[mf][nf][3]);
        }
    }
}

// =================================================================
// RMSNorm + RoPE + transpose + bf16 hi/lo split.
// =================================================================
__device__ __forceinline__ void split_store(uint16_t* hi, uint16_t* lo,
                                            size_t idx, float x) {
    uint32_t u = __float_as_uint(x);
    hi[idx] = (uint16_t)(u >> 16);
    float r = x - __uint_as_float(u & 0xFFFF0000u);
    __nv_bfloat16 t = __float2bfloat16(r);
    lo[idx] = *reinterpret_cast<uint16_t*>(&t);
}

__global__ __launch_bounds__(256)
void norm_rope_kernel(const float* __restrict__ qkv,
                      const float* __restrict__ qw, const float* __restrict__ kw,
                      uint16_t* __restrict__ qh, uint16_t* __restrict__ ql,
                      uint16_t* __restrict__ kh, uint16_t* __restrict__ kl,
                      uint16_t* __restrict__ vh, uint16_t* __restrict__ vl) {
    const int gw   = blockIdx.x * 8 + (threadIdx.x >> 5);
    const int lane = threadIdx.x & 31;
    const int h  = gw & (Hh - 1);
    const int bs = gw >> 4;
    const int s  = bs & (Ss - 1);
    const int b  = bs >> 11;

    const size_t src = (size_t)bs * 3072 + h * HDd;
    const size_t dst = (((size_t)(b * Hh + h)) * Ss + s) * HDd;

    const float inv = exp2f(-(float)lane * 0.4152410118609203f);
    float sn, cs;
    sincosf((float)s * inv, &sn, &cs);

    { // Q
        float x1 = qkv[src + lane], x2 = qkv[src + lane + 32];
        float ss2 = x1 * x1 + x2 * x2;
#pragma unroll
        for (int off = 16; off; off >>= 1)
            ss2 += __shfl_xor_sync(0xffffffffu, ss2, off);
        float r = rsqrtf(ss2 * (1.0f / 64.0f) + 1e-6f);
        float n1 = x1 * r * qw[lane];
        float n2 = x2 * r * qw[lane + 32];
        split_store(qh, ql, dst + lane,      n1 * cs - n2 * sn);
        split_store(qh, ql, dst + lane + 32, n2 * cs + n1 * sn);
    }
    { // K
        float x1 = qkv[src + 1024 + lane], x2 = qkv[src + 1024 + lane + 32];
        float ss2 = x1 * x1 + x2 * x2;
#pragma unroll
        for (int off = 16; off; off >>= 1)
            ss2 += __shfl_xor_sync(0xffffffffu, ss2, off);
        float r = rsqrtf(ss2 * (1.0f / 64.0f) + 1e-6f);
        float n1 = x1 * r * kw[lane];
        float n2 = x2 * r * kw[lane + 32];
        split_store(kh, kl, dst + lane,      n1 * cs - n2 * sn);
        split_store(kh, kl, dst + lane + 32, n2 * cs + n1 * sn);
    }
    { // V
        split_store(vh, vl, dst + lane,      qkv[src + 2048 + lane]);
        split_store(vh, vl, dst + lane + 32, qkv[src + 2048 + lane + 32]);
    }
}

// =================================================================
// Tensor-core flash attention, causal + sink, bf16-split, 3-stage ring
// =================================================================
#define APITCH 144
#define A_QH 0
#define A_QL 18432
#define A_QSZ 36864
#define A_KH 0
#define A_KL 9216
#define A_VH 18432
#define A_VL 27648
#define A_STG 36864
#define ATTN_SMEM (A_QSZ + 3 * A_STG)   // 147456

__device__ __forceinline__ void attn_kv_issue(
    uint32_t stg, const uint16_t* __restrict__ kh, const uint16_t* __restrict__ kl,
    const uint16_t* __restrict__ vh, const uint16_t* __restrict__ vl,
    size_t seqbase, int j, int tid) {
#pragma unroll
    for (int u = 0; u < 2; ++u) {
        int q = tid + u * 256;          // 0..511
        int r = q >> 3, c = q & 7;
        size_t src = seqbase + (size_t)(j * 64 + r) * 64 + c * 8;
        uint32_t d = r * APITCH + c * 16;
        cp_async16(stg + A_KH + d, kh + src);
        cp_async16(stg + A_KL + d, kl + src);
        cp_async16(stg + A_VH + d, vh + src);
        cp_async16(stg + A_VL + d, vl + src);
    }
}

__global__ __launch_bounds__(256, 1)
void attn_tc(const uint16_t* __restrict__ qh, const uint16_t* __restrict__ ql,
             const uint16_t* __restrict__ kh, const uint16_t* __restrict__ kl,
             const uint16_t* __restrict__ vh, const uint16_t* __restrict__ vl,
             const float* __restrict__ sinkl,
             uint16_t* __restrict__ aoh, uint16_t* __restrict__ aol) {
    extern __shared__ char smem[];
    const uint32_t sb = smem_u32(smem);
    const int tid = threadIdx.x;
    const int wid = tid >> 5, lane = tid & 31;
    const int gid = lane >> 2, tig = lane & 3;
    const int qb = gridDim.x - 1 - blockIdx.x;   // heavy tiles first
    const int bh = blockIdx.y;
    const int h  = bh & (Hh - 1);
    const int b  = bh >> 4;
    const size_t seqbase = (size_t)bh * Ss * HDd;
    const int q0 = qb * 128;
    const int jmax = 2 * qb + 1;

    // ---- prologue: Q tile + KV stage 0 (group 0), stage 1 (group 1) ----
#pragma unroll
    for (int u = 0; u < 4; ++u) {
        int q = tid + u * 256;
        int r = q >> 3, c = q & 7;
        size_t src = seqbase + (size_t)(q0 + r) * 64 + c * 8;
        uint32_t d = r * APITCH + c * 16;
        cp_async16(sb + A_QH + d, qh + src);
        cp_async16(sb + A_QL + d, ql + src);
    }
    attn_kv_issue(sb + A_QSZ, kh, kl, vh, vl, seqbase, 0, tid);
    CP_COMMIT();
    attn_kv_issue(sb + A_QSZ + A_STG, kh, kl, vh, vl, seqbase, 1, tid);
    CP_COMMIT();

    const uint32_t qA = sb + A_QH + (wid * 16 + (lane & 15)) * APITCH
                        + (lane >> 4) * 16;
    uint32_t kB[4];
#pragma unroll
    for (int nb = 0; nb < 4; ++nb)
        kB[nb] = (nb * 16 + ((lane >> 4) << 3) + (lane & 7)) * APITCH
                 + ((lane >> 3) & 1) * 16;
    const uint32_t vBrel = (lane & 15) * APITCH + (lane >> 4) * 16;

    const float snk = sinkl[h];
    float m0 = snk, m1 = snk, l0 = 1.f, l1 = 1.f;
    float o[8][4];
#pragma unroll
    for (int i = 0; i < 8; ++i)
#pragma unroll
        for (int c = 0; c < 4; ++c) o[i][c] = 0.f;

    const int r0g = q0 + wid * 16 + gid;
    const int r1g = r0g + 8;

    for (int j = 0; j <= jmax; ++j) {
        if (j < jmax) { CP_WAIT(1); } else { CP_WAIT(0); }
        __syncthreads();
        if (j + 2 <= jmax) {
            attn_kv_issue(sb + A_QSZ + ((j + 2) % 3) * A_STG,
                          kh, kl, vh, vl, seqbase, j + 2, tid);
            CP_COMMIT();
        }
        const uint32_t stg = sb + A_QSZ + (j % 3) * A_STG;

        // ---- S = Q K^T (3-term split) ----
        float s[8][4];
#pragma unroll
        for (int i = 0; i < 8; ++i)
#pragma unroll
            for (int c = 0; c < 4; ++c) s[i][c] = 0.f;

#pragma unroll
        for (int ks = 0; ks < 4; ++ks) {
            uint32_t qah[4], qal[4];
            LDSM_X4(qah, qA + ks * 32);
            LDSM_X4(qal, qA + (A_QL - A_QH) + ks * 32);
#pragma unroll
            for (int nb = 0; nb < 4; ++nb) {
                uint32_t kbh[4], kbl[4];
                LDSM_X4(kbh, stg + A_KH + kB[nb] + ks * 32);
                LDSM_X4(kbl, stg + A_KL + kB[nb] + ks * 32);
                MMA_BF16(s[2*nb],   qah, kbh[0], kbh[1]);
                MMA_BF16(s[2*nb+1], qah, kbh[2], kbh[3]);
                MMA_BF16(s[2*nb],   qah, kbl[0], kbl[1]);
                MMA_BF16(s[2*nb+1], qah, kbl[2], kbl[3]);
                MMA_BF16(s[2*nb],   qal, kbh[0], kbh[1]);
                MMA_BF16(s[2*nb+1], qal, kbh[2], kbh[3]);
            }
        }

        // ---- scale + causal mask ----
        const bool msk = (j >= 2 * qb);
#pragma unroll
        for (int nf = 0; nf < 8; ++nf)
#pragma unroll
            for (int c = 0; c < 4; ++c) {
                float v = s[nf][c] * 0.125f;
                if (msk) {
                    int col = j * 64 + nf * 8 + tig * 2 + (c & 1);
                    int row = (c < 2) ? r0g : r1g;
                    if (col > row) v = -1e30f;
                }
                s[nf][c] = v;
            }

        // ---- online softmax ----
        float mx0 = -1e30f, mx1 = -1e30f;
#pragma unroll
        for (int nf = 0; nf < 8; ++nf) {
            mx0 = fmaxf(mx0, fmaxf(s[nf][0], s[nf][1]));
            mx1 = fmaxf(mx1, fmaxf(s[nf][2], s[nf][3]));
        }
        mx0 = fmaxf(mx0, __shfl_xor_sync(0xffffffffu, mx0, 1));
        mx0 = fmaxf(mx0, __shfl_xor_sync(0xffffffffu, mx0, 2));
        mx1 = fmaxf(mx1, __shfl_xor_sync(0xffffffffu, mx1, 1));
        mx1 = fmaxf(mx1, __shfl_xor_sync(0xffffffffu, mx1, 2));
        const float mn0 = fmaxf(m0, mx0), mn1 = fmaxf(m1, mx1);
        const float cr0 = __expf(m0 - mn0), cr1 = __expf(m1 - mn1);
        float rs0 = 0.f, rs1 = 0.f;
#pragma unroll
        for (int nf = 0; nf < 8; ++nf) {
            s[nf][0] = __expf(s[nf][0] - mn0);
            s[nf][1] = __expf(s[nf][1] - mn0);
            s[nf][2] = __expf(s[nf][2] - mn1);
            s[nf][3] = __expf(s[nf][3] - mn1);
            rs0 += s[nf][0] + s[nf][1];
            rs1 += s[nf][2] + s[nf][3];
        }
        rs0 += __shfl_xor_sync(0xffffffffu, rs0, 1);
        rs0 += __shfl_xor_sync(0xffffffffu, rs0, 2);
        rs1 += __shfl_xor_sync(0xffffffffu, rs1, 1);
        rs1 += __shfl_xor_sync(0xffffffffu, rs1, 2);
        l0 = l0 * cr0 + rs0; l1 = l1 * cr1 + rs1;
        m0 = mn0; m1 = mn1;
#pragma unroll
        for (int nf = 0; nf < 8; ++nf) {
            o[nf][0] *= cr0; o[nf][1] *= cr0;
            o[nf][2] *= cr1; o[nf][3] *= cr1;
        }

        // ---- O += P V (3-term split) ----
#pragma unroll
        for (int ks = 0; ks < 4; ++ks) {
            uint32_t pah[4], pal[4];
            pah[0] = pack_trunc(s[2*ks][0],   s[2*ks][1]);
            pah[1] = pack_trunc(s[2*ks][2],   s[2*ks][3]);
            pah[2] = pack_trunc(s[2*ks+1][0], s[2*ks+1][1]);
            pah[3] = pack_trunc(s[2*ks+1][2], s[2*ks+1][3]);
            pal[0] = pack_rn(s[2*ks][0]   - trunc_bf(s[2*ks][0]),
                             s[2*ks][1]   - trunc_bf(s[2*ks][1]));
            pal[1] = pack_rn(s[2*ks][2]   - trunc_bf(s[2*ks][2]),
                             s[2*ks][3]   - trunc_bf(s[2*ks][3]));
            pal[2] = pack_rn(s[2*ks+1][0] - trunc_bf(s[2*ks+1][0]),
                             s[2*ks+1][1] - trunc_bf(s[2*ks+1][1]));
            pal[3] = pack_rn(s[2*ks+1][2] - trunc_bf(s[2*ks+1][2]),
                             s[2*ks+1][3] - trunc_bf(s[2*ks+1][3]));
#pragma unroll
            for (int db = 0; db < 4; ++db) {
                uint32_t vbh[4], vbl[4];
                LDSM_X4_T(vbh, stg + A_VH + vBrel + ks * 16 * APITCH + db * 32);
                LDSM_X4_T(vbl, stg + A_VL + vBrel + ks * 16 * APITCH + db * 32);
                MMA_BF16(o[2*db],   pah, vbh[0], vbh[1]);
                MMA_BF16(o[2*db+1], pah, vbh[2], vbh[3]);
                MMA_BF16(o[2*db],   pah, vbl[0], vbl[1]);
                MMA_BF16(o[2*db+1], pah, vbl[2], vbl[3]);
                MMA_BF16(o[2*db],   pal, vbh[0], vbh[1]);
                MMA_BF16(o[2*db+1], pal, vbh[2], vbh[3]);
            }
        }
    }

    // ---- epilogue ----
    const float i0 = 1.f / l0, i1 = 1.f / l1;
#pragma unroll
    for (int nf = 0; nf < 8; ++nf) {
        const int col = h * HDd + nf * 8 + tig * 2;
        {
            float y0 = o[nf][0] * i0, y1 = o[nf][1] * i0;
            size_t idx = ((size_t)(b * Ss + r0g)) * Dd + col;
            *(uint32_t*)&aoh[idx] = pack_trunc(y0, y1);
            *(uint32_t*)&aol[idx] = pack_rn(y0 - trunc_bf(y0), y1 - trunc_bf(y1));
        }
        {
            float y2 = o[nf][2] * i1, y3 = o[nf][3] * i1;
            size_t idx = ((size_t)(b * Ss + r1g)) * Dd + col;
            *(uint32_t*)&aoh[idx] = pack_trunc(y2, y3);
            *(uint32_t*)&aol[idx] = pack_rn(y2 - trunc_bf(y2), y3 - trunc_bf(y3));
        }
    }
}

// =================================================================
extern "C" void kernel_launch(void* const* d_in, const int* in_sizes, int n_in,
                              void* d_out, int out_size) {
    const float* x  = (const float*)d_in[0];
    const float* wq = (const float*)d_in[1];
    const float* wk = (const float*)d_in[2];
    const float* wv = (const float*)d_in[3];
    const float* wo = (const float*)d_in[4];
    const float* qw = (const float*)d_in[5];
    const float* kw = (const float*)d_in[6];
    const float* sk = (const float*)d_in[7];
    float* out = (float*)d_out;

    float *qkv;
    uint16_t *xh, *xl, *wh, *wl, *woh, *wol;
    uint16_t *qhp, *qlp, *khp, *klp, *vhp, *vlp, *aoh, *aol;
    cudaGetSymbolAddress((void**)&qkv, g_qkv);
    cudaGetSymbolAddress((void**)&xh,  g_xh);
    cudaGetSymbolAddress((void**)&xl,  g_xl);
    cudaGetSymbolAddress((void**)&wh,  g_wh);
    cudaGetSymbolAddress((void**)&wl,  g_wl);
    cudaGetSymbolAddress((void**)&woh, g_woh);
    cudaGetSymbolAddress((void**)&wol, g_wol);
    cudaGetSymbolAddress((void**)&qhp, g_qh);
    cudaGetSymbolAddress((void**)&qlp, g_ql);
    cudaGetSymbolAddress((void**)&khp, g_kh);
    cudaGetSymbolAddress((void**)&klp, g_kl);
    cudaGetSymbolAddress((void**)&vhp, g_vh);
    cudaGetSymbolAddress((void**)&vlp, g_vl);
    cudaGetSymbolAddress((void**)&aoh, g_aoh);
    cudaGetSymbolAddress((void**)&aol, g_aol);

    cudaFuncSetAttribute(gemm_bf16s, cudaFuncAttributeMaxDynamicSharedMemorySize,
                         GEMM_SMEM);
    cudaFuncSetAttribute(attn_tc, cudaFuncAttributeMaxDynamicSharedMemorySize,
                         ATTN_SMEM);

    // ---- fused converts (2M float4) ----
    cvt_all<<<8192, 256>>>((const float4*)x, (const float4*)wq,
                           (const float4*)wk, (const float4*)wv,
                           (const float4*)wo,
                           (uint2*)xh, (uint2*)xl, (uint2*)wh, (uint2*)wl,
                           (uint2*)woh, (uint2*)wol);

    // ---- fused QKV projection: [4096,1024] x [3072,1024]^T ----
    gemm_bf16s<<<dim3(3072 / 128, Mrows / 256), 256, GEMM_SMEM>>>(
        xh, xl, wh, wl, qkv, 3072);

    // ---- norm + rope + split ----
    norm_rope_kernel<<<(Mrows * Hh) / 8, 256>>>(qkv, qw, kw,
                                                qhp, qlp, khp, klp, vhp, vlp);

    // ---- flash attention ----
    attn_tc<<<dim3(Ss / 128, Bb * Hh), 256, ATTN_SMEM>>>(
        qhp, qlp, khp, klp, vhp, vlp, sk, aoh, aol);

    // ---- output projection ----
    gemm_bf16s<<<dim3(Dd / 128, Mrows / 256), 256, GEMM_SMEM>>>(
        aoh, aol, woh, wol, out, Dd);
}

// round 6
// speedup vs baseline: 4.5357x; 1.3765x over previous
#include <cuda_runtime.h>
#include <cuda_fp16.h>
#include <stdint.h>
#include <math.h>

// Problem constants
#define Bb   2
#define Ss   2048
#define Dd   1024
#define Hh   16
#define HDd  64
#define Mrows (Bb*Ss)   // 4096

// ---------------- scratch (no allocs allowed) ----------------
__device__ float    g_qkv[Mrows * 3072];          // fused QKV output (fp32)
__device__ uint16_t g_xh [Mrows * Dd];            // x fp16 hi/lo
__device__ uint16_t g_xl [Mrows * Dd];
__device__ uint16_t g_wh [3072 * Dd];             // fused wq|wk|wv fp16
__device__ uint16_t g_woh[Dd * Dd];               // wo fp16
__device__ uint16_t g_qh [Mrows * Dd];            // [B,H,S,64] fp16 hi/lo
__device__ uint16_t g_ql [Mrows * Dd];
__device__ uint16_t g_kh [Mrows * Dd];            // fp16
__device__ uint16_t g_vh [Mrows * Dd];            // fp16
__device__ uint16_t g_aoh[Mrows * Dd];            // attn out fp16 hi/lo
__device__ uint16_t g_aol[Mrows * Dd];

// ================= PTX helpers ==========================
__device__ __forceinline__ uint32_t smem_u32(const void* p) {
    uint32_t a;
    asm("{ .reg .u64 t; cvta.to.shared.u64 t, %1; cvt.u32.u64 %0, t; }"
        : "=r"(a) : "l"(p));
    return a;
}
__device__ __forceinline__ void cp_async16(uint32_t s, const void* g) {
    asm volatile("cp.async.cg.shared.global [%0], [%1], 16;" :: "r"(s), "l"(g));
}
#define CP_COMMIT() asm volatile("cp.async.commit_group;" ::: "memory")
#define CP_WAIT(n)  asm volatile("cp.async.wait_group %0;" :: "n"(n) : "memory")

#define LDSM_X4(r, addr) \
    asm volatile("ldmatrix.sync.aligned.m8n8.x4.shared.b16 {%0,%1,%2,%3}, [%4];" \
        : "=r"((r)[0]), "=r"((r)[1]), "=r"((r)[2]), "=r"((r)[3]) : "r"(addr))
#define LDSM_X4_T(r, addr) \
    asm volatile("ldmatrix.sync.aligned.m8n8.x4.trans.shared.b16 {%0,%1,%2,%3}, [%4];" \
        : "=r"((r)[0]), "=r"((r)[1]), "=r"((r)[2]), "=r"((r)[3]) : "r"(addr))

#define MMA_F16(d, a, b0, b1) \
    asm volatile("mma.sync.aligned.m16n8k16.row.col.f32.f16.f16.f32 " \
        "{%0,%1,%2,%3}, {%4,%5,%6,%7}, {%8,%9}, {%0,%1,%2,%3};" \
        : "+f"((d)[0]), "+f"((d)[1]), "+f"((d)[2]), "+f"((d)[3]) \
        : "r"((a)[0]), "r"((a)[1]), "r"((a)[2]), "r"((a)[3]), \
          "r"(b0), "r"(b1))

// pack two floats to f16x2 (a -> low half, b -> high half)
__device__ __forceinline__ uint32_t pack_h2(float a, float b) {
    uint32_t r;
    asm("cvt.rn.f16x2.f32 %0, %1, %2;" : "=r"(r) : "f"(b), "f"(a));
    return r;
}
// split pair into fp16 hi + fp16 residual lo
__device__ __forceinline__ void split2_h(float x0, float x1,
                                         uint32_t& hi, uint32_t& lo) {
    hi = pack_h2(x0, x1);
    float2 f = __half22float2(*reinterpret_cast<__half2*>(&hi));
    lo = pack_h2(x0 - f.x, x1 - f.y);
}

// =================================================================
// fused convert: x -> fp16 hi/lo ; wq|wk|wv, wo -> plain fp16
// =================================================================
__global__ __launch_bounds__(256)
void cvt_all(const float4* __restrict__ x,  const float4* __restrict__ wq,
             const float4* __restrict__ wk, const float4* __restrict__ wv,
             const float4* __restrict__ wo,
             uint2* __restrict__ xh, uint2* __restrict__ xl,
             uint2* __restrict__ wh, uint2* __restrict__ woh) {
    int i = blockIdx.x * 256 + threadIdx.x;     // 0 .. 2M-1
    if (i < 1048576) {
        float4 v = x[i];
        uint2 h, l;
        split2_h(v.x, v.y, h.x, l.x);
        split2_h(v.z, v.w, h.y, l.y);
        xh[i] = h;
        xl[i] = l;
    } else {
        int i2 = i - 1048576;
        int reg = i2 >> 18;            // 0..3
        int off = i2 & 262143;
        const float4* src;
        uint2* dst;
        if (reg == 0)      { src = wq + off; dst = wh + off; }
        else if (reg == 1) { src = wk + off; dst = wh + 262144 + off; }
        else if (reg == 2) { src = wv + off; dst = wh + 524288 + off; }
        else               { src = wo + off; dst = woh + off; }
        float4 v = *src;
        uint2 o;
        o.x = pack_h2(v.x, v.y);
        o.y = pack_h2(v.z, v.w);
        *dst = o;
    }
}

// =================================================================
// fp16 2-term split HMMA GEMM NT:
//   C[M,N] = (Ah+Al)[M,K] * Bh[N,K]^T, fp32 accum (err ~1e-4)
// Tile 128x128x32, 256 thr, warps 4(M)x2(N), warp 32x64.
// 3-stage cp.async ring, 92KB smem -> 2 CTAs/SM.
// =================================================================
#define GK 1024
#define GPITCH 80                 // 32 f16 = 64B + 16B pad
#define G_AH 0                    // 128*80 = 10240
#define G_AL 10240
#define G_B  20480                // 10240
#define G_STG 30720
#define GEMM_SMEM (3 * G_STG)     // 92160

__device__ __forceinline__ void gemm_issue(
    uint32_t stg, const uint16_t* __restrict__ Ah,
    const uint16_t* __restrict__ Al, const uint16_t* __restrict__ B,
    int bm, int bn, int k0, int tid) {
#pragma unroll
    for (int u = 0; u < 2; ++u) {
        int q = tid + u * 256;          // 0..511
        int r = q >> 2, c = q & 3;
        uint32_t d = r * GPITCH + c * 16;
        size_t sa = (size_t)(bm + r) * GK + k0 + c * 8;
        size_t sb = (size_t)(bn + r) * GK + k0 + c * 8;
        cp_async16(stg + G_AH + d, Ah + sa);
        cp_async16(stg + G_AL + d, Al + sa);
        cp_async16(stg + G_B  + d, B  + sb);
    }
}

__global__ __launch_bounds__(256, 2)
void gemm_f16s(const uint16_t* __restrict__ Ah, const uint16_t* __restrict__ Al,
               const uint16_t* __restrict__ B, float* __restrict__ C, int N) {
    extern __shared__ char smem[];
    const uint32_t sb = smem_u32(smem);
    const int tid = threadIdx.x;
    const int wid = tid >> 5, lane = tid & 31;
    const int wm = wid & 3, wn = wid >> 2;
    const int gid = lane >> 2, tig = lane & 3;
    const int bm = blockIdx.y * 128, bn = blockIdx.x * 128;
    const int NS = GK / 32;   // 32 stages

    uint32_t aAddr[2], bAddr[4];
#pragma unroll
    for (int mf = 0; mf < 2; ++mf)
        aAddr[mf] = (wm * 32 + mf * 16 + (lane & 15)) * GPITCH
                    + (lane >> 4) * 16;
#pragma unroll
    for (int nb = 0; nb < 4; ++nb)
        bAddr[nb] = G_B + (wn * 64 + nb * 16 + ((lane >> 4) << 3) + (lane & 7))
                    * GPITCH + ((lane >> 3) & 1) * 16;

    float acc[2][8][4];
#pragma unroll
    for (int i = 0; i < 2; ++i)
#pragma unroll
        for (int j = 0; j < 8; ++j)
#pragma unroll
            for (int c = 0; c < 4; ++c) acc[i][j][c] = 0.f;

    gemm_issue(sb, Ah, Al, B, bm, bn, 0, tid);
    CP_COMMIT();
    gemm_issue(sb + G_STG, Ah, Al, B, bm, bn, 32, tid);
    CP_COMMIT();

    for (int s = 0; s < NS; ++s) {
        if (s < NS - 1) { CP_WAIT(1); } else { CP_WAIT(0); }
        __syncthreads();
        if (s + 2 < NS) {
            gemm_issue(sb + ((s + 2) % 3) * G_STG, Ah, Al, B,
                       bm, bn, (s + 2) * 32, tid);
            CP_COMMIT();
        }
        const uint32_t stg = sb + (s % 3) * G_STG;

#pragma unroll
        for (int ks = 0; ks < 2; ++ks) {
            uint32_t bh4[4][4];
#pragma unroll
            for (int nb = 0; nb < 4; ++nb)
                LDSM_X4(bh4[nb], stg + bAddr[nb] + ks * 32);
#pragma unroll
            for (int mf = 0; mf < 2; ++mf) {
                uint32_t ah[4], al[4];
                LDSM_X4(ah, stg + G_AH + aAddr[mf] + ks * 32);
                LDSM_X4(al, stg + G_AL + aAddr[mf] + ks * 32);
#pragma unroll
                for (int nb = 0; nb < 4; ++nb) {
                    MMA_F16(acc[mf][2*nb],   ah, bh4[nb][0], bh4[nb][1]);
                    MMA_F16(acc[mf][2*nb+1], ah, bh4[nb][2], bh4[nb][3]);
                    MMA_F16(acc[mf][2*nb],   al, bh4[nb][0], bh4[nb][1]);
                    MMA_F16(acc[mf][2*nb+1], al, bh4[nb][2], bh4[nb][3]);
                }
            }
        }
    }

    // epilogue
#pragma unroll
    for (int mf = 0; mf < 2; ++mf) {
        const int row = bm + wm * 32 + mf * 16 + gid;
#pragma unroll
        for (int nf = 0; nf < 8; ++nf) {
            const int col = bn + wn * 64 + nf * 8 + tig * 2;
            *(float2*)&C[(size_t)row * N + col] =
                make_float2(acc[mf][nf][0], acc[mf][nf][1]);
            *(float2*)&C[(size_t)(row + 8) * N + col] =
                make_float2(acc[mf][nf][2], acc[mf][nf][3]);
        }
    }
}

// =================================================================
// RMSNorm + RoPE + transpose; Q -> fp16 hi/lo, K/V -> plain fp16
// =================================================================
__device__ __forceinline__ void split_store_h(uint16_t* hi, uint16_t* lo,
                                              size_t idx, float x) {
    __half h = __float2half_rn(x);
    hi[idx] = *reinterpret_cast<uint16_t*>(&h);
    __half l = __float2half_rn(x - __half2float(h));
    lo[idx] = *reinterpret_cast<uint16_t*>(&l);
}
__device__ __forceinline__ void store_h(uint16_t* p, size_t idx, float x) {
    __half h = __float2half_rn(x);
    p[idx] = *reinterpret_cast<uint16_t*>(&h);
}

__global__ __launch_bounds__(256)
void norm_rope_kernel(const float* __restrict__ qkv,
                      const float* __restrict__ qw, const float* __restrict__ kw,
                      uint16_t* __restrict__ qh, uint16_t* __restrict__ ql,
                      uint16_t* __restrict__ kh, uint16_t* __restrict__ vh) {
    const int gw   = blockIdx.x * 8 + (threadIdx.x >> 5);
    const int lane = threadIdx.x & 31;
    const int h  = gw & (Hh - 1);
    const int bs = gw >> 4;
    const int s  = bs & (Ss - 1);
    const int b  = bs >> 11;

    const size_t src = (size_t)bs * 3072 + h * HDd;
    const size_t dst = (((size_t)(b * Hh + h)) * Ss + s) * HDd;

    const float inv = exp2f(-(float)lane * 0.4152410118609203f);
    float sn, cs;
    sincosf((float)s * inv, &sn, &cs);

    { // Q
        float x1 = qkv[src + lane], x2 = qkv[src + lane + 32];
        float ss2 = x1 * x1 + x2 * x2;
#pragma unroll
        for (int off = 16; off; off >>= 1)
            ss2 += __shfl_xor_sync(0xffffffffu, ss2, off);
        float r = rsqrtf(ss2 * (1.0f / 64.0f) + 1e-6f);
        float n1 = x1 * r * qw[lane];
        float n2 = x2 * r * qw[lane + 32];
        split_store_h(qh, ql, dst + lane,      n1 * cs - n2 * sn);
        split_store_h(qh, ql, dst + lane + 32, n2 * cs + n1 * sn);
    }
    { // K
        float x1 = qkv[src + 1024 + lane], x2 = qkv[src + 1024 + lane + 32];
        float ss2 = x1 * x1 + x2 * x2;
#pragma unroll
        for (int off = 16; off; off >>= 1)
            ss2 += __shfl_xor_sync(0xffffffffu, ss2, off);
        float r = rsqrtf(ss2 * (1.0f / 64.0f) + 1e-6f);
        float n1 = x1 * r * kw[lane];
        float n2 = x2 * r * kw[lane + 32];
        store_h(kh, dst + lane,      n1 * cs - n2 * sn);
        store_h(kh, dst + lane + 32, n2 * cs + n1 * sn);
    }
    { // V
        store_h(vh, dst + lane,      qkv[src + 2048 + lane]);
        store_h(vh, dst + lane + 32, qkv[src + 2048 + lane + 32]);
    }
}

// =================================================================
// fp16 flash attention, causal + sink. Q split hi/lo, K/V plain.
// Br=128, Bc=64, 8 warps x 16 q-rows. 3-stage ring, 2 CTAs/SM.
// =================================================================
#define APITCH 144
#define A_QH 0
#define A_QL 18432
#define A_QSZ 36864
#define A_K 0
#define A_V 9216
#define A_STG 18432
#define ATTN_SMEM (A_QSZ + 3 * A_STG)   // 92160

__device__ __forceinline__ void attn_kv_issue(
    uint32_t stg, const uint16_t* __restrict__ kh,
    const uint16_t* __restrict__ vh, size_t seqbase, int j, int tid) {
#pragma unroll
    for (int u = 0; u < 2; ++u) {
        int q = tid + u * 256;          // 0..511
        int r = q >> 3, c = q & 7;
        size_t src = seqbase + (size_t)(j * 64 + r) * 64 + c * 8;
        uint32_t d = r * APITCH + c * 16;
        cp_async16(stg + A_K + d, kh + src);
        cp_async16(stg + A_V + d, vh + src);
    }
}

__global__ __launch_bounds__(256, 2)
void attn_tc(const uint16_t* __restrict__ qh, const uint16_t* __restrict__ ql,
             const uint16_t* __restrict__ kh, const uint16_t* __restrict__ vh,
             const float* __restrict__ sinkl,
             uint16_t* __restrict__ aoh, uint16_t* __restrict__ aol) {
    extern __shared__ char smem[];
    const uint32_t sb = smem_u32(smem);
    const int tid = threadIdx.x;
    const int wid = tid >> 5, lane = tid & 31;
    const int gid = lane >> 2, tig = lane & 3;
    const int qb = gridDim.x - 1 - blockIdx.x;   // heavy tiles first
    const int bh = blockIdx.y;
    const int h  = bh & (Hh - 1);
    const int b  = bh >> 4;
    const size_t seqbase = (size_t)bh * Ss * HDd;
    const int q0 = qb * 128;
    const int jmax = 2 * qb + 1;

    // ---- prologue: Q tile + KV stages 0,1 ----
#pragma unroll
    for (int u = 0; u < 4; ++u) {
        int q = tid + u * 256;
        int r = q >> 3, c = q & 7;
        size_t src = seqbase + (size_t)(q0 + r) * 64 + c * 8;
        uint32_t d = r * APITCH + c * 16;
        cp_async16(sb + A_QH + d, qh + src);
        cp_async16(sb + A_QL + d, ql + src);
    }
    attn_kv_issue(sb + A_QSZ, kh, vh, seqbase, 0, tid);
    CP_COMMIT();
    attn_kv_issue(sb + A_QSZ + A_STG, kh, vh, seqbase, 1, tid);
    CP_COMMIT();

    const uint32_t qA = sb + A_QH + (wid * 16 + (lane & 15)) * APITCH
                        + (lane >> 4) * 16;
    uint32_t kB[4];
#pragma unroll
    for (int nb = 0; nb < 4; ++nb)
        kB[nb] = A_K + (nb * 16 + ((lane >> 4) << 3) + (lane & 7)) * APITCH
                 + ((lane >> 3) & 1) * 16;
    const uint32_t vBrel = A_V + (lane & 15) * APITCH + (lane >> 4) * 16;

    const float snk = sinkl[h];
    float m0 = snk, m1 = snk, l0 = 1.f, l1 = 1.f;
    float o[8][4];
#pragma unroll
    for (int i = 0; i < 8; ++i)
#pragma unroll
        for (int c = 0; c < 4; ++c) o[i][c] = 0.f;

    const int r0g = q0 + wid * 16 + gid;
    const int r1g = r0g + 8;

    for (int j = 0; j <= jmax; ++j) {
        if (j < jmax) { CP_WAIT(1); } else { CP_WAIT(0); }
        __syncthreads();
        if (j + 2 <= jmax) {
            attn_kv_issue(sb + A_QSZ + ((j + 2) % 3) * A_STG,
                          kh, vh, seqbase, j + 2, tid);
            CP_COMMIT();
        }
        const uint32_t stg = sb + A_QSZ + (j % 3) * A_STG;

        // ---- S = Q K^T (Q split, K plain) ----
        float s[8][4];
#pragma unroll
        for (int i = 0; i < 8; ++i)
#pragma unroll
            for (int c = 0; c < 4; ++c) s[i][c] = 0.f;

#pragma unroll
        for (int ks = 0; ks < 4; ++ks) {
            uint32_t qah[4], qal[4];
            LDSM_X4(qah, qA + ks * 32);
            LDSM_X4(qal, qA + (A_QL - A_QH) + ks * 32);
#pragma unroll
            for (int nb = 0; nb < 4; ++nb) {
                uint32_t kb4[4];
                LDSM_X4(kb4, stg + kB[nb] + ks * 32);
                MMA_F16(s[2*nb],   qah, kb4[0], kb4[1]);
                MMA_F16(s[2*nb+1], qah, kb4[2], kb4[3]);
                MMA_F16(s[2*nb],   qal, kb4[0], kb4[1]);
                MMA_F16(s[2*nb+1], qal, kb4[2], kb4[3]);
            }
        }

        // ---- scale + causal mask ----
        const bool msk = (j >= 2 * qb);
#pragma unroll
        for (int nf = 0; nf < 8; ++nf)
#pragma unroll
            for (int c = 0; c < 4; ++c) {
                float v = s[nf][c] * 0.125f;
                if (msk) {
                    int col = j * 64 + nf * 8 + tig * 2 + (c & 1);
                    int row = (c < 2) ? r0g : r1g;
                    if (col > row) v = -1e30f;
                }
                s[nf][c] = v;
            }

        // ---- online softmax ----
        float mx0 = -1e30f, mx1 = -1e30f;
#pragma unroll
        for (int nf = 0; nf < 8; ++nf) {
            mx0 = fmaxf(mx0, fmaxf(s[nf][0], s[nf][1]));
            mx1 = fmaxf(mx1, fmaxf(s[nf][2], s[nf][3]));
        }
        mx0 = fmaxf(mx0, __shfl_xor_sync(0xffffffffu, mx0, 1));
        mx0 = fmaxf(mx0, __shfl_xor_sync(0xffffffffu, mx0, 2));
        mx1 = fmaxf(mx1, __shfl_xor_sync(0xffffffffu, mx1, 1));
        mx1 = fmaxf(mx1, __shfl_xor_sync(0xffffffffu, mx1, 2));
        const float mn0 = fmaxf(m0, mx0), mn1 = fmaxf(m1, mx1);
        const float cr0 = __expf(m0 - mn0), cr1 = __expf(m1 - mn1);
        float rs0 = 0.f, rs1 = 0.f;
#pragma unroll
        for (int nf = 0; nf < 8; ++nf) {
            s[nf][0] = __expf(s[nf][0] - mn0);
            s[nf][1] = __expf(s[nf][1] - mn0);
            s[nf][2] = __expf(s[nf][2] - mn1);
            s[nf][3] = __expf(s[nf][3] - mn1);
            rs0 += s[nf][0] + s[nf][1];
            rs1 += s[nf][2] + s[nf][3];
        }
        rs0 += __shfl_xor_sync(0xffffffffu, rs0, 1);
        rs0 += __shfl_xor_sync(0xffffffffu, rs0, 2);
        rs1 += __shfl_xor_sync(0xffffffffu, rs1, 1);
        rs1 += __shfl_xor_sync(0xffffffffu, rs1, 2);
        l0 = l0 * cr0 + rs0; l1 = l1 * cr1 + rs1;
        m0 = mn0; m1 = mn1;
#pragma unroll
        for (int nf = 0; nf < 8; ++nf) {
            o[nf][0] *= cr0; o[nf][1] *= cr0;
            o[nf][2] *= cr1; o[nf][3] *= cr1;
        }

        // ---- O += P V (P split, V plain) ----
#pragma unroll
        for (int ks = 0; ks < 4; ++ks) {
            uint32_t pah[4], pal[4];
            {
                float a0 = s[2*ks][0],   a1 = s[2*ks][1];
                float a2 = s[2*ks][2],   a3 = s[2*ks][3];
                float b0 = s[2*ks+1][0], b1 = s[2*ks+1][1];
                float b2 = s[2*ks+1][2], b3 = s[2*ks+1][3];
                split2_h(a0, a1, pah[0], pal[0]);
                split2_h(a2, a3, pah[1], pal[1]);
                split2_h(b0, b1, pah[2], pal[2]);
                split2_h(b2, b3, pah[3], pal[3]);
            }
#pragma unroll
            for (int db = 0; db < 4; ++db) {
                uint32_t vb4[4];
                LDSM_X4_T(vb4, stg + vBrel + ks * 16 * APITCH + db * 32);
                MMA_F16(o[2*db],   pah, vb4[0], vb4[1]);
                MMA_F16(o[2*db+1], pah, vb4[2], vb4[3]);
                MMA_F16(o[2*db],   pal, vb4[0], vb4[1]);
                MMA_F16(o[2*db+1], pal, vb4[2], vb4[3]);
            }
        }
    }

    // ---- epilogue: normalize, fp16 hi/lo split, write [B,S,D] ----
    const float i0 = 1.f / l0, i1 = 1.f / l1;
#pragma unroll
    for (int nf = 0; nf < 8; ++nf) {
        const int col = h * HDd + nf * 8 + tig * 2;
        {
            float y0 = o[nf][0] * i0, y1 = o[nf][1] * i0;
            size_t idx = ((size_t)(b * Ss + r0g)) * Dd + col;
            uint32_t hi, lo;
            split2_h(y0, y1, hi, lo);
            *(uint32_t*)&aoh[idx] = hi;
            *(uint32_t*)&aol[idx] = lo;
        }
        {
            float y2 = o[nf][2] * i1, y3 = o[nf][3] * i1;
            size_t idx = ((size_t)(b * Ss + r1g)) * Dd + col;
            uint32_t hi, lo;
            split2_h(y2, y3, hi, lo);
            *(uint32_t*)&aoh[idx] = hi;
            *(uint32_t*)&aol[idx] = lo;
        }
    }
}

// =================================================================
extern "C" void kernel_launch(void* const* d_in, const int* in_sizes, int n_in,
                              void* d_out, int out_size) {
    const float* x  = (const float*)d_in[0];
    const float* wq = (const float*)d_in[1];
    const float* wk = (const float*)d_in[2];
    const float* wv = (const float*)d_in[3];
    const float* wo = (const float*)d_in[4];
    const float* qw = (const float*)d_in[5];
    const float* kw = (const float*)d_in[6];
    const float* sk = (const float*)d_in[7];
    float* out = (float*)d_out;

    float *qkv;
    uint16_t *xh, *xl, *wh, *woh;
    uint16_t *qhp, *qlp, *khp, *vhp, *aoh, *aol;
    cudaGetSymbolAddress((void**)&qkv, g_qkv);
    cudaGetSymbolAddress((void**)&xh,  g_xh);
    cudaGetSymbolAddress((void**)&xl,  g_xl);
    cudaGetSymbolAddress((void**)&wh,  g_wh);
    cudaGetSymbolAddress((void**)&woh, g_woh);
    cudaGetSymbolAddress((void**)&qhp, g_qh);
    cudaGetSymbolAddress((void**)&qlp, g_ql);
    cudaGetSymbolAddress((void**)&khp, g_kh);
    cudaGetSymbolAddress((void**)&vhp, g_vh);
    cudaGetSymbolAddress((void**)&aoh, g_aoh);
    cudaGetSymbolAddress((void**)&aol, g_aol);

    cudaFuncSetAttribute(gemm_f16s, cudaFuncAttributeMaxDynamicSharedMemorySize,
                         GEMM_SMEM);
    cudaFuncSetAttribute(attn_tc, cudaFuncAttributeMaxDynamicSharedMemorySize,
                         ATTN_SMEM);

    // ---- fused converts ----
    cvt_all<<<8192, 256>>>((const float4*)x, (const float4*)wq,
                           (const float4*)wk, (const float4*)wv,
                           (const float4*)wo,
                           (uint2*)xh, (uint2*)xl, (uint2*)wh, (uint2*)woh);

    // ---- fused QKV projection ----
    gemm_f16s<<<dim3(3072 / 128, Mrows / 128), 256, GEMM_SMEM>>>(
        xh, xl, wh, qkv, 3072);

    // ---- norm + rope ----
    norm_rope_kernel<<<(Mrows * Hh) / 8, 256>>>(qkv, qw, kw, qhp, qlp, khp, vhp);

    // ---- flash attention ----
    attn_tc<<<dim3(Ss / 128, Bb * Hh), 256, ATTN_SMEM>>>(
        qhp, qlp, khp, vhp, sk, aoh, aol);

    // ---- output projection ----
    gemm_f16s<<<dim3(Dd / 128, Mrows / 128), 256, GEMM_SMEM>>>(
        aoh, aol, woh, out, Dd);
}

// round 7
// speedup vs baseline: 4.7829x; 1.0545x over previous
#include <cuda_runtime.h>
#include <cuda_fp16.h>
#include <stdint.h>
#include <math.h>

// Problem constants
#define Bb   2
#define Ss   2048
#define Dd   1024
#define Hh   16
#define HDd  64
#define Mrows (Bb*Ss)   // 4096

#define SC2 0.18033688011112042f   // 0.125 * log2(e), folded into Q
#define LOG2E 1.4426950408889634f

// ---------------- scratch (no allocs allowed) ----------------
__device__ uint16_t g_xh [Mrows * Dd];            // x fp16 hi/lo
__device__ uint16_t g_xl [Mrows * Dd];
__device__ uint16_t g_wh [3072 * Dd];             // fused wq|wk|wv fp16
__device__ uint16_t g_woh[Dd * Dd];               // wo fp16
__device__ uint16_t g_qh [Mrows * Dd];            // [B,H,S,64] fp16 hi/lo (pre-scaled)
__device__ uint16_t g_ql [Mrows * Dd];
__device__ uint16_t g_kh [Mrows * Dd];            // fp16
__device__ uint16_t g_vh [Mrows * Dd];            // fp16 hi/lo (exact split)
__device__ uint16_t g_vl [Mrows * Dd];
__device__ uint16_t g_aoh[Mrows * Dd];            // attn out fp16 hi/lo
__device__ uint16_t g_aol[Mrows * Dd];
__device__ float    g_cosT[Ss * 32];              // rope tables
__device__ float    g_sinT[Ss * 32];

// ================= PTX helpers ==========================
__device__ __forceinline__ uint32_t smem_u32(const void* p) {
    uint32_t a;
    asm("{ .reg .u64 t; cvta.to.shared.u64 t, %1; cvt.u32.u64 %0, t; }"
        : "=r"(a) : "l"(p));
    return a;
}
__device__ __forceinline__ void cp_async16(uint32_t s, const void* g) {
    asm volatile("cp.async.cg.shared.global [%0], [%1], 16;" :: "r"(s), "l"(g));
}
#define CP_COMMIT() asm volatile("cp.async.commit_group;" ::: "memory")
#define CP_WAIT(n)  asm volatile("cp.async.wait_group %0;" :: "n"(n) : "memory")

#define LDSM_X4(r, addr) \
    asm volatile("ldmatrix.sync.aligned.m8n8.x4.shared.b16 {%0,%1,%2,%3}, [%4];" \
        : "=r"((r)[0]), "=r"((r)[1]), "=r"((r)[2]), "=r"((r)[3]) : "r"(addr))
#define LDSM_X4_T(r, addr) \
    asm volatile("ldmatrix.sync.aligned.m8n8.x4.trans.shared.b16 {%0,%1,%2,%3}, [%4];" \
        : "=r"((r)[0]), "=r"((r)[1]), "=r"((r)[2]), "=r"((r)[3]) : "r"(addr))

#define MMA_F16(d, a, b0, b1) \
    asm volatile("mma.sync.aligned.m16n8k16.row.col.f32.f16.f16.f32 " \
        "{%0,%1,%2,%3}, {%4,%5,%6,%7}, {%8,%9}, {%0,%1,%2,%3};" \
        : "+f"((d)[0]), "+f"((d)[1]), "+f"((d)[2]), "+f"((d)[3]) \
        : "r"((a)[0]), "r"((a)[1]), "r"((a)[2]), "r"((a)[3]), \
          "r"(b0), "r"(b1))

__device__ __forceinline__ uint32_t pack_h2(float a, float b) {
    uint32_t r;
    asm("cvt.rn.f16x2.f32 %0, %1, %2;" : "=r"(r) : "f"(b), "f"(a));
    return r;
}
__device__ __forceinline__ void split2_h(float x0, float x1,
                                         uint32_t& hi, uint32_t& lo) {
    hi = pack_h2(x0, x1);
    float2 f = __half22float2(*reinterpret_cast<__half2*>(&hi));
    lo = pack_h2(x0 - f.x, x1 - f.y);
}
__device__ __forceinline__ float ex2f(float x) {
    float y;
    asm("ex2.approx.f32 %0, %1;" : "=f"(y) : "f"(x));
    return y;
}

// =================================================================
// fused convert: x -> fp16 hi/lo ; w,wo -> fp16 ; rope tables
// =================================================================
__global__ __launch_bounds__(256)
void cvt_all(const float4* __restrict__ x,  const float4* __restrict__ wq,
             const float4* __restrict__ wk, const float4* __restrict__ wv,
             const float4* __restrict__ wo,
             uint2* __restrict__ xh, uint2* __restrict__ xl,
             uint2* __restrict__ wh, uint2* __restrict__ woh,
             float* __restrict__ cosT, float* __restrict__ sinT) {
    int i = blockIdx.x * 256 + threadIdx.x;     // 0 .. 2M-1
    if (i < 65536) {  // rope table: s = i>>5, j = i&31
        int s = i >> 5, j = i & 31;
        float inv = exp2f(-(float)j * 0.4152410118609203f);  // log2(1e4)/32
        float sn, cs;
        sincosf((float)s * inv, &sn, &cs);
        cosT[i] = cs;
        sinT[i] = sn;
    }
    if (i < 1048576) {
        float4 v = x[i];
        uint2 h, l;
        split2_h(v.x, v.y, h.x, l.x);
        split2_h(v.z, v.w, h.y, l.y);
        xh[i] = h;
        xl[i] = l;
    } else {
        int i2 = i - 1048576;
        int reg = i2 >> 18;            // 0..3
        int off = i2 & 262143;
        const float4* src;
        uint2* dst;
        if (reg == 0)      { src = wq + off; dst = wh + off; }
        else if (reg == 1) { src = wk + off; dst = wh + 262144 + off; }
        else if (reg == 2) { src = wv + off; dst = wh + 524288 + off; }
        else               { src = wo + off; dst = woh + off; }
        float4 v = *src;
        uint2 o;
        o.x = pack_h2(v.x, v.y);
        o.y = pack_h2(v.z, v.w);
        *dst = o;
    }
}

// =================================================================
// GEMM common: fp16 2-term split mainloop (A=Ah+Al, B plain).
// Tile 128x128x32, 256 thr, warps 4(M)x2(N), warp 32x64, 3-stage ring.
// =================================================================
#define GK 1024
#define GPITCH 80
#define G_AH 0
#define G_AL 10240
#define G_B  20480
#define G_STG 30720
#define GEMM_SMEM (3 * G_STG)     // 92160

__device__ __forceinline__ void gemm_issue(
    uint32_t stg, const uint16_t* __restrict__ Ah,
    const uint16_t* __restrict__ Al, const uint16_t* __restrict__ B,
    int bm, int bn, int k0, int tid) {
#pragma unroll
    for (int u = 0; u < 2; ++u) {
        int q = tid + u * 256;
        int r = q >> 2, c = q & 3;
        uint32_t d = r * GPITCH + c * 16;
        size_t sa = (size_t)(bm + r) * GK + k0 + c * 8;
        size_t sb = (size_t)(bn + r) * GK + k0 + c * 8;
        cp_async16(stg + G_AH + d, Ah + sa);
        cp_async16(stg + G_AL + d, Al + sa);
        cp_async16(stg + G_B  + d, B  + sb);
    }
}

// mainloop macro-ish: computes acc[2][8][4] for warp tile 32x64
#define GEMM_MAINLOOP(Ah, Al, B, bm, bn)                                     \
    gemm_issue(sb, Ah, Al, B, bm, bn, 0, tid);                               \
    CP_COMMIT();                                                             \
    gemm_issue(sb + G_STG, Ah, Al, B, bm, bn, 32, tid);                      \
    CP_COMMIT();                                                             \
    for (int s = 0; s < 32; ++s) {                                           \
        if (s < 31) { CP_WAIT(1); } else { CP_WAIT(0); }                     \
        __syncthreads();                                                     \
        if (s + 2 < 32) {                                                    \
            gemm_issue(sb + ((s + 2) % 3) * G_STG, Ah, Al, B,                \
                       bm, bn, (s + 2) * 32, tid);                           \
            CP_COMMIT();                                                     \
        }                                                                    \
        const uint32_t stg = sb + (s % 3) * G_STG;                           \
        _Pragma("unroll")                                                    \
        for (int ks = 0; ks < 2; ++ks) {                                     \
            uint32_t bh4[4][4];                                              \
            _Pragma("unroll")                                                \
            for (int nb = 0; nb < 4; ++nb)                                   \
                LDSM_X4(bh4[nb], stg + bAddr[nb] + ks * 32);                 \
            _Pragma("unroll")                                                \
            for (int mf = 0; mf < 2; ++mf) {                                 \
                uint32_t ah[4], al[4];                                       \
                LDSM_X4(ah, stg + G_AH + aAddr[mf] + ks * 32);               \
                LDSM_X4(al, stg + G_AL + aAddr[mf] + ks * 32);               \
                _Pragma("unroll")                                            \
                for (int nb = 0; nb < 4; ++nb) {                             \
                    MMA_F16(acc[mf][2*nb],   ah, bh4[nb][0], bh4[nb][1]);    \
                    MMA_F16(acc[mf][2*nb+1], ah, bh4[nb][2], bh4[nb][3]);    \
                    MMA_F16(acc[mf][2*nb],   al, bh4[nb][0], bh4[nb][1]);    \
                    MMA_F16(acc[mf][2*nb+1], al, bh4[nb][2], bh4[nb][3]);    \
                }                                                            \
            }                                                                \
        }                                                                    \
    }

#define GEMM_PREAMBLE                                                        \
    extern __shared__ char smem[];                                           \
    const uint32_t sb = smem_u32(smem);                                      \
    const int tid = threadIdx.x;                                             \
    const int wid = tid >> 5, lane = tid & 31;                               \
    const int wm = wid & 3, wn = wid >> 2;                                   \
    const int gid = lane >> 2, tig = lane & 3;                               \
    const int bm = blockIdx.y * 128, bn = blockIdx.x * 128;                  \
    uint32_t aAddr[2], bAddr[4];                                             \
    _Pragma("unroll")                                                        \
    for (int mf = 0; mf < 2; ++mf)                                           \
        aAddr[mf] = (wm * 32 + mf * 16 + (lane & 15)) * GPITCH               \
                    + (lane >> 4) * 16;                                      \
    _Pragma("unroll")                                                        \
    for (int nb = 0; nb < 4; ++nb)                                           \
        bAddr[nb] = G_B + (wn * 64 + nb * 16 + ((lane >> 4) << 3)            \
                    + (lane & 7)) * GPITCH + ((lane >> 3) & 1) * 16;         \
    float acc[2][8][4];                                                      \
    _Pragma("unroll")                                                        \
    for (int i = 0; i < 2; ++i)                                              \
        _Pragma("unroll")                                                    \
        for (int j = 0; j < 8; ++j)                                          \
            _Pragma("unroll")                                                \
            for (int c = 0; c < 4; ++c) acc[i][j][c] = 0.f;

// =================================================================
// QKV GEMM with fused RMSNorm+RoPE+split epilogue.
// N-block [0,1024)=Q, [1024,2048)=K, [2048,3072)=V; warp col span
// (64) == one head. Writes qh/ql (pre-scaled by SC2), kh, vh/vl
// in [B,H,S,64] layout.
// =================================================================
__global__ __launch_bounds__(256, 2)
void gemm_qkv(const uint16_t* __restrict__ Ah, const uint16_t* __restrict__ Al,
              const uint16_t* __restrict__ B,
              const float* __restrict__ qw, const float* __restrict__ kw,
              const float* __restrict__ cosT, const float* __restrict__ sinT,
              uint16_t* __restrict__ qh, uint16_t* __restrict__ ql,
              uint16_t* __restrict__ kh,
              uint16_t* __restrict__ vh, uint16_t* __restrict__ vl) {
    GEMM_PREAMBLE
    GEMM_MAINLOOP(Ah, Al, B, bm, bn)

    const int cb = bn + wn * 64;
    const int sect = cb >> 10;          // 0=Q, 1=K, 2=V
    const int hh = (cb >> 6) & 15;

#pragma unroll
    for (int mf = 0; mf < 2; ++mf) {
#pragma unroll
        for (int hf = 0; hf < 2; ++hf) {
            const int row = bm + wm * 32 + mf * 16 + gid + hf * 8;
            const int s = row & (Ss - 1);
            const int b = row >> 11;
            const size_t dst = (((size_t)(b * Hh + hh)) * Ss + s) * HDd;
            float v[8][2];
#pragma unroll
            for (int nf = 0; nf < 8; ++nf) {
                v[nf][0] = acc[mf][nf][hf * 2];
                v[nf][1] = acc[mf][nf][hf * 2 + 1];
            }
            if (sect == 2) {   // V: exact fp16 split, no norm/rope
#pragma unroll
                for (int nf = 0; nf < 8; ++nf) {
                    int d0 = nf * 8 + tig * 2;
                    uint32_t hi, lo;
                    split2_h(v[nf][0], v[nf][1], hi, lo);
                    *(uint32_t*)&vh[dst + d0] = hi;
                    *(uint32_t*)&vl[dst + d0] = lo;
                }
            } else {           // Q or K: rms + rope
                float ss = 0.f;
#pragma unroll
                for (int nf = 0; nf < 8; ++nf)
                    ss += v[nf][0] * v[nf][0] + v[nf][1] * v[nf][1];
                ss += __shfl_xor_sync(0xffffffffu, ss, 1);
                ss += __shfl_xor_sync(0xffffffffu, ss, 2);
                const float r = rsqrtf(ss * (1.0f / 64.0f) + 1e-6f);
                const float* w = sect ? kw : qw;
#pragma unroll
                for (int nf = 0; nf < 4; ++nf) {
                    int d0 = nf * 8 + tig * 2;
                    float2 w1 = *(const float2*)&w[d0];
                    float2 w2 = *(const float2*)&w[d0 + 32];
                    float2 cs = *(const float2*)&cosT[s * 32 + d0];
                    float2 sn = *(const float2*)&sinT[s * 32 + d0];
                    float x1a = v[nf][0]     * r * w1.x;
                    float x1b = v[nf][1]     * r * w1.y;
                    float x2a = v[nf + 4][0] * r * w2.x;
                    float x2b = v[nf + 4][1] * r * w2.y;
                    float o1a = x1a * cs.x - x2a * sn.x;
                    float o1b = x1b * cs.y - x2b * sn.y;
                    float o2a = x2a * cs.x + x1a * sn.x;
                    float o2b = x2b * cs.y + x1b * sn.y;
                    if (sect == 0) {   // Q: scale + split
                        o1a *= SC2; o1b *= SC2; o2a *= SC2; o2b *= SC2;
                        uint32_t hi, lo;
                        split2_h(o1a, o1b, hi, lo);
                        *(uint32_t*)&qh[dst + d0] = hi;
                        *(uint32_t*)&ql[dst + d0] = lo;
                        split2_h(o2a, o2b, hi, lo);
                        *(uint32_t*)&qh[dst + d0 + 32] = hi;
                        *(uint32_t*)&ql[dst + d0 + 32] = lo;
                    } else {           // K: plain fp16
                        *(uint32_t*)&kh[dst + d0]      = pack_h2(o1a, o1b);
                        *(uint32_t*)&kh[dst + d0 + 32] = pack_h2(o2a, o2b);
                    }
                }
            }
        }
    }
}

// =================================================================
// Output-projection GEMM (fp32 C epilogue)
// =================================================================
__global__ __launch_bounds__(256, 2)
void gemm_out(const uint16_t* __restrict__ Ah, const uint16_t* __restrict__ Al,
              const uint16_t* __restrict__ B, float* __restrict__ C) {
    GEMM_PREAMBLE
    GEMM_MAINLOOP(Ah, Al, B, bm, bn)
#pragma unroll
    for (int mf = 0; mf < 2; ++mf) {
        const int row = bm + wm * 32 + mf * 16 + gid;
#pragma unroll
        for (int nf = 0; nf < 8; ++nf) {
            const int col = bn + wn * 64 + nf * 8 + tig * 2;
            *(float2*)&C[(size_t)row * Dd + col] =
                make_float2(acc[mf][nf][0], acc[mf][nf][1]);
            *(float2*)&C[(size_t)(row + 8) * Dd + col] =
                make_float2(acc[mf][nf][2], acc[mf][nf][3]);
        }
    }
}

// =================================================================
// fp16 flash attention: Q pre-scaled split, K plain, V split.
// exp2-domain softmax; l via ones-column tensor MMA.
// Br=128, Bc=64, 2-stage KV ring, 2 CTAs/SM.
// =================================================================
#define APITCH 144
#define A_QH 0
#define A_QL 18432
#define A_QSZ 36864
#define A_K  0
#define A_VH 9216
#define A_VL 18432
#define A_STG 27648
#define ATTN_SMEM (A_QSZ + 2 * A_STG)   // 92160
#define ONES_H2 0x3C003C00u

__device__ __forceinline__ void attn_kv_issue(
    uint32_t stg, const uint16_t* __restrict__ kh,
    const uint16_t* __restrict__ vh, const uint16_t* __restrict__ vl,
    size_t seqbase, int j, int tid) {
#pragma unroll
    for (int u = 0; u < 2; ++u) {
        int q = tid + u * 256;          // 0..511
        int r = q >> 3, c = q & 7;
        size_t src = seqbase + (size_t)(j * 64 + r) * 64 + c * 8;
        uint32_t d = r * APITCH + c * 16;
        cp_async16(stg + A_K  + d, kh + src);
        cp_async16(stg + A_VH + d, vh + src);
        cp_async16(stg + A_VL + d, vl + src);
    }
}

__global__ __launch_bounds__(256, 2)
void attn_tc(const uint16_t* __restrict__ qh, const uint16_t* __restrict__ ql,
             const uint16_t* __restrict__ kh,
             const uint16_t* __restrict__ vh, const uint16_t* __restrict__ vl,
             const float* __restrict__ sinkl,
             uint16_t* __restrict__ aoh, uint16_t* __restrict__ aol) {
    extern __shared__ char smem[];
    const uint32_t sb = smem_u32(smem);
    const int tid = threadIdx.x;
    const int wid = tid >> 5, lane = tid & 31;
    const int gid = lane >> 2, tig = lane & 3;
    const int qb = gridDim.x - 1 - blockIdx.x;   // heavy tiles first
    const int bh = blockIdx.y;
    const int h  = bh & (Hh - 1);
    const int b  = bh >> 4;
    const size_t seqbase = (size_t)bh * Ss * HDd;
    const int q0 = qb * 128;
    const int jmax = 2 * qb + 1;

    // ---- prologue: Q tile + KV stage 0 (one commit group) ----
#pragma unroll
    for (int u = 0; u < 4; ++u) {
        int q = tid + u * 256;
        int r = q >> 3, c = q & 7;
        size_t src = seqbase + (size_t)(q0 + r) * 64 + c * 8;
        uint32_t d = r * APITCH + c * 16;
        cp_async16(sb + A_QH + d, qh + src);
        cp_async16(sb + A_QL + d, ql + src);
    }
    attn_kv_issue(sb + A_QSZ, kh, vh, vl, seqbase, 0, tid);
    CP_COMMIT();

    const uint32_t qA = sb + A_QH + (wid * 16 + (lane & 15)) * APITCH
                        + (lane >> 4) * 16;
    uint32_t kB[4];
#pragma unroll
    for (int nb = 0; nb < 4; ++nb)
        kB[nb] = A_K + (nb * 16 + ((lane >> 4) << 3) + (lane & 7)) * APITCH
                 + ((lane >> 3) & 1) * 16;
    const uint32_t vBrel = (lane & 15) * APITCH + (lane >> 4) * 16;

    const float snk2 = sinkl[h] * LOG2E;
    float m0 = snk2, m1 = snk2;
    float o[8][4], ol[4];
#pragma unroll
    for (int i = 0; i < 8; ++i)
#pragma unroll
        for (int c = 0; c < 4; ++c) o[i][c] = 0.f;
#pragma unroll
    for (int c = 0; c < 4; ++c) ol[c] = 0.f;

    const int r0g = q0 + wid * 16 + gid;
    const int r1g = r0g + 8;

    for (int j = 0; j <= jmax; ++j) {
        CP_WAIT(0);
        __syncthreads();
        if (j < jmax) {
            attn_kv_issue(sb + A_QSZ + ((j + 1) & 1) * A_STG,
                          kh, vh, vl, seqbase, j + 1, tid);
            CP_COMMIT();
        }
        const uint32_t stg = sb + A_QSZ + (j & 1) * A_STG;

        // ---- S = Q K^T (Q split pre-scaled, K plain) ----
        float s[8][4];
#pragma unroll
        for (int i = 0; i < 8; ++i)
#pragma unroll
            for (int c = 0; c < 4; ++c) s[i][c] = 0.f;

#pragma unroll
        for (int ks = 0; ks < 4; ++ks) {
            uint32_t qah[4], qal[4];
            LDSM_X4(qah, qA + ks * 32);
            LDSM_X4(qal, qA + (A_QL - A_QH) + ks * 32);
#pragma unroll
            for (int nb = 0; nb < 4; ++nb) {
                uint32_t kb4[4];
                LDSM_X4(kb4, stg + kB[nb] + ks * 32);
                MMA_F16(s[2*nb],   qah, kb4[0], kb4[1]);
                MMA_F16(s[2*nb+1], qah, kb4[2], kb4[3]);
                MMA_F16(s[2*nb],   qal, kb4[0], kb4[1]);
                MMA_F16(s[2*nb+1], qal, kb4[2], kb4[3]);
            }
        }

        // ---- causal mask (diagonal blocks only; scale pre-folded) ----
        if (j >= 2 * qb) {
#pragma unroll
            for (int nf = 0; nf < 8; ++nf)
#pragma unroll
                for (int c = 0; c < 4; ++c) {
                    int col = j * 64 + nf * 8 + tig * 2 + (c & 1);
                    int row = (c < 2) ? r0g : r1g;
                    if (col > row) s[nf][c] = -1e30f;
                }
        }

        // ---- online softmax (base-2) ----
        float mx0 = -1e30f, mx1 = -1e30f;
#pragma unroll
        for (int nf = 0; nf < 8; ++nf) {
            mx0 = fmaxf(mx0, fmaxf(s[nf][0], s[nf][1]));
            mx1 = fmaxf(mx1, fmaxf(s[nf][2], s[nf][3]));
        }
        mx0 = fmaxf(mx0, __shfl_xor_sync(0xffffffffu, mx0, 1));
        mx0 = fmaxf(mx0, __shfl_xor_sync(0xffffffffu, mx0, 2));
        mx1 = fmaxf(mx1, __shfl_xor_sync(0xffffffffu, mx1, 1));
        mx1 = fmaxf(mx1, __shfl_xor_sync(0xffffffffu, mx1, 2));
        const float mn0 = fmaxf(m0, mx0), mn1 = fmaxf(m1, mx1);
        const float cr0 = ex2f(m0 - mn0), cr1 = ex2f(m1 - mn1);
        m0 = mn0; m1 = mn1;
#pragma unroll
        for (int nf = 0; nf < 8; ++nf) {
            o[nf][0] *= cr0; o[nf][1] *= cr0;
            o[nf][2] *= cr1; o[nf][3] *= cr1;
        }
        ol[0] *= cr0; ol[1] *= cr0; ol[2] *= cr1; ol[3] *= cr1;

        // P = 2^(s-m), packed straight into fp16 fragments
        uint32_t pp[8][2];
#pragma unroll
        for (int nf = 0; nf < 8; ++nf) {
            float e0 = ex2f(s[nf][0] - mn0);
            float e1 = ex2f(s[nf][1] - mn0);
            float e2 = ex2f(s[nf][2] - mn1);
            float e3 = ex2f(s[nf][3] - mn1);
            pp[nf][0] = pack_h2(e0, e1);
            pp[nf][1] = pack_h2(e2, e3);
        }

        // ---- O += P (Vh + Vl);  l += P * ones (tensor-core row sum) ----
#pragma unroll
        for (int ks = 0; ks < 4; ++ks) {
            uint32_t pa[4] = { pp[2*ks][0], pp[2*ks][1],
                               pp[2*ks+1][0], pp[2*ks+1][1] };
            MMA_F16(ol, pa, ONES_H2, ONES_H2);
#pragma unroll
            for (int db = 0; db < 4; ++db) {
                uint32_t vbh[4], vbl[4];
                LDSM_X4_T(vbh, stg + A_VH + vBrel + ks * 16 * APITCH + db * 32);
                LDSM_X4_T(vbl, stg + A_VL + vBrel + ks * 16 * APITCH + db * 32);
                MMA_F16(o[2*db],   pa, vbh[0], vbh[1]);
                MMA_F16(o[2*db+1], pa, vbh[2], vbh[3]);
                MMA_F16(o[2*db],   pa, vbl[0], vbl[1]);
                MMA_F16(o[2*db+1], pa, vbl[2], vbl[3]);
            }
        }
    }

    // ---- epilogue: add sink to l, normalize, split, store ----
    const float l0 = ol[0] + ex2f(snk2 - m0);
    const float l1 = ol[2] + ex2f(snk2 - m1);
    const float i0 = 1.f / l0, i1 = 1.f / l1;
#pragma unroll
    for (int nf = 0; nf < 8; ++nf) {
        const int col = h * HDd + nf * 8 + tig * 2;
        {
            float y0 = o[nf][0] * i0, y1 = o[nf][1] * i0;
            size_t idx = ((size_t)(b * Ss + r0g)) * Dd + col;
            uint32_t hi, lo;
            split2_h(y0, y1, hi, lo);
            *(uint32_t*)&aoh[idx] = hi;
            *(uint32_t*)&aol[idx] = lo;
        }
        {
            float y2 = o[nf][2] * i1, y3 = o[nf][3] * i1;
            size_t idx = ((size_t)(b * Ss + r1g)) * Dd + col;
            uint32_t hi, lo;
            split2_h(y2, y3, hi, lo);
            *(uint32_t*)&aoh[idx] = hi;
            *(uint32_t*)&aol[idx] = lo;
        }
    }
}

// =================================================================
extern "C" void kernel_launch(void* const* d_in, const int* in_sizes, int n_in,
                              void* d_out, int out_size) {
    const float* x  = (const float*)d_in[0];
    const float* wq = (const float*)d_in[1];
    const float* wk = (const float*)d_in[2];
    const float* wv = (const float*)d_in[3];
    const float* wo = (const float*)d_in[4];
    const float* qw = (const float*)d_in[5];
    const float* kw = (const float*)d_in[6];
    const float* sk = (const float*)d_in[7];
    float* out = (float*)d_out;

    uint16_t *xh, *xl, *wh, *woh;
    uint16_t *qhp, *qlp, *khp, *vhp, *vlp, *aoh, *aol;
    float *cosT, *sinT;
    cudaGetSymbolAddress((void**)&xh,  g_xh);
    cudaGetSymbolAddress((void**)&xl,  g_xl);
    cudaGetSymbolAddress((void**)&wh,  g_wh);
    cudaGetSymbolAddress((void**)&woh, g_woh);
    cudaGetSymbolAddress((void**)&qhp, g_qh);
    cudaGetSymbolAddress((void**)&qlp, g_ql);
    cudaGetSymbolAddress((void**)&khp, g_kh);
    cudaGetSymbolAddress((void**)&vhp, g_vh);
    cudaGetSymbolAddress((void**)&vlp, g_vl);
    cudaGetSymbolAddress((void**)&aoh, g_aoh);
    cudaGetSymbolAddress((void**)&aol, g_aol);
    cudaGetSymbolAddress((void**)&cosT, g_cosT);
    cudaGetSymbolAddress((void**)&sinT, g_sinT);

    cudaFuncSetAttribute(gemm_qkv, cudaFuncAttributeMaxDynamicSharedMemorySize,
                         GEMM_SMEM);
    cudaFuncSetAttribute(gemm_out, cudaFuncAttributeMaxDynamicSharedMemorySize,
                         GEMM_SMEM);
    cudaFuncSetAttribute(attn_tc, cudaFuncAttributeMaxDynamicSharedMemorySize,
                         ATTN_SMEM);

    // converts + rope tables
    cvt_all<<<8192, 256>>>((const float4*)x, (const float4*)wq,
                           (const float4*)wk, (const float4*)wv,
                           (const float4*)wo,
                           (uint2*)xh, (uint2*)xl, (uint2*)wh, (uint2*)woh,
                           cosT, sinT);

    // QKV projection + fused norm/rope/split
    gemm_qkv<<<dim3(3072 / 128, Mrows / 128), 256, GEMM_SMEM>>>(
        xh, xl, wh, qw, kw, cosT, sinT, qhp, qlp, khp, vhp, vlp);

    // flash attention
    attn_tc<<<dim3(Ss / 128, Bb * Hh), 256, ATTN_SMEM>>>(
        qhp, qlp, khp, vhp, vlp, sk, aoh, aol);

    // output projection
    gemm_out<<<dim3(Dd / 128, Mrows / 128), 256, GEMM_SMEM>>>(
        aoh, aol, woh, out);
}

// round 8
// speedup vs baseline: 6.4550x; 1.3496x over previous
#include <cuda_runtime.h>
#include <cuda_fp16.h>
#include <stdint.h>
#include <math.h>

// Problem constants
#define Bb   2
#define Ss   2048
#define Dd   1024
#define Hh   16
#define HDd  64
#define Mrows (Bb*Ss)   // 4096

#define SC2 0.18033688011112042f   // 0.125 * log2(e), folded into Q
#define LOG2E 1.4426950408889634f

// ---------------- scratch (no allocs allowed) ----------------
__device__ uint16_t g_xh [Mrows * Dd];            // x fp16 (plain)
__device__ uint16_t g_wh [3072 * Dd];             // fused wq|wk|wv fp16
__device__ uint16_t g_woh[Dd * Dd];               // wo fp16
__device__ uint16_t g_qh [Mrows * Dd];            // [B,H,S,64] fp16 hi/lo (pre-scaled)
__device__ uint16_t g_ql [Mrows * Dd];
__device__ uint16_t g_kh [Mrows * Dd];            // fp16
__device__ uint16_t g_vh [Mrows * Dd];            // fp16 (plain)
__device__ uint16_t g_aoh[Mrows * Dd];            // attn out fp16 hi/lo
__device__ uint16_t g_aol[Mrows * Dd];
__device__ float    g_cosT[Ss * 32];              // rope tables
__device__ float    g_sinT[Ss * 32];

// ================= PTX helpers ==========================
__device__ __forceinline__ uint32_t smem_u32(const void* p) {
    uint32_t a;
    asm("{ .reg .u64 t; cvta.to.shared.u64 t, %1; cvt.u32.u64 %0, t; }"
        : "=r"(a) : "l"(p));
    return a;
}
__device__ __forceinline__ void cp_async16(uint32_t s, const void* g) {
    asm volatile("cp.async.cg.shared.global [%0], [%1], 16;" :: "r"(s), "l"(g));
}
#define CP_COMMIT() asm volatile("cp.async.commit_group;" ::: "memory")
#define CP_WAIT(n)  asm volatile("cp.async.wait_group %0;" :: "n"(n) : "memory")

#define LDSM_X4(r, addr) \
    asm volatile("ldmatrix.sync.aligned.m8n8.x4.shared.b16 {%0,%1,%2,%3}, [%4];" \
        : "=r"((r)[0]), "=r"((r)[1]), "=r"((r)[2]), "=r"((r)[3]) : "r"(addr))
#define LDSM_X4_T(r, addr) \
    asm volatile("ldmatrix.sync.aligned.m8n8.x4.trans.shared.b16 {%0,%1,%2,%3}, [%4];" \
        : "=r"((r)[0]), "=r"((r)[1]), "=r"((r)[2]), "=r"((r)[3]) : "r"(addr))

#define MMA_F16(d, a, b0, b1) \
    asm volatile("mma.sync.aligned.m16n8k16.row.col.f32.f16.f16.f32 " \
        "{%0,%1,%2,%3}, {%4,%5,%6,%7}, {%8,%9}, {%0,%1,%2,%3};" \
        : "+f"((d)[0]), "+f"((d)[1]), "+f"((d)[2]), "+f"((d)[3]) \
        : "r"((a)[0]), "r"((a)[1]), "r"((a)[2]), "r"((a)[3]), \
          "r"(b0), "r"(b1))

__device__ __forceinline__ uint32_t pack_h2(float a, float b) {
    uint32_t r;
    asm("cvt.rn.f16x2.f32 %0, %1, %2;" : "=r"(r) : "f"(b), "f"(a));
    return r;
}
__device__ __forceinline__ void split2_h(float x0, float x1,
                                         uint32_t& hi, uint32_t& lo) {
    hi = pack_h2(x0, x1);
    float2 f = __half22float2(*reinterpret_cast<__half2*>(&hi));
    lo = pack_h2(x0 - f.x, x1 - f.y);
}
__device__ __forceinline__ float ex2f(float x) {
    float y;
    asm("ex2.approx.f32 %0, %1;" : "=f"(y) : "f"(x));
    return y;
}

// =================================================================
// fused convert: x, w, wo -> plain fp16 ; rope tables
// =================================================================
__global__ __launch_bounds__(256)
void cvt_all(const float4* __restrict__ x,  const float4* __restrict__ wq,
             const float4* __restrict__ wk, const float4* __restrict__ wv,
             const float4* __restrict__ wo,
             uint2* __restrict__ xh, uint2* __restrict__ wh,
             uint2* __restrict__ woh,
             float* __restrict__ cosT, float* __restrict__ sinT) {
    int i = blockIdx.x * 256 + threadIdx.x;     // 0 .. 2M-1
    if (i < 65536) {  // rope table
        int s = i >> 5, j = i & 31;
        float inv = exp2f(-(float)j * 0.4152410118609203f);  // log2(1e4)/32
        float sn, cs;
        sincosf((float)s * inv, &sn, &cs);
        cosT[i] = cs;
        sinT[i] = sn;
    }
    const float4* src;
    uint2* dst;
    if (i < 1048576) {
        src = x + i; dst = xh + i;
    } else {
        int i2 = i - 1048576;
        int reg = i2 >> 18;            // 0..3
        int off = i2 & 262143;
        if (reg == 0)      { src = wq + off; dst = wh + off; }
        else if (reg == 1) { src = wk + off; dst = wh + 262144 + off; }
        else if (reg == 2) { src = wv + off; dst = wh + 524288 + off; }
        else               { src = wo + off; dst = woh + off; }
    }
    float4 v = *src;
    uint2 o;
    o.x = pack_h2(v.x, v.y);
    o.y = pack_h2(v.z, v.w);
    *dst = o;
}

// =================================================================
// GEMM framework. Tile 128x128x32, 256 thr, warps 4(M)x2(N),
// warp 32x64, 3-stage cp.async ring.
// Variant 1: A plain.  Variant 2: A = Ah + Al (2-term split).
// =================================================================
#define GK 1024
#define GPITCH 80
// plain-A layout
#define P_A  0
#define P_B  10240
#define P_STG 20480
#define GEMM1_SMEM (3 * P_STG)    // 61440
// split-A layout
#define S_AH 0
#define S_AL 10240
#define S_B  20480
#define S_STG 30720
#define GEMM2_SMEM (3 * S_STG)    // 92160

#define GEMM_PREAMBLE                                                        \
    extern __shared__ char smem[];                                           \
    const uint32_t sb = smem_u32(smem);                                      \
    const int tid = threadIdx.x;                                             \
    const int wid = tid >> 5, lane = tid & 31;                               \
    const int wm = wid & 3, wn = wid >> 2;                                   \
    const int gid = lane >> 2, tig = lane & 3;                               \
    const int bm = blockIdx.y * 128, bn = blockIdx.x * 128;                  \
    uint32_t aAddr[2], bAddr[4];                                             \
    _Pragma("unroll")                                                        \
    for (int mf = 0; mf < 2; ++mf)                                           \
        aAddr[mf] = (wm * 32 + mf * 16 + (lane & 15)) * GPITCH               \
                    + (lane >> 4) * 16;                                      \
    _Pragma("unroll")                                                        \
    for (int nb = 0; nb < 4; ++nb)                                           \
        bAddr[nb] = (wn * 64 + nb * 16 + ((lane >> 4) << 3)                  \
                    + (lane & 7)) * GPITCH + ((lane >> 3) & 1) * 16;         \
    float acc[2][8][4];                                                      \
    _Pragma("unroll")                                                        \
    for (int i = 0; i < 2; ++i)                                              \
        _Pragma("unroll")                                                    \
        for (int j = 0; j < 8; ++j)                                          \
            _Pragma("unroll")                                                \
            for (int c = 0; c < 4; ++c) acc[i][j][c] = 0.f;

// ---- plain-A issue + mainloop ----
__device__ __forceinline__ void gemm1_issue(
    uint32_t stg, const uint16_t* __restrict__ A,
    const uint16_t* __restrict__ B, int bm, int bn, int k0, int tid) {
#pragma unroll
    for (int u = 0; u < 2; ++u) {
        int q = tid + u * 256;
        int r = q >> 2, c = q & 3;
        uint32_t d = r * GPITCH + c * 16;
        cp_async16(stg + P_A + d, A + (size_t)(bm + r) * GK + k0 + c * 8);
        cp_async16(stg + P_B + d, B + (size_t)(bn + r) * GK + k0 + c * 8);
    }
}

#define GEMM1_MAINLOOP(A, B, bm, bn)                                         \
    gemm1_issue(sb, A, B, bm, bn, 0, tid);                                   \
    CP_COMMIT();                                                             \
    gemm1_issue(sb + P_STG, A, B, bm, bn, 32, tid);                          \
    CP_COMMIT();                                                             \
    for (int s = 0; s < 32; ++s) {                                           \
        if (s < 31) { CP_WAIT(1); } else { CP_WAIT(0); }                     \
        __syncthreads();                                                     \
        if (s + 2 < 32) {                                                    \
            gemm1_issue(sb + ((s + 2) % 3) * P_STG, A, B,                    \
                        bm, bn, (s + 2) * 32, tid);                          \
            CP_COMMIT();                                                     \
        }                                                                    \
        const uint32_t stg = sb + (s % 3) * P_STG;                           \
        _Pragma("unroll")                                                    \
        for (int ks = 0; ks < 2; ++ks) {                                     \
            uint32_t bh4[4][4];                                              \
            _Pragma("unroll")                                                \
            for (int nb = 0; nb < 4; ++nb)                                   \
                LDSM_X4(bh4[nb], stg + P_B + bAddr[nb] + ks * 32);           \
            _Pragma("unroll")                                                \
            for (int mf = 0; mf < 2; ++mf) {                                 \
                uint32_t ah[4];                                              \
                LDSM_X4(ah, stg + P_A + aAddr[mf] + ks * 32);                \
                _Pragma("unroll")                                            \
                for (int nb = 0; nb < 4; ++nb) {                             \
                    MMA_F16(acc[mf][2*nb],   ah, bh4[nb][0], bh4[nb][1]);    \
                    MMA_F16(acc[mf][2*nb+1], ah, bh4[nb][2], bh4[nb][3]);    \
                }                                                            \
            }                                                                \
        }                                                                    \
    }

// ---- split-A issue + mainloop ----
__device__ __forceinline__ void gemm2_issue(
    uint32_t stg, const uint16_t* __restrict__ Ah,
    const uint16_t* __restrict__ Al, const uint16_t* __restrict__ B,
    int bm, int bn, int k0, int tid) {
#pragma unroll
    for (int u = 0; u < 2; ++u) {
        int q = tid + u * 256;
        int r = q >> 2, c = q & 3;
        uint32_t d = r * GPITCH + c * 16;
        size_t sa = (size_t)(bm + r) * GK + k0 + c * 8;
        cp_async16(stg + S_AH + d, Ah + sa);
        cp_async16(stg + S_AL + d, Al + sa);
        cp_async16(stg + S_B  + d, B + (size_t)(bn + r) * GK + k0 + c * 8);
    }
}

#define GEMM2_MAINLOOP(Ah, Al, B, bm, bn)                                    \
    gemm2_issue(sb, Ah, Al, B, bm, bn, 0, tid);                              \
    CP_COMMIT();                                                             \
    gemm2_issue(sb + S_STG, Ah, Al, B, bm, bn, 32, tid);                     \
    CP_COMMIT();                                                             \
    for (int s = 0; s < 32; ++s) {                                           \
        if (s < 31) { CP_WAIT(1); } else { CP_WAIT(0); }                     \
        __syncthreads();                                                     \
        if (s + 2 < 32) {                                                    \
            gemm2_issue(sb + ((s + 2) % 3) * S_STG, Ah, Al, B,               \
                        bm, bn, (s + 2) * 32, tid);                          \
            CP_COMMIT();                                                     \
        }                                                                    \
        const uint32_t stg = sb + (s % 3) * S_STG;                           \
        _Pragma("unroll")                                                    \
        for (int ks = 0; ks < 2; ++ks) {                                     \
            uint32_t bh4[4][4];                                              \
            _Pragma("unroll")                                                \
            for (int nb = 0; nb < 4; ++nb)                                   \
                LDSM_X4(bh4[nb], stg + S_B + bAddr[nb] + ks * 32);           \
            _Pragma("unroll")                                                \
            for (int mf = 0; mf < 2; ++mf) {                                 \
                uint32_t ah[4], al[4];                                       \
                LDSM_X4(ah, stg + S_AH + aAddr[mf] + ks * 32);               \
                LDSM_X4(al, stg + S_AL + aAddr[mf] + ks * 32);               \
                _Pragma("unroll")                                            \
                for (int nb = 0; nb < 4; ++nb) {                             \
                    MMA_F16(acc[mf][2*nb],   ah, bh4[nb][0], bh4[nb][1]);    \
                    MMA_F16(acc[mf][2*nb+1], ah, bh4[nb][2], bh4[nb][3]);    \
                    MMA_F16(acc[mf][2*nb],   al, bh4[nb][0], bh4[nb][1]);    \
                    MMA_F16(acc[mf][2*nb+1], al, bh4[nb][2], bh4[nb][3]);    \
                }                                                            \
            }                                                                \
        }                                                                    \
    }

// =================================================================
// QKV GEMM (A plain) with fused RMSNorm+RoPE+split epilogue.
// =================================================================
__global__ __launch_bounds__(256, 2)
void gemm_qkv(const uint16_t* __restrict__ A, const uint16_t* __restrict__ B,
              const float* __restrict__ qw, const float* __restrict__ kw,
              const float* __restrict__ cosT, const float* __restrict__ sinT,
              uint16_t* __restrict__ qh, uint16_t* __restrict__ ql,
              uint16_t* __restrict__ kh, uint16_t* __restrict__ vh) {
    GEMM_PREAMBLE
    GEMM1_MAINLOOP(A, B, bm, bn)

    const int cb = bn + wn * 64;
    const int sect = cb >> 10;          // 0=Q, 1=K, 2=V
    const int hh = (cb >> 6) & 15;

#pragma unroll
    for (int mf = 0; mf < 2; ++mf) {
#pragma unroll
        for (int hf = 0; hf < 2; ++hf) {
            const int row = bm + wm * 32 + mf * 16 + gid + hf * 8;
            const int s = row & (Ss - 1);
            const int b = row >> 11;
            const size_t dst = (((size_t)(b * Hh + hh)) * Ss + s) * HDd;
            float v[8][2];
#pragma unroll
            for (int nf = 0; nf < 8; ++nf) {
                v[nf][0] = acc[mf][nf][hf * 2];
                v[nf][1] = acc[mf][nf][hf * 2 + 1];
            }
            if (sect == 2) {   // V: plain fp16
#pragma unroll
                for (int nf = 0; nf < 8; ++nf) {
                    int d0 = nf * 8 + tig * 2;
                    *(uint32_t*)&vh[dst + d0] = pack_h2(v[nf][0], v[nf][1]);
                }
            } else {           // Q or K: rms + rope
                float ss = 0.f;
#pragma unroll
                for (int nf = 0; nf < 8; ++nf)
                    ss += v[nf][0] * v[nf][0] + v[nf][1] * v[nf][1];
                ss += __shfl_xor_sync(0xffffffffu, ss, 1);
                ss += __shfl_xor_sync(0xffffffffu, ss, 2);
                const float r = rsqrtf(ss * (1.0f / 64.0f) + 1e-6f);
                const float* w = sect ? kw : qw;
#pragma unroll
                for (int nf = 0; nf < 4; ++nf) {
                    int d0 = nf * 8 + tig * 2;
                    float2 w1 = *(const float2*)&w[d0];
                    float2 w2 = *(const float2*)&w[d0 + 32];
                    float2 cs = *(const float2*)&cosT[s * 32 + d0];
                    float2 sn = *(const float2*)&sinT[s * 32 + d0];
                    float x1a = v[nf][0]     * r * w1.x;
                    float x1b = v[nf][1]     * r * w1.y;
                    float x2a = v[nf + 4][0] * r * w2.x;
                    float x2b = v[nf + 4][1] * r * w2.y;
                    float o1a = x1a * cs.x - x2a * sn.x;
                    float o1b = x1b * cs.y - x2b * sn.y;
                    float o2a = x2a * cs.x + x1a * sn.x;
                    float o2b = x2b * cs.y + x1b * sn.y;
                    if (sect == 0) {   // Q: scale + split
                        o1a *= SC2; o1b *= SC2; o2a *= SC2; o2b *= SC2;
                        uint32_t hi, lo;
                        split2_h(o1a, o1b, hi, lo);
                        *(uint32_t*)&qh[dst + d0] = hi;
                        *(uint32_t*)&ql[dst + d0] = lo;
                        split2_h(o2a, o2b, hi, lo);
                        *(uint32_t*)&qh[dst + d0 + 32] = hi;
                        *(uint32_t*)&ql[dst + d0 + 32] = lo;
                    } else {           // K: plain fp16
                        *(uint32_t*)&kh[dst + d0]      = pack_h2(o1a, o1b);
                        *(uint32_t*)&kh[dst + d0 + 32] = pack_h2(o2a, o2b);
                    }
                }
            }
        }
    }
}

// =================================================================
// Output-projection GEMM (A = aoh+aol split, fp32 C)
// =================================================================
__global__ __launch_bounds__(256, 2)
void gemm_out(const uint16_t* __restrict__ Ah, const uint16_t* __restrict__ Al,
              const uint16_t* __restrict__ B, float* __restrict__ C) {
    GEMM_PREAMBLE
    GEMM2_MAINLOOP(Ah, Al, B, bm, bn)
#pragma unroll
    for (int mf = 0; mf < 2; ++mf) {
        const int row = bm + wm * 32 + mf * 16 + gid;
#pragma unroll
        for (int nf = 0; nf < 8; ++nf) {
            const int col = bn + wn * 64 + nf * 8 + tig * 2;
            *(float2*)&C[(size_t)row * Dd + col] =
                make_float2(acc[mf][nf][0], acc[mf][nf][1]);
            *(float2*)&C[(size_t)(row + 8) * Dd + col] =
                make_float2(acc[mf][nf][2], acc[mf][nf][3]);
        }
    }
}

// =================================================================
// fp16 flash attention: Q pre-scaled split, K plain, V plain.
// exp2-domain softmax; l via ones-column tensor MMA.
// Br=128, Bc=64, 3-stage KV ring, 2 CTAs/SM.
// =================================================================
#define APITCH 144
#define A_QH 0
#define A_QL 18432
#define A_QSZ 36864
#define A_K  0
#define A_V  9216
#define A_STG 18432
#define ATTN_SMEM (A_QSZ + 3 * A_STG)   // 92160
#define ONES_H2 0x3C003C00u

__device__ __forceinline__ void attn_kv_issue(
    uint32_t stg, const uint16_t* __restrict__ kh,
    const uint16_t* __restrict__ vh, size_t seqbase, int j, int tid) {
#pragma unroll
    for (int u = 0; u < 2; ++u) {
        int q = tid + u * 256;          // 0..511
        int r = q >> 3, c = q & 7;
        size_t src = seqbase + (size_t)(j * 64 + r) * 64 + c * 8;
        uint32_t d = r * APITCH + c * 16;
        cp_async16(stg + A_K + d, kh + src);
        cp_async16(stg + A_V + d, vh + src);
    }
}

__global__ __launch_bounds__(256, 2)
void attn_tc(const uint16_t* __restrict__ qh, const uint16_t* __restrict__ ql,
             const uint16_t* __restrict__ kh, const uint16_t* __restrict__ vh,
             const float* __restrict__ sinkl,
             uint16_t* __restrict__ aoh, uint16_t* __restrict__ aol) {
    extern __shared__ char smem[];
    const uint32_t sb = smem_u32(smem);
    const int tid = threadIdx.x;
    const int wid = tid >> 5, lane = tid & 31;
    const int gid = lane >> 2, tig = lane & 3;
    const int qb = gridDim.x - 1 - blockIdx.x;   // heavy tiles first
    const int bh = blockIdx.y;
    const int h  = bh & (Hh - 1);
    const int b  = bh >> 4;
    const size_t seqbase = (size_t)bh * Ss * HDd;
    const int q0 = qb * 128;
    const int jmax = 2 * qb + 1;

    // ---- prologue: Q tile + KV stage 0, then KV stage 1 ----
#pragma unroll
    for (int u = 0; u < 4; ++u) {
        int q = tid + u * 256;
        int r = q >> 3, c = q & 7;
        size_t src = seqbase + (size_t)(q0 + r) * 64 + c * 8;
        uint32_t d = r * APITCH + c * 16;
        cp_async16(sb + A_QH + d, qh + src);
        cp_async16(sb + A_QL + d, ql + src);
    }
    attn_kv_issue(sb + A_QSZ, kh, vh, seqbase, 0, tid);
    CP_COMMIT();
    attn_kv_issue(sb + A_QSZ + A_STG, kh, vh, seqbase, 1, tid);
    CP_COMMIT();

    const uint32_t qA = sb + A_QH + (wid * 16 + (lane & 15)) * APITCH
                        + (lane >> 4) * 16;
    uint32_t kB[4];
#pragma unroll
    for (int nb = 0; nb < 4; ++nb)
        kB[nb] = A_K + (nb * 16 + ((lane >> 4) << 3) + (lane & 7)) * APITCH
                 + ((lane >> 3) & 1) * 16;
    const uint32_t vBrel = A_V + (lane & 15) * APITCH + (lane >> 4) * 16;

    const float snk2 = sinkl[h] * LOG2E;
    float m0 = snk2, m1 = snk2;
    float o[8][4], ol[4];
#pragma unroll
    for (int i = 0; i < 8; ++i)
#pragma unroll
        for (int c = 0; c < 4; ++c) o[i][c] = 0.f;
#pragma unroll
    for (int c = 0; c < 4; ++c) ol[c] = 0.f;

    const int r0g = q0 + wid * 16 + gid;
    const int r1g = r0g + 8;

    for (int j = 0; j <= jmax; ++j) {
        if (j < jmax) { CP_WAIT(1); } else { CP_WAIT(0); }
        __syncthreads();
        if (j + 2 <= jmax) {
            attn_kv_issue(sb + A_QSZ + ((j + 2) % 3) * A_STG,
                          kh, vh, seqbase, j + 2, tid);
            CP_COMMIT();
        }
        const uint32_t stg = sb + A_QSZ + (j % 3) * A_STG;

        // ---- S = Q K^T (Q split pre-scaled, K plain) ----
        float s[8][4];
#pragma unroll
        for (int i = 0; i < 8; ++i)
#pragma unroll
            for (int c = 0; c < 4; ++c) s[i][c] = 0.f;

#pragma unroll
        for (int ks = 0; ks < 4; ++ks) {
            uint32_t qah[4], qal[4];
            LDSM_X4(qah, qA + ks * 32);
            LDSM_X4(qal, qA + (A_QL - A_QH) + ks * 32);
#pragma unroll
            for (int nb = 0; nb < 4; ++nb) {
                uint32_t kb4[4];
                LDSM_X4(kb4, stg + kB[nb] + ks * 32);
                MMA_F16(s[2*nb],   qah, kb4[0], kb4[1]);
                MMA_F16(s[2*nb+1], qah, kb4[2], kb4[3]);
                MMA_F16(s[2*nb],   qal, kb4[0], kb4[1]);
                MMA_F16(s[2*nb+1], qal, kb4[2], kb4[3]);
            }
        }

        // ---- causal mask (diagonal blocks only) ----
        if (j >= 2 * qb) {
#pragma unroll
            for (int nf = 0; nf < 8; ++nf)
#pragma unroll
                for (int c = 0; c < 4; ++c) {
                    int col = j * 64 + nf * 8 + tig * 2 + (c & 1);
                    int row = (c < 2) ? r0g : r1g;
                    if (col > row) s[nf][c] = -1e30f;
                }
        }

        // ---- online softmax (base-2) ----
        float mx0 = -1e30f, mx1 = -1e30f;
#pragma unroll
        for (int nf = 0; nf < 8; ++nf) {
            mx0 = fmaxf(mx0, fmaxf(s[nf][0], s[nf][1]));
            mx1 = fmaxf(mx1, fmaxf(s[nf][2], s[nf][3]));
        }
        mx0 = fmaxf(mx0, __shfl_xor_sync(0xffffffffu, mx0, 1));
        mx0 = fmaxf(mx0, __shfl_xor_sync(0xffffffffu, mx0, 2));
        mx1 = fmaxf(mx1, __shfl_xor_sync(0xffffffffu, mx1, 1));
        mx1 = fmaxf(mx1, __shfl_xor_sync(0xffffffffu, mx1, 2));
        const float mn0 = fmaxf(m0, mx0), mn1 = fmaxf(m1, mx1);
        const float cr0 = ex2f(m0 - mn0), cr1 = ex2f(m1 - mn1);
        m0 = mn0; m1 = mn1;
#pragma unroll
        for (int nf = 0; nf < 8; ++nf) {
            o[nf][0] *= cr0; o[nf][1] *= cr0;
            o[nf][2] *= cr1; o[nf][3] *= cr1;
        }
        ol[0] *= cr0; ol[1] *= cr0; ol[2] *= cr1; ol[3] *= cr1;

        // P = 2^(s-m), packed straight into fp16 fragments
        uint32_t pp[8][2];
#pragma unroll
        for (int nf = 0; nf < 8; ++nf) {
            float e0 = ex2f(s[nf][0] - mn0);
            float e1 = ex2f(s[nf][1] - mn0);
            float e2 = ex2f(s[nf][2] - mn1);
            float e3 = ex2f(s[nf][3] - mn1);
            pp[nf][0] = pack_h2(e0, e1);
            pp[nf][1] = pack_h2(e2, e3);
        }

        // ---- O += P V ;  l += P * ones ----
#pragma unroll
        for (int ks = 0; ks < 4; ++ks) {
            uint32_t pa[4] = { pp[2*ks][0], pp[2*ks][1],
                               pp[2*ks+1][0], pp[2*ks+1][1] };
            MMA_F16(ol, pa, ONES_H2, ONES_H2);
#pragma unroll
            for (int db = 0; db < 4; ++db) {
                uint32_t vb4[4];
                LDSM_X4_T(vb4, stg + vBrel + ks * 16 * APITCH + db * 32);
                MMA_F16(o[2*db],   pa, vb4[0], vb4[1]);
                MMA_F16(o[2*db+1], pa, vb4[2], vb4[3]);
            }
        }
    }

    // ---- epilogue: add sink to l, normalize, split, store ----
    const float l0 = ol[0] + ex2f(snk2 - m0);
    const float l1 = ol[2] + ex2f(snk2 - m1);
    const float i0 = 1.f / l0, i1 = 1.f / l1;
#pragma unroll
    for (int nf = 0; nf < 8; ++nf) {
        const int col = h * HDd + nf * 8 + tig * 2;
        {
            float y0 = o[nf][0] * i0, y1 = o[nf][1] * i0;
            size_t idx = ((size_t)(b * Ss + r0g)) * Dd + col;
            uint32_t hi, lo;
            split2_h(y0, y1, hi, lo);
            *(uint32_t*)&aoh[idx] = hi;
            *(uint32_t*)&aol[idx] = lo;
        }
        {
            float y2 = o[nf][2] * i1, y3 = o[nf][3] * i1;
            size_t idx = ((size_t)(b * Ss + r1g)) * Dd + col;
            uint32_t hi, lo;
            split2_h(y2, y3, hi, lo);
            *(uint32_t*)&aoh[idx] = hi;
            *(uint32_t*)&aol[idx] = lo;
        }
    }
}

// =================================================================
extern "C" void kernel_launch(void* const* d_in, const int* in_sizes, int n_in,
                              void* d_out, int out_size) {
    const float* x  = (const float*)d_in[0];
    const float* wq = (const float*)d_in[1];
    const float* wk = (const float*)d_in[2];
    const float* wv = (const float*)d_in[3];
    const float* wo = (const float*)d_in[4];
    const float* qw = (const float*)d_in[5];
    const float* kw = (const float*)d_in[6];
    const float* sk = (const float*)d_in[7];
    float* out = (float*)d_out;

    uint16_t *xh, *wh, *woh;
    uint16_t *qhp, *qlp, *khp, *vhp, *aoh, *aol;
    float *cosT, *sinT;
    cudaGetSymbolAddress((void**)&xh,  g_xh);
    cudaGetSymbolAddress((void**)&wh,  g_wh);
    cudaGetSymbolAddress((void**)&woh, g_woh);
    cudaGetSymbolAddress((void**)&qhp, g_qh);
    cudaGetSymbolAddress((void**)&qlp, g_ql);
    cudaGetSymbolAddress((void**)&khp, g_kh);
    cudaGetSymbolAddress((void**)&vhp, g_vh);
    cudaGetSymbolAddress((void**)&aoh, g_aoh);
    cudaGetSymbolAddress((void**)&aol, g_aol);
    cudaGetSymbolAddress((void**)&cosT, g_cosT);
    cudaGetSymbolAddress((void**)&sinT, g_sinT);

    cudaFuncSetAttribute(gemm_qkv, cudaFuncAttributeMaxDynamicSharedMemorySize,
                         GEMM1_SMEM);
    cudaFuncSetAttribute(gemm_out, cudaFuncAttributeMaxDynamicSharedMemorySize,
                         GEMM2_SMEM);
    cudaFuncSetAttribute(attn_tc, cudaFuncAttributeMaxDynamicSharedMemorySize,
                         ATTN_SMEM);

    // converts + rope tables
    cvt_all<<<8192, 256>>>((const float4*)x, (const float4*)wq,
                           (const float4*)wk, (const float4*)wv,
                           (const float4*)wo,
                           (uint2*)xh, (uint2*)wh, (uint2*)woh, cosT, sinT);

    // QKV projection + fused norm/rope/split (A plain)
    gemm_qkv<<<dim3(3072 / 128, Mrows / 128), 256, GEMM1_SMEM>>>(
        xh, wh, qw, kw, cosT, sinT, qhp, qlp, khp, vhp);

    // flash attention
    attn_tc<<<dim3(Ss / 128, Bb * Hh), 256, ATTN_SMEM>>>(
        qhp, qlp, khp, vhp, sk, aoh, aol);

    // output projection (A split)
    gemm_out<<<dim3(Dd / 128, Mrows / 128), 256, GEMM2_SMEM>>>(
        aoh, aol, woh, out);
}

// round 9
// speedup vs baseline: 6.9640x; 1.0789x over previous
#include <cuda_runtime.h>
#include <cuda_fp16.h>
#include <stdint.h>
#include <math.h>

// Problem constants
#define Bb   2
#define Ss   2048
#define Dd   1024
#define Hh   16
#define HDd  64
#define Mrows (Bb*Ss)   // 4096

#define SC2 0.18033688011112042f   // 0.125 * log2(e), folded into Q
#define LOG2E 1.4426950408889634f

// ---------------- scratch (no allocs allowed) ----------------
__device__ uint16_t g_xh [Mrows * Dd];            // x fp16 (plain)
__device__ uint16_t g_wh [3072 * Dd];             // fused wq|wk|wv fp16
__device__ uint16_t g_woh[Dd * Dd];               // wo fp16
__device__ uint16_t g_qh [Mrows * Dd];            // [B,H,S,64] fp16 hi/lo (pre-scaled)
__device__ uint16_t g_ql [Mrows * Dd];
__device__ uint16_t g_kh [Mrows * Dd];            // fp16
__device__ uint16_t g_vh [Mrows * Dd];            // fp16 (plain)
__device__ uint16_t g_aoh[Mrows * Dd];            // attn out fp16 (plain)
__device__ float    g_cosT[Ss * 32];              // rope tables
__device__ float    g_sinT[Ss * 32];

// ================= PTX helpers ==========================
__device__ __forceinline__ uint32_t smem_u32(const void* p) {
    uint32_t a;
    asm("{ .reg .u64 t; cvta.to.shared.u64 t, %1; cvt.u32.u64 %0, t; }"
        : "=r"(a) : "l"(p));
    return a;
}
__device__ __forceinline__ void cp_async16(uint32_t s, const void* g) {
    asm volatile("cp.async.cg.shared.global [%0], [%1], 16;" :: "r"(s), "l"(g));
}
#define CP_COMMIT() asm volatile("cp.async.commit_group;" ::: "memory")
#define CP_WAIT(n)  asm volatile("cp.async.wait_group %0;" :: "n"(n) : "memory")

#define LDSM_X4(r, addr) \
    asm volatile("ldmatrix.sync.aligned.m8n8.x4.shared.b16 {%0,%1,%2,%3}, [%4];" \
        : "=r"((r)[0]), "=r"((r)[1]), "=r"((r)[2]), "=r"((r)[3]) : "r"(addr))
#define LDSM_X4_T(r, addr) \
    asm volatile("ldmatrix.sync.aligned.m8n8.x4.trans.shared.b16 {%0,%1,%2,%3}, [%4];" \
        : "=r"((r)[0]), "=r"((r)[1]), "=r"((r)[2]), "=r"((r)[3]) : "r"(addr))

#define MMA_F16(d, a, b0, b1) \
    asm volatile("mma.sync.aligned.m16n8k16.row.col.f32.f16.f16.f32 " \
        "{%0,%1,%2,%3}, {%4,%5,%6,%7}, {%8,%9}, {%0,%1,%2,%3};" \
        : "+f"((d)[0]), "+f"((d)[1]), "+f"((d)[2]), "+f"((d)[3]) \
        : "r"((a)[0]), "r"((a)[1]), "r"((a)[2]), "r"((a)[3]), \
          "r"(b0), "r"(b1))

__device__ __forceinline__ uint32_t pack_h2(float a, float b) {
    uint32_t r;
    asm("cvt.rn.f16x2.f32 %0, %1, %2;" : "=r"(r) : "f"(b), "f"(a));
    return r;
}
__device__ __forceinline__ void split2_h(float x0, float x1,
                                         uint32_t& hi, uint32_t& lo) {
    hi = pack_h2(x0, x1);
    float2 f = __half22float2(*reinterpret_cast<__half2*>(&hi));
    lo = pack_h2(x0 - f.x, x1 - f.y);
}
__device__ __forceinline__ float ex2f(float x) {
    float y;
    asm("ex2.approx.f32 %0, %1;" : "=f"(y) : "f"(x));
    return y;
}

// =================================================================
// fused convert: x, w, wo -> plain fp16 ; rope tables
// =================================================================
__global__ __launch_bounds__(256)
void cvt_all(const float4* __restrict__ x,  const float4* __restrict__ wq,
             const float4* __restrict__ wk, const float4* __restrict__ wv,
             const float4* __restrict__ wo,
             uint2* __restrict__ xh, uint2* __restrict__ wh,
             uint2* __restrict__ woh,
             float* __restrict__ cosT, float* __restrict__ sinT) {
    int i = blockIdx.x * 256 + threadIdx.x;     // 0 .. 2M-1
    if (i < 65536) {  // rope table
        int s = i >> 5, j = i & 31;
        float inv = exp2f(-(float)j * 0.4152410118609203f);  // log2(1e4)/32
        float sn, cs;
        sincosf((float)s * inv, &sn, &cs);
        cosT[i] = cs;
        sinT[i] = sn;
    }
    const float4* src;
    uint2* dst;
    if (i < 1048576) {
        src = x + i; dst = xh + i;
    } else {
        int i2 = i - 1048576;
        int reg = i2 >> 18;            // 0..3
        int off = i2 & 262143;
        if (reg == 0)      { src = wq + off; dst = wh + off; }
        else if (reg == 1) { src = wk + off; dst = wh + 262144 + off; }
        else if (reg == 2) { src = wv + off; dst = wh + 524288 + off; }
        else               { src = wo + off; dst = woh + off; }
    }
    float4 v = *src;
    uint2 o;
    o.x = pack_h2(v.x, v.y);
    o.y = pack_h2(v.z, v.w);
    *dst = o;
}

// =================================================================
// GEMM framework: plain-A fp16 HMMA, tile 128x128x32, 256 thr,
// warps 4(M)x2(N), warp 32x64, 3-stage cp.async ring, 2+ CTAs/SM.
// =================================================================
#define GK 1024
#define GPITCH 80
#define P_A  0
#define P_B  10240
#define P_STG 20480
#define GEMM1_SMEM (3 * P_STG)    // 61440

#define GEMM_PREAMBLE                                                        \
    extern __shared__ char smem[];                                           \
    const uint32_t sb = smem_u32(smem);                                      \
    const int tid = threadIdx.x;                                             \
    const int wid = tid >> 5, lane = tid & 31;                               \
    const int wm = wid & 3, wn = wid >> 2;                                   \
    const int gid = lane >> 2, tig = lane & 3;                               \
    const int bm = blockIdx.y * 128, bn = blockIdx.x * 128;                  \
    uint32_t aAddr[2], bAddr[4];                                             \
    _Pragma("unroll")                                                        \
    for (int mf = 0; mf < 2; ++mf)                                           \
        aAddr[mf] = (wm * 32 + mf * 16 + (lane & 15)) * GPITCH               \
                    + (lane >> 4) * 16;                                      \
    _Pragma("unroll")                                                        \
    for (int nb = 0; nb < 4; ++nb)                                           \
        bAddr[nb] = (wn * 64 + nb * 16 + ((lane >> 4) << 3)                  \
                    + (lane & 7)) * GPITCH + ((lane >> 3) & 1) * 16;         \
    float acc[2][8][4];                                                      \
    _Pragma("unroll")                                                        \
    for (int i = 0; i < 2; ++i)                                              \
        _Pragma("unroll")                                                    \
        for (int j = 0; j < 8; ++j)                                          \
            _Pragma("unroll")                                                \
            for (int c = 0; c < 4; ++c) acc[i][j][c] = 0.f;

__device__ __forceinline__ void gemm1_issue(
    uint32_t stg, const uint16_t* __restrict__ A,
    const uint16_t* __restrict__ B, int bm, int bn, int k0, int tid) {
#pragma unroll
    for (int u = 0; u < 2; ++u) {
        int q = tid + u * 256;
        int r = q >> 2, c = q & 3;
        uint32_t d = r * GPITCH + c * 16;
        cp_async16(stg + P_A + d, A + (size_t)(bm + r) * GK + k0 + c * 8);
        cp_async16(stg + P_B + d, B + (size_t)(bn + r) * GK + k0 + c * 8);
    }
}

#define GEMM1_MAINLOOP(A, B, bm, bn)                                         \
    gemm1_issue(sb, A, B, bm, bn, 0, tid);                                   \
    CP_COMMIT();                                                             \
    gemm1_issue(sb + P_STG, A, B, bm, bn, 32, tid);                          \
    CP_COMMIT();                                                             \
    for (int s = 0; s < 32; ++s) {                                           \
        if (s < 31) { CP_WAIT(1); } else { CP_WAIT(0); }                     \
        __syncthreads();                                                     \
        if (s + 2 < 32) {                                                    \
            gemm1_issue(sb + ((s + 2) % 3) * P_STG, A, B,                    \
                        bm, bn, (s + 2) * 32, tid);                          \
            CP_COMMIT();                                                     \
        }                                                                    \
        const uint32_t stg = sb + (s % 3) * P_STG;                           \
        _Pragma("unroll")                                                    \
        for (int ks = 0; ks < 2; ++ks) {                                     \
            uint32_t bh4[4][4];                                              \
            _Pragma("unroll")                                                \
            for (int nb = 0; nb < 4; ++nb)                                   \
                LDSM_X4(bh4[nb], stg + P_B + bAddr[nb] + ks * 32);           \
            _Pragma("unroll")                                                \
            for (int mf = 0; mf < 2; ++mf) {                                 \
                uint32_t ah[4];                                              \
                LDSM_X4(ah, stg + P_A + aAddr[mf] + ks * 32);                \
                _Pragma("unroll")                                            \
                for (int nb = 0; nb < 4; ++nb) {                             \
                    MMA_F16(acc[mf][2*nb],   ah, bh4[nb][0], bh4[nb][1]);    \
                    MMA_F16(acc[mf][2*nb+1], ah, bh4[nb][2], bh4[nb][3]);    \
                }                                                            \
            }                                                                \
        }                                                                    \
    }

// =================================================================
// QKV GEMM (A plain) with fused RMSNorm+RoPE+split epilogue.
// =================================================================
__global__ __launch_bounds__(256, 2)
void gemm_qkv(const uint16_t* __restrict__ A, const uint16_t* __restrict__ B,
              const float* __restrict__ qw, const float* __restrict__ kw,
              const float* __restrict__ cosT, const float* __restrict__ sinT,
              uint16_t* __restrict__ qh, uint16_t* __restrict__ ql,
              uint16_t* __restrict__ kh, uint16_t* __restrict__ vh) {
    GEMM_PREAMBLE
    GEMM1_MAINLOOP(A, B, bm, bn)

    const int cb = bn + wn * 64;
    const int sect = cb >> 10;          // 0=Q, 1=K, 2=V
    const int hh = (cb >> 6) & 15;

#pragma unroll
    for (int mf = 0; mf < 2; ++mf) {
#pragma unroll
        for (int hf = 0; hf < 2; ++hf) {
            const int row = bm + wm * 32 + mf * 16 + gid + hf * 8;
            const int s = row & (Ss - 1);
            const int b = row >> 11;
            const size_t dst = (((size_t)(b * Hh + hh)) * Ss + s) * HDd;
            float v[8][2];
#pragma unroll
            for (int nf = 0; nf < 8; ++nf) {
                v[nf][0] = acc[mf][nf][hf * 2];
                v[nf][1] = acc[mf][nf][hf * 2 + 1];
            }
            if (sect == 2) {   // V: plain fp16
#pragma unroll
                for (int nf = 0; nf < 8; ++nf) {
                    int d0 = nf * 8 + tig * 2;
                    *(uint32_t*)&vh[dst + d0] = pack_h2(v[nf][0], v[nf][1]);
                }
            } else {           // Q or K: rms + rope
                float ss = 0.f;
#pragma unroll
                for (int nf = 0; nf < 8; ++nf)
                    ss += v[nf][0] * v[nf][0] + v[nf][1] * v[nf][1];
                ss += __shfl_xor_sync(0xffffffffu, ss, 1);
                ss += __shfl_xor_sync(0xffffffffu, ss, 2);
                const float r = rsqrtf(ss * (1.0f / 64.0f) + 1e-6f);
                const float* w = sect ? kw : qw;
#pragma unroll
                for (int nf = 0; nf < 4; ++nf) {
                    int d0 = nf * 8 + tig * 2;
                    float2 w1 = *(const float2*)&w[d0];
                    float2 w2 = *(const float2*)&w[d0 + 32];
                    float2 cs = *(const float2*)&cosT[s * 32 + d0];
                    float2 sn = *(const float2*)&sinT[s * 32 + d0];
                    float x1a = v[nf][0]     * r * w1.x;
                    float x1b = v[nf][1]     * r * w1.y;
                    float x2a = v[nf + 4][0] * r * w2.x;
                    float x2b = v[nf + 4][1] * r * w2.y;
                    float o1a = x1a * cs.x - x2a * sn.x;
                    float o1b = x1b * cs.y - x2b * sn.y;
                    float o2a = x2a * cs.x + x1a * sn.x;
                    float o2b = x2b * cs.y + x1b * sn.y;
                    if (sect == 0) {   // Q: scale + split
                        o1a *= SC2; o1b *= SC2; o2a *= SC2; o2b *= SC2;
                        uint32_t hi, lo;
                        split2_h(o1a, o1b, hi, lo);
                        *(uint32_t*)&qh[dst + d0] = hi;
                        *(uint32_t*)&ql[dst + d0] = lo;
                        split2_h(o2a, o2b, hi, lo);
                        *(uint32_t*)&qh[dst + d0 + 32] = hi;
                        *(uint32_t*)&ql[dst + d0 + 32] = lo;
                    } else {           // K: plain fp16
                        *(uint32_t*)&kh[dst + d0]      = pack_h2(o1a, o1b);
                        *(uint32_t*)&kh[dst + d0 + 32] = pack_h2(o2a, o2b);
                    }
                }
            }
        }
    }
}

// =================================================================
// Output-projection GEMM (A plain fp16, fp32 C)
// =================================================================
__global__ __launch_bounds__(256, 2)
void gemm_out(const uint16_t* __restrict__ A, const uint16_t* __restrict__ B,
              float* __restrict__ C) {
    GEMM_PREAMBLE
    GEMM1_MAINLOOP(A, B, bm, bn)
#pragma unroll
    for (int mf = 0; mf < 2; ++mf) {
        const int row = bm + wm * 32 + mf * 16 + gid;
#pragma unroll
        for (int nf = 0; nf < 8; ++nf) {
            const int col = bn + wn * 64 + nf * 8 + tig * 2;
            *(float2*)&C[(size_t)row * Dd + col] =
                make_float2(acc[mf][nf][0], acc[mf][nf][1]);
            *(float2*)&C[(size_t)(row + 8) * Dd + col] =
                make_float2(acc[mf][nf][2], acc[mf][nf][3]);
        }
    }
}

// =================================================================
// fp16 flash attention: Q pre-scaled split, K plain, V plain.
// exp2-domain softmax; l via ones-column tensor MMA.
// Br=128, Bc=64, 3-stage KV ring, 2 CTAs/SM.
// =================================================================
#define APITCH 144
#define A_QH 0
#define A_QL 18432
#define A_QSZ 36864
#define A_K  0
#define A_V  9216
#define A_STG 18432
#define ATTN_SMEM (A_QSZ + 3 * A_STG)   // 92160
#define ONES_H2 0x3C003C00u

__device__ __forceinline__ void attn_kv_issue(
    uint32_t stg, const uint16_t* __restrict__ kh,
    const uint16_t* __restrict__ vh, size_t seqbase, int j, int tid) {
#pragma unroll
    for (int u = 0; u < 2; ++u) {
        int q = tid + u * 256;          // 0..511
        int r = q >> 3, c = q & 7;
        size_t src = seqbase + (size_t)(j * 64 + r) * 64 + c * 8;
        uint32_t d = r * APITCH + c * 16;
        cp_async16(stg + A_K + d, kh + src);
        cp_async16(stg + A_V + d, vh + src);
    }
}

__global__ __launch_bounds__(256, 2)
void attn_tc(const uint16_t* __restrict__ qh, const uint16_t* __restrict__ ql,
             const uint16_t* __restrict__ kh, const uint16_t* __restrict__ vh,
             const float* __restrict__ sinkl,
             uint16_t* __restrict__ aoh) {
    extern __shared__ char smem[];
    const uint32_t sb = smem_u32(smem);
    const int tid = threadIdx.x;
    const int wid = tid >> 5, lane = tid & 31;
    const int gid = lane >> 2, tig = lane & 3;
    const int qb = gridDim.x - 1 - blockIdx.x;   // heavy tiles first
    const int bh = blockIdx.y;
    const int h  = bh & (Hh - 1);
    const int b  = bh >> 4;
    const size_t seqbase = (size_t)bh * Ss * HDd;
    const int q0 = qb * 128;
    const int jmax = 2 * qb + 1;

    // ---- prologue: Q tile + KV stages 0,1 ----
#pragma unroll
    for (int u = 0; u < 4; ++u) {
        int q = tid + u * 256;
        int r = q >> 3, c = q & 7;
        size_t src = seqbase + (size_t)(q0 + r) * 64 + c * 8;
        uint32_t d = r * APITCH + c * 16;
        cp_async16(sb + A_QH + d, qh + src);
        cp_async16(sb + A_QL + d, ql + src);
    }
    attn_kv_issue(sb + A_QSZ, kh, vh, seqbase, 0, tid);
    CP_COMMIT();
    attn_kv_issue(sb + A_QSZ + A_STG, kh, vh, seqbase, 1, tid);
    CP_COMMIT();

    const uint32_t qA = sb + A_QH + (wid * 16 + (lane & 15)) * APITCH
                        + (lane >> 4) * 16;
    uint32_t kB[4];
#pragma unroll
    for (int nb = 0; nb < 4; ++nb)
        kB[nb] = A_K + (nb * 16 + ((lane >> 4) << 3) + (lane & 7)) * APITCH
                 + ((lane >> 3) & 1) * 16;
    const uint32_t vBrel = A_V + (lane & 15) * APITCH + (lane >> 4) * 16;

    const float snk2 = sinkl[h] * LOG2E;
    float m0 = snk2, m1 = snk2;
    float o[8][4], ol[4];
#pragma unroll
    for (int i = 0; i < 8; ++i)
#pragma unroll
        for (int c = 0; c < 4; ++c) o[i][c] = 0.f;
#pragma unroll
    for (int c = 0; c < 4; ++c) ol[c] = 0.f;

    const int r0g = q0 + wid * 16 + gid;
    const int r1g = r0g + 8;

    for (int j = 0; j <= jmax; ++j) {
        if (j < jmax) { CP_WAIT(1); } else { CP_WAIT(0); }
        __syncthreads();
        if (j + 2 <= jmax) {
            attn_kv_issue(sb + A_QSZ + ((j + 2) % 3) * A_STG,
                          kh, vh, seqbase, j + 2, tid);
            CP_COMMIT();
        }
        const uint32_t stg = sb + A_QSZ + (j % 3) * A_STG;

        // ---- S = Q K^T (Q split pre-scaled, K plain) ----
        float s[8][4];
#pragma unroll
        for (int i = 0; i < 8; ++i)
#pragma unroll
            for (int c = 0; c < 4; ++c) s[i][c] = 0.f;

#pragma unroll
        for (int ks = 0; ks < 4; ++ks) {
            uint32_t qah[4], qal[4];
            LDSM_X4(qah, qA + ks * 32);
            LDSM_X4(qal, qA + (A_QL - A_QH) + ks * 32);
#pragma unroll
            for (int nb = 0; nb < 4; ++nb) {
                uint32_t kb4[4];
                LDSM_X4(kb4, stg + kB[nb] + ks * 32);
                MMA_F16(s[2*nb],   qah, kb4[0], kb4[1]);
                MMA_F16(s[2*nb+1], qah, kb4[2], kb4[3]);
                MMA_F16(s[2*nb],   qal, kb4[0], kb4[1]);
                MMA_F16(s[2*nb+1], qal, kb4[2], kb4[3]);
            }
        }

        // ---- causal mask (diagonal blocks only) ----
        if (j >= 2 * qb) {
#pragma unroll
            for (int nf = 0; nf < 8; ++nf)
#pragma unroll
                for (int c = 0; c < 4; ++c) {
                    int col = j * 64 + nf * 8 + tig * 2 + (c & 1);
                    int row = (c < 2) ? r0g : r1g;
                    if (col > row) s[nf][c] = -1e30f;
                }
        }

        // ---- online softmax (base-2) ----
        float mx0 = -1e30f, mx1 = -1e30f;
#pragma unroll
        for (int nf = 0; nf < 8; ++nf) {
            mx0 = fmaxf(mx0, fmaxf(s[nf][0], s[nf][1]));
            mx1 = fmaxf(mx1, fmaxf(s[nf][2], s[nf][3]));
        }
        mx0 = fmaxf(mx0, __shfl_xor_sync(0xffffffffu, mx0, 1));
        mx0 = fmaxf(mx0, __shfl_xor_sync(0xffffffffu, mx0, 2));
        mx1 = fmaxf(mx1, __shfl_xor_sync(0xffffffffu, mx1, 1));
        mx1 = fmaxf(mx1, __shfl_xor_sync(0xffffffffu, mx1, 2));
        const float mn0 = fmaxf(m0, mx0), mn1 = fmaxf(m1, mx1);
        const float cr0 = ex2f(m0 - mn0), cr1 = ex2f(m1 - mn1);
        m0 = mn0; m1 = mn1;
#pragma unroll
        for (int nf = 0; nf < 8; ++nf) {
            o[nf][0] *= cr0; o[nf][1] *= cr0;
            o[nf][2] *= cr1; o[nf][3] *= cr1;
        }
        ol[0] *= cr0; ol[1] *= cr0; ol[2] *= cr1; ol[3] *= cr1;

        // ---- O += P V ;  l += P * ones (P packed inline) ----
#pragma unroll
        for (int ks = 0; ks < 4; ++ks) {
            uint32_t pa[4];
            pa[0] = pack_h2(ex2f(s[2*ks][0]   - mn0), ex2f(s[2*ks][1]   - mn0));
            pa[1] = pack_h2(ex2f(s[2*ks][2]   - mn1), ex2f(s[2*ks][3]   - mn1));
            pa[2] = pack_h2(ex2f(s[2*ks+1][0] - mn0), ex2f(s[2*ks+1][1] - mn0));
            pa[3] = pack_h2(ex2f(s[2*ks+1][2] - mn1), ex2f(s[2*ks+1][3] - mn1));
            MMA_F16(ol, pa, ONES_H2, ONES_H2);
#pragma unroll
            for (int db = 0; db < 4; ++db) {
                uint32_t vb4[4];
                LDSM_X4_T(vb4, stg + vBrel + ks * 16 * APITCH + db * 32);
                MMA_F16(o[2*db],   pa, vb4[0], vb4[1]);
                MMA_F16(o[2*db+1], pa, vb4[2], vb4[3]);
            }
        }
    }

    // ---- epilogue: add sink to l, normalize, plain fp16 store ----
    const float l0 = ol[0] + ex2f(snk2 - m0);
    const float l1 = ol[2] + ex2f(snk2 - m1);
    const float i0 = 1.f / l0, i1 = 1.f / l1;
#pragma unroll
    for (int nf = 0; nf < 8; ++nf) {
        const int col = h * HDd + nf * 8 + tig * 2;
        {
            size_t idx = ((size_t)(b * Ss + r0g)) * Dd + col;
            *(uint32_t*)&aoh[idx] = pack_h2(o[nf][0] * i0, o[nf][1] * i0);
        }
        {
            size_t idx = ((size_t)(b * Ss + r1g)) * Dd + col;
            *(uint32_t*)&aoh[idx] = pack_h2(o[nf][2] * i1, o[nf][3] * i1);
        }
    }
}

// =================================================================
extern "C" void kernel_launch(void* const* d_in, const int* in_sizes, int n_in,
                              void* d_out, int out_size) {
    const float* x  = (const float*)d_in[0];
    const float* wq = (const float*)d_in[1];
    const float* wk = (const float*)d_in[2];
    const float* wv = (const float*)d_in[3];
    const float* wo = (const float*)d_in[4];
    const float* qw = (const float*)d_in[5];
    const float* kw = (const float*)d_in[6];
    const float* sk = (const float*)d_in[7];
    float* out = (float*)d_out;

    uint16_t *xh, *wh, *woh;
    uint16_t *qhp, *qlp, *khp, *vhp, *aoh;
    float *cosT, *sinT;
    cudaGetSymbolAddress((void**)&xh,  g_xh);
    cudaGetSymbolAddress((void**)&wh,  g_wh);
    cudaGetSymbolAddress((void**)&woh, g_woh);
    cudaGetSymbolAddress((void**)&qhp, g_qh);
    cudaGetSymbolAddress((void**)&qlp, g_ql);
    cudaGetSymbolAddress((void**)&khp, g_kh);
    cudaGetSymbolAddress((void**)&vhp, g_vh);
    cudaGetSymbolAddress((void**)&aoh, g_aoh);
    cudaGetSymbolAddress((void**)&cosT, g_cosT);
    cudaGetSymbolAddress((void**)&sinT, g_sinT);

    cudaFuncSetAttribute(gemm_qkv, cudaFuncAttributeMaxDynamicSharedMemorySize,
                         GEMM1_SMEM);
    cudaFuncSetAttribute(gemm_out, cudaFuncAttributeMaxDynamicSharedMemorySize,
                         GEMM1_SMEM);
    cudaFuncSetAttribute(attn_tc, cudaFuncAttributeMaxDynamicSharedMemorySize,
                         ATTN_SMEM);

    // converts + rope tables
    cvt_all<<<8192, 256>>>((const float4*)x, (const float4*)wq,
                           (const float4*)wk, (const float4*)wv,
                           (const float4*)wo,
                           (uint2*)xh, (uint2*)wh, (uint2*)woh, cosT, sinT);

    // QKV projection + fused norm/rope/split (A plain)
    gemm_qkv<<<dim3(3072 / 128, Mrows / 128), 256, GEMM1_SMEM>>>(
        xh, wh, qw, kw, cosT, sinT, qhp, qlp, khp, vhp);

    // flash attention
    attn_tc<<<dim3(Ss / 128, Bb * Hh), 256, ATTN_SMEM>>>(
        qhp, qlp, khp, vhp, sk, aoh);

    // output projection (A plain)
    gemm_out<<<dim3(Dd / 128, Mrows / 128), 256, GEMM1_SMEM>>>(
        aoh, woh, out);
}

// round 10
// speedup vs baseline: 7.5430x; 1.0831x over previous
#include <cuda_runtime.h>
#include <cuda_fp16.h>
#include <stdint.h>
#include <math.h>

// Problem constants
#define Bb   2
#define Ss   2048
#define Dd   1024
#define Hh   16
#define HDd  64
#define Mrows (Bb*Ss)   // 4096

#define SC2 0.18033688011112042f   // 0.125 * log2(e), folded into Q
#define LOG2E 1.4426950408889634f

// ---------------- scratch (no allocs allowed) ----------------
__device__ uint16_t g_xh [Mrows * Dd];            // x fp16 (plain)
__device__ uint16_t g_wh [3072 * Dd];             // fused wq|wk|wv fp16
__device__ uint16_t g_woh[Dd * Dd];               // wo fp16
__device__ uint16_t g_qh [Mrows * Dd];            // [B,H,S,64] fp16 hi/lo (pre-scaled)
__device__ uint16_t g_ql [Mrows * Dd];
__device__ uint16_t g_kh [Mrows * Dd];            // fp16
__device__ uint16_t g_vh [Mrows * Dd];            // fp16 (plain)
__device__ uint16_t g_aoh[Mrows * Dd];            // attn out fp16 (plain)
__device__ float    g_cosT[Ss * 32];              // rope tables
__device__ float    g_sinT[Ss * 32];

// ================= PTX helpers ==========================
__device__ __forceinline__ uint32_t smem_u32(const void* p) {
    uint32_t a;
    asm("{ .reg .u64 t; cvta.to.shared.u64 t, %1; cvt.u32.u64 %0, t; }"
        : "=r"(a) : "l"(p));
    return a;
}
__device__ __forceinline__ void cp_async16(uint32_t s, const void* g) {
    asm volatile("cp.async.cg.shared.global [%0], [%1], 16;" :: "r"(s), "l"(g));
}
#define CP_COMMIT() asm volatile("cp.async.commit_group;" ::: "memory")
#define CP_WAIT(n)  asm volatile("cp.async.wait_group %0;" :: "n"(n) : "memory")

#define LDSM_X4(r, addr) \
    asm volatile("ldmatrix.sync.aligned.m8n8.x4.shared.b16 {%0,%1,%2,%3}, [%4];" \
        : "=r"((r)[0]), "=r"((r)[1]), "=r"((r)[2]), "=r"((r)[3]) : "r"(addr))
#define LDSM_X4_T(r, addr) \
    asm volatile("ldmatrix.sync.aligned.m8n8.x4.trans.shared.b16 {%0,%1,%2,%3}, [%4];" \
        : "=r"((r)[0]), "=r"((r)[1]), "=r"((r)[2]), "=r"((r)[3]) : "r"(addr))

#define MMA_F16(d, a, b0, b1) \
    asm volatile("mma.sync.aligned.m16n8k16.row.col.f32.f16.f16.f32 " \
        "{%0,%1,%2,%3}, {%4,%5,%6,%7}, {%8,%9}, {%0,%1,%2,%3};" \
        : "+f"((d)[0]), "+f"((d)[1]), "+f"((d)[2]), "+f"((d)[3]) \
        : "r"((a)[0]), "r"((a)[1]), "r"((a)[2]), "r"((a)[3]), \
          "r"(b0), "r"(b1))

__device__ __forceinline__ uint32_t pack_h2(float a, float b) {
    uint32_t r;
    asm("cvt.rn.f16x2.f32 %0, %1, %2;" : "=r"(r) : "f"(b), "f"(a));
    return r;
}
__device__ __forceinline__ void split2_h(float x0, float x1,
                                         uint32_t& hi, uint32_t& lo) {
    hi = pack_h2(x0, x1);
    float2 f = __half22float2(*reinterpret_cast<__half2*>(&hi));
    lo = pack_h2(x0 - f.x, x1 - f.y);
}
__device__ __forceinline__ float ex2f(float x) {
    float y;
    asm("ex2.approx.f32 %0, %1;" : "=f"(y) : "f"(x));
    return y;
}

// =================================================================
// fused convert: x, w, wo -> plain fp16 ; rope tables
// =================================================================
__global__ __launch_bounds__(256)
void cvt_all(const float4* __restrict__ x,  const float4* __restrict__ wq,
             const float4* __restrict__ wk, const float4* __restrict__ wv,
             const float4* __restrict__ wo,
             uint2* __restrict__ xh, uint2* __restrict__ wh,
             uint2* __restrict__ woh,
             float* __restrict__ cosT, float* __restrict__ sinT) {
    int i = blockIdx.x * 256 + threadIdx.x;     // 0 .. 2M-1
    if (i < 65536) {  // rope table
        int s = i >> 5, j = i & 31;
        float inv = exp2f(-(float)j * 0.4152410118609203f);  // log2(1e4)/32
        float sn, cs;
        sincosf((float)s * inv, &sn, &cs);
        cosT[i] = cs;
        sinT[i] = sn;
    }
    const float4* src;
    uint2* dst;
    if (i < 1048576) {
        src = x + i; dst = xh + i;
    } else {
        int i2 = i - 1048576;
        int reg = i2 >> 18;            // 0..3
        int off = i2 & 262143;
        if (reg == 0)      { src = wq + off; dst = wh + off; }
        else if (reg == 1) { src = wk + off; dst = wh + 262144 + off; }
        else if (reg == 2) { src = wv + off; dst = wh + 524288 + off; }
        else               { src = wo + off; dst = woh + off; }
    }
    float4 v = *src;
    uint2 o;
    o.x = pack_h2(v.x, v.y);
    o.y = pack_h2(v.z, v.w);
    *dst = o;
}

// =================================================================
// GEMM framework: plain-A fp16 HMMA, tile 128x128x64, 256 thr,
// warps 4(M)x2(N), warp 32x64, 3-stage cp.async ring (16 stages,
// half the barriers of k=32), 110.6KB smem -> 2 CTAs/SM.
// =================================================================
#define GK 1024
#define GPITCH 144                // 64 f16 = 128B + 16B pad
#define P_A  0                    // 128*144 = 18432
#define P_B  18432
#define P_STG 36864
#define GEMM1_SMEM (3 * P_STG)    // 110592

#define GEMM_PREAMBLE                                                        \
    extern __shared__ char smem[];                                           \
    const uint32_t sb = smem_u32(smem);                                      \
    const int tid = threadIdx.x;                                             \
    const int wid = tid >> 5, lane = tid & 31;                               \
    const int wm = wid & 3, wn = wid >> 2;                                   \
    const int gid = lane >> 2, tig = lane & 3;                               \
    const int bm = blockIdx.y * 128, bn = blockIdx.x * 128;                  \
    uint32_t aAddr[2], bAddr[4];                                             \
    _Pragma("unroll")                                                        \
    for (int mf = 0; mf < 2; ++mf)                                           \
        aAddr[mf] = (wm * 32 + mf * 16 + (lane & 15)) * GPITCH               \
                    + (lane >> 4) * 16;                                      \
    _Pragma("unroll")                                                        \
    for (int nb = 0; nb < 4; ++nb)                                           \
        bAddr[nb] = (wn * 64 + nb * 16 + ((lane >> 4) << 3)                  \
                    + (lane & 7)) * GPITCH + ((lane >> 3) & 1) * 16;         \
    float acc[2][8][4];                                                      \
    _Pragma("unroll")                                                        \
    for (int i = 0; i < 2; ++i)                                              \
        _Pragma("unroll")                                                    \
        for (int j = 0; j < 8; ++j)                                          \
            _Pragma("unroll")                                                \
            for (int c = 0; c < 4; ++c) acc[i][j][c] = 0.f;

__device__ __forceinline__ void gemm1_issue(
    uint32_t stg, const uint16_t* __restrict__ A,
    const uint16_t* __restrict__ B, int bm, int bn, int k0, int tid) {
#pragma unroll
    for (int u = 0; u < 4; ++u) {
        int q = tid + u * 256;          // 0..1023
        int r = q >> 3, c = q & 7;
        uint32_t d = r * GPITCH + c * 16;
        cp_async16(stg + P_A + d, A + (size_t)(bm + r) * GK + k0 + c * 8);
        cp_async16(stg + P_B + d, B + (size_t)(bn + r) * GK + k0 + c * 8);
    }
}

#define GEMM1_MAINLOOP(A, B, bm, bn)                                         \
    gemm1_issue(sb, A, B, bm, bn, 0, tid);                                   \
    CP_COMMIT();                                                             \
    gemm1_issue(sb + P_STG, A, B, bm, bn, 64, tid);                          \
    CP_COMMIT();                                                             \
    for (int s = 0; s < 16; ++s) {                                           \
        if (s < 15) { CP_WAIT(1); } else { CP_WAIT(0); }                     \
        __syncthreads();                                                     \
        if (s + 2 < 16) {                                                    \
            gemm1_issue(sb + ((s + 2) % 3) * P_STG, A, B,                    \
                        bm, bn, (s + 2) * 64, tid);                          \
            CP_COMMIT();                                                     \
        }                                                                    \
        const uint32_t stg = sb + (s % 3) * P_STG;                           \
        _Pragma("unroll")                                                    \
        for (int ks = 0; ks < 4; ++ks) {                                     \
            uint32_t bh4[4][4];                                              \
            _Pragma("unroll")                                                \
            for (int nb = 0; nb < 4; ++nb)                                   \
                LDSM_X4(bh4[nb], stg + P_B + bAddr[nb] + ks * 32);           \
            _Pragma("unroll")                                                \
            for (int mf = 0; mf < 2; ++mf) {                                 \
                uint32_t ah[4];                                              \
                LDSM_X4(ah, stg + P_A + aAddr[mf] + ks * 32);                \
                _Pragma("unroll")                                            \
                for (int nb = 0; nb < 4; ++nb) {                             \
                    MMA_F16(acc[mf][2*nb],   ah, bh4[nb][0], bh4[nb][1]);    \
                    MMA_F16(acc[mf][2*nb+1], ah, bh4[nb][2], bh4[nb][3]);    \
                }                                                            \
            }                                                                \
        }                                                                    \
    }

// =================================================================
// QKV GEMM (A plain) with fused RMSNorm+RoPE+split epilogue.
// =================================================================
__global__ __launch_bounds__(256, 2)
void gemm_qkv(const uint16_t* __restrict__ A, const uint16_t* __restrict__ B,
              const float* __restrict__ qw, const float* __restrict__ kw,
              const float* __restrict__ cosT, const float* __restrict__ sinT,
              uint16_t* __restrict__ qh, uint16_t* __restrict__ ql,
              uint16_t* __restrict__ kh, uint16_t* __restrict__ vh) {
    GEMM_PREAMBLE
    GEMM1_MAINLOOP(A, B, bm, bn)

    const int cb = bn + wn * 64;
    const int sect = cb >> 10;          // 0=Q, 1=K, 2=V
    const int hh = (cb >> 6) & 15;

#pragma unroll
    for (int mf = 0; mf < 2; ++mf) {
#pragma unroll
        for (int hf = 0; hf < 2; ++hf) {
            const int row = bm + wm * 32 + mf * 16 + gid + hf * 8;
            const int s = row & (Ss - 1);
            const int b = row >> 11;
            const size_t dst = (((size_t)(b * Hh + hh)) * Ss + s) * HDd;
            float v[8][2];
#pragma unroll
            for (int nf = 0; nf < 8; ++nf) {
                v[nf][0] = acc[mf][nf][hf * 2];
                v[nf][1] = acc[mf][nf][hf * 2 + 1];
            }
            if (sect == 2) {   // V: plain fp16
#pragma unroll
                for (int nf = 0; nf < 8; ++nf) {
                    int d0 = nf * 8 + tig * 2;
                    *(uint32_t*)&vh[dst + d0] = pack_h2(v[nf][0], v[nf][1]);
                }
            } else {           // Q or K: rms + rope
                float ss = 0.f;
#pragma unroll
                for (int nf = 0; nf < 8; ++nf)
                    ss += v[nf][0] * v[nf][0] + v[nf][1] * v[nf][1];
                ss += __shfl_xor_sync(0xffffffffu, ss, 1);
                ss += __shfl_xor_sync(0xffffffffu, ss, 2);
                const float r = rsqrtf(ss * (1.0f / 64.0f) + 1e-6f);
                const float* w = sect ? kw : qw;
#pragma unroll
                for (int nf = 0; nf < 4; ++nf) {
                    int d0 = nf * 8 + tig * 2;
                    float2 w1 = *(const float2*)&w[d0];
                    float2 w2 = *(const float2*)&w[d0 + 32];
                    float2 cs = *(const float2*)&cosT[s * 32 + d0];
                    float2 sn = *(const float2*)&sinT[s * 32 + d0];
                    float x1a = v[nf][0]     * r * w1.x;
                    float x1b = v[nf][1]     * r * w1.y;
                    float x2a = v[nf + 4][0] * r * w2.x;
                    float x2b = v[nf + 4][1] * r * w2.y;
                    float o1a = x1a * cs.x - x2a * sn.x;
                    float o1b = x1b * cs.y - x2b * sn.y;
                    float o2a = x2a * cs.x + x1a * sn.x;
                    float o2b = x2b * cs.y + x1b * sn.y;
                    if (sect == 0) {   // Q: scale + split
                        o1a *= SC2; o1b *= SC2; o2a *= SC2; o2b *= SC2;
                        uint32_t hi, lo;
                        split2_h(o1a, o1b, hi, lo);
                        *(uint32_t*)&qh[dst + d0] = hi;
                        *(uint32_t*)&ql[dst + d0] = lo;
                        split2_h(o2a, o2b, hi, lo);
                        *(uint32_t*)&qh[dst + d0 + 32] = hi;
                        *(uint32_t*)&ql[dst + d0 + 32] = lo;
                    } else {           // K: plain fp16
                        *(uint32_t*)&kh[dst + d0]      = pack_h2(o1a, o1b);
                        *(uint32_t*)&kh[dst + d0 + 32] = pack_h2(o2a, o2b);
                    }
                }
            }
        }
    }
}

// =================================================================
// Output-projection GEMM (A plain fp16, fp32 C)
// =================================================================
__global__ __launch_bounds__(256, 2)
void gemm_out(const uint16_t* __restrict__ A, const uint16_t* __restrict__ B,
              float* __restrict__ C) {
    GEMM_PREAMBLE
    GEMM1_MAINLOOP(A, B, bm, bn)
#pragma unroll
    for (int mf = 0; mf < 2; ++mf) {
        const int row = bm + wm * 32 + mf * 16 + gid;
#pragma unroll
        for (int nf = 0; nf < 8; ++nf) {
            const int col = bn + wn * 64 + nf * 8 + tig * 2;
            *(float2*)&C[(size_t)row * Dd + col] =
                make_float2(acc[mf][nf][0], acc[mf][nf][1]);
            *(float2*)&C[(size_t)(row + 8) * Dd + col] =
                make_float2(acc[mf][nf][2], acc[mf][nf][3]);
        }
    }
}

// =================================================================
// fp16 flash attention: Q pre-scaled split, K plain, V plain.
// exp2-domain softmax; l via ones-column tensor MMA.
// Br=128, Bc=64, 3-stage KV ring, 2 CTAs/SM.
// =================================================================
#define APITCH 144
#define A_QH 0
#define A_QL 18432
#define A_QSZ 36864
#define A_K  0
#define A_V  9216
#define A_STG 18432
#define ATTN_SMEM (A_QSZ + 3 * A_STG)   // 92160
#define ONES_H2 0x3C003C00u

__device__ __forceinline__ void attn_kv_issue(
    uint32_t stg, const uint16_t* __restrict__ kh,
    const uint16_t* __restrict__ vh, size_t seqbase, int j, int tid) {
#pragma unroll
    for (int u = 0; u < 2; ++u) {
        int q = tid + u * 256;          // 0..511
        int r = q >> 3, c = q & 7;
        size_t src = seqbase + (size_t)(j * 64 + r) * 64 + c * 8;
        uint32_t d = r * APITCH + c * 16;
        cp_async16(stg + A_K + d, kh + src);
        cp_async16(stg + A_V + d, vh + src);
    }
}

__global__ __launch_bounds__(256, 2)
void attn_tc(const uint16_t* __restrict__ qh, const uint16_t* __restrict__ ql,
             const uint16_t* __restrict__ kh, const uint16_t* __restrict__ vh,
             const float* __restrict__ sinkl,
             uint16_t* __restrict__ aoh) {
    extern __shared__ char smem[];
    const uint32_t sb = smem_u32(smem);
    const int tid = threadIdx.x;
    const int wid = tid >> 5, lane = tid & 31;
    const int gid = lane >> 2, tig = lane & 3;
    const int qb = gridDim.x - 1 - blockIdx.x;   // heavy tiles first
    const int bh = blockIdx.y;
    const int h  = bh & (Hh - 1);
    const int b  = bh >> 4;
    const size_t seqbase = (size_t)bh * Ss * HDd;
    const int q0 = qb * 128;
    const int jmax = 2 * qb + 1;

    // ---- prologue: Q tile + KV stages 0,1 ----
#pragma unroll
    for (int u = 0; u < 4; ++u) {
        int q = tid + u * 256;
        int r = q >> 3, c = q & 7;
        size_t src = seqbase + (size_t)(q0 + r) * 64 + c * 8;
        uint32_t d = r * APITCH + c * 16;
        cp_async16(sb + A_QH + d, qh + src);
        cp_async16(sb + A_QL + d, ql + src);
    }
    attn_kv_issue(sb + A_QSZ, kh, vh, seqbase, 0, tid);
    CP_COMMIT();
    attn_kv_issue(sb + A_QSZ + A_STG, kh, vh, seqbase, 1, tid);
    CP_COMMIT();

    const uint32_t qA = sb + A_QH + (wid * 16 + (lane & 15)) * APITCH
                        + (lane >> 4) * 16;
    uint32_t kB[4];
#pragma unroll
    for (int nb = 0; nb < 4; ++nb)
        kB[nb] = A_K + (nb * 16 + ((lane >> 4) << 3) + (lane & 7)) * APITCH
                 + ((lane >> 3) & 1) * 16;
    const uint32_t vBrel = A_V + (lane & 15) * APITCH + (lane >> 4) * 16;

    const float snk2 = sinkl[h] * LOG2E;
    float m0 = snk2, m1 = snk2;
    float o[8][4], ol[4];
#pragma unroll
    for (int i = 0; i < 8; ++i)
#pragma unroll
        for (int c = 0; c < 4; ++c) o[i][c] = 0.f;
#pragma unroll
    for (int c = 0; c < 4; ++c) ol[c] = 0.f;

    const int r0g = q0 + wid * 16 + gid;
    const int r1g = r0g + 8;

    for (int j = 0; j <= jmax; ++j) {
        if (j < jmax) { CP_WAIT(1); } else { CP_WAIT(0); }
        __syncthreads();
        if (j + 2 <= jmax) {
            attn_kv_issue(sb + A_QSZ + ((j + 2) % 3) * A_STG,
                          kh, vh, seqbase, j + 2, tid);
            CP_COMMIT();
        }
        const uint32_t stg = sb + A_QSZ + (j % 3) * A_STG;

        // ---- S = Q K^T (Q split pre-scaled, K plain) ----
        float s[8][4];
#pragma unroll
        for (int i = 0; i < 8; ++i)
#pragma unroll
            for (int c = 0; c < 4; ++c) s[i][c] = 0.f;

#pragma unroll
        for (int ks = 0; ks < 4; ++ks) {
            uint32_t qah[4], qal[4];
            LDSM_X4(qah, qA + ks * 32);
            LDSM_X4(qal, qA + (A_QL - A_QH) + ks * 32);
#pragma unroll
            for (int nb = 0; nb < 4; ++nb) {
                uint32_t kb4[4];
                LDSM_X4(kb4, stg + kB[nb] + ks * 32);
                MMA_F16(s[2*nb],   qah, kb4[0], kb4[1]);
                MMA_F16(s[2*nb+1], qah, kb4[2], kb4[3]);
                MMA_F16(s[2*nb],   qal, kb4[0], kb4[1]);
                MMA_F16(s[2*nb+1], qal, kb4[2], kb4[3]);
            }
        }

        // ---- causal mask (diagonal blocks only) ----
        if (j >= 2 * qb) {
#pragma unroll
            for (int nf = 0; nf < 8; ++nf)
#pragma unroll
                for (int c = 0; c < 4; ++c) {
                    int col = j * 64 + nf * 8 + tig * 2 + (c & 1);
                    int row = (c < 2) ? r0g : r1g;
                    if (col > row) s[nf][c] = -1e30f;
                }
        }

        // ---- online softmax (base-2) ----
        float mx0 = -1e30f, mx1 = -1e30f;
#pragma unroll
        for (int nf = 0; nf < 8; ++nf) {
            mx0 = fmaxf(mx0, fmaxf(s[nf][0], s[nf][1]));
            mx1 = fmaxf(mx1, fmaxf(s[nf][2], s[nf][3]));
        }
        mx0 = fmaxf(mx0, __shfl_xor_sync(0xffffffffu, mx0, 1));
        mx0 = fmaxf(mx0, __shfl_xor_sync(0xffffffffu, mx0, 2));
        mx1 = fmaxf(mx1, __shfl_xor_sync(0xffffffffu, mx1, 1));
        mx1 = fmaxf(mx1, __shfl_xor_sync(0xffffffffu, mx1, 2));
        const float mn0 = fmaxf(m0, mx0), mn1 = fmaxf(m1, mx1);
        const float cr0 = ex2f(m0 - mn0), cr1 = ex2f(m1 - mn1);
        m0 = mn0; m1 = mn1;
#pragma unroll
        for (int nf = 0; nf < 8; ++nf) {
            o[nf][0] *= cr0; o[nf][1] *= cr0;
            o[nf][2] *= cr1; o[nf][3] *= cr1;
        }
        ol[0] *= cr0; ol[1] *= cr0; ol[2] *= cr1; ol[3] *= cr1;

        // ---- O += P V ;  l += P * ones (P packed inline) ----
#pragma unroll
        for (int ks = 0; ks < 4; ++ks) {
            uint32_t pa[4];
            pa[0] = pack_h2(ex2f(s[2*ks][0]   - mn0), ex2f(s[2*ks][1]   - mn0));
            pa[1] = pack_h2(ex2f(s[2*ks][2]   - mn1), ex2f(s[2*ks][3]   - mn1));
            pa[2] = pack_h2(ex2f(s[2*ks+1][0] - mn0), ex2f(s[2*ks+1][1] - mn0));
            pa[3] = pack_h2(ex2f(s[2*ks+1][2] - mn1), ex2f(s[2*ks+1][3] - mn1));
            MMA_F16(ol, pa, ONES_H2, ONES_H2);
#pragma unroll
            for (int db = 0; db < 4; ++db) {
                uint32_t vb4[4];
                LDSM_X4_T(vb4, stg + vBrel + ks * 16 * APITCH + db * 32);
                MMA_F16(o[2*db],   pa, vb4[0], vb4[1]);
                MMA_F16(o[2*db+1], pa, vb4[2], vb4[3]);
            }
        }
    }

    // ---- epilogue: add sink to l, normalize, plain fp16 store ----
    const float l0 = ol[0] + ex2f(snk2 - m0);
    const float l1 = ol[2] + ex2f(snk2 - m1);
    const float i0 = 1.f / l0, i1 = 1.f / l1;
#pragma unroll
    for (int nf = 0; nf < 8; ++nf) {
        const int col = h * HDd + nf * 8 + tig * 2;
        {
            size_t idx = ((size_t)(b * Ss + r0g)) * Dd + col;
            *(uint32_t*)&aoh[idx] = pack_h2(o[nf][0] * i0, o[nf][1] * i0);
        }
        {
            size_t idx = ((size_t)(b * Ss + r1g)) * Dd + col;
            *(uint32_t*)&aoh[idx] = pack_h2(o[nf][2] * i1, o[nf][3] * i1);
        }
    }
}

// =================================================================
extern "C" void kernel_launch(void* const* d_in, const int* in_sizes, int n_in,
                              void* d_out, int out_size) {
    const float* x  = (const float*)d_in[0];
    const float* wq = (const float*)d_in[1];
    const float* wk = (const float*)d_in[2];
    const float* wv = (const float*)d_in[3];
    const float* wo = (const float*)d_in[4];
    const float* qw = (const float*)d_in[5];
    const float* kw = (const float*)d_in[6];
    const float* sk = (const float*)d_in[7];
    float* out = (float*)d_out;

    uint16_t *xh, *wh, *woh;
    uint16_t *qhp, *qlp, *khp, *vhp, *aoh;
    float *cosT, *sinT;
    cudaGetSymbolAddress((void**)&xh,  g_xh);
    cudaGetSymbolAddress((void**)&wh,  g_wh);
    cudaGetSymbolAddress((void**)&woh, g_woh);
    cudaGetSymbolAddress((void**)&qhp, g_qh);
    cudaGetSymbolAddress((void**)&qlp, g_ql);
    cudaGetSymbolAddress((void**)&khp, g_kh);
    cudaGetSymbolAddress((void**)&vhp, g_vh);
    cudaGetSymbolAddress((void**)&aoh, g_aoh);
    cudaGetSymbolAddress((void**)&cosT, g_cosT);
    cudaGetSymbolAddress((void**)&sinT, g_sinT);

    cudaFuncSetAttribute(gemm_qkv, cudaFuncAttributeMaxDynamicSharedMemorySize,
                         GEMM1_SMEM);
    cudaFuncSetAttribute(gemm_out, cudaFuncAttributeMaxDynamicSharedMemorySize,
                         GEMM1_SMEM);
    cudaFuncSetAttribute(attn_tc, cudaFuncAttributeMaxDynamicSharedMemorySize,
                         ATTN_SMEM);

    // converts + rope tables
    cvt_all<<<8192, 256>>>((const float4*)x, (const float4*)wq,
                           (const float4*)wk, (const float4*)wv,
                           (const float4*)wo,
                           (uint2*)xh, (uint2*)wh, (uint2*)woh, cosT, sinT);

    // QKV projection + fused norm/rope/split (A plain)
    gemm_qkv<<<dim3(3072 / 128, Mrows / 128), 256, GEMM1_SMEM>>>(
        xh, wh, qw, kw, cosT, sinT, qhp, qlp, khp, vhp);

    // flash attention
    attn_tc<<<dim3(Ss / 128, Bb * Hh), 256, ATTN_SMEM>>>(
        qhp, qlp, khp, vhp, sk, aoh);

    // output projection (A plain)
    gemm_out<<<dim3(Dd / 128, Mrows / 128), 256, GEMM1_SMEM>>>(
        aoh, woh, out);
}